// round 7
// baseline (speedup 1.0000x reference)
#include <cuda_runtime.h>
#include <cuda_bf16.h>
#include <math.h>

// ---------------------------------------------------------------------------
// Problem constants
// ---------------------------------------------------------------------------
#define BATCH 8
#define NTOK 4096
#define ROWS (BATCH*NTOK)
#define DIMC 180
#define HEADS 6
#define HD 30
#define QKVW 540
#define MTOK 64
#define RDIM 10
#define GS 128
#define NG 32
#define WS 16
#define WINN 256
#define NWIN 128
#define MLP_HID 360
#define DTD 64
#define CFF 424
#define HH 64
#define WW 64

// ---------------------------------------------------------------------------
// Scratch
// ---------------------------------------------------------------------------
__device__ float g_xn   [ROWS*DIMC];
__device__ float g_qkv  [ROWS*QKVW];
__device__ float g_qatd [ROWS*RDIM];
__device__ float g_kkn  [BATCH*MTOK*RDIM];
__device__ float g_vv   [BATCH*MTOK*DIMC];
__device__ float g_tdpr [BATCH*MTOK*DTD];
__device__ float g_patd [ROWS*MTOK];
__device__ int   g_tkid [ROWS];
__device__ int   g_sidx [ROWS];
__device__ float g_yaca [ROWS*DIMC];
__device__ float g_ywin [ROWS*DIMC];
__device__ float g_xsum [ROWS*DIMC];
__device__ float g_x2n  [ROWS*DIMC];
__device__ float g_hc   [ROWS*CFF];
__device__ float g_hc2  [ROWS*CFF];
__device__ float g_wbias[HEADS*WINN*WINN];

// ---------------------------------------------------------------------------
// Helpers
// ---------------------------------------------------------------------------
__device__ __forceinline__ float warp_sum(float v) {
    #pragma unroll
    for (int o = 16; o; o >>= 1) v += __shfl_xor_sync(0xffffffffu, v, o);
    return v;
}
__device__ __forceinline__ float gelu_exact(float v) {
    return 0.5f * v * (1.0f + erff(v * 0.70710678118654752440f));
}
__device__ __forceinline__ unsigned long long pack2(float lo, float hi) {
    unsigned long long r;
    asm("mov.b64 %0,{%1,%2};" : "=l"(r) : "f"(lo), "f"(hi));
    return r;
}
__device__ __forceinline__ void unpack2(unsigned long long v, float& lo, float& hi) {
    asm("mov.b64 {%0,%1},%2;" : "=f"(lo), "=f"(hi) : "l"(v));
}
__device__ __forceinline__ void fma2(unsigned long long& d, unsigned long long a,
                                     unsigned long long b) {
    asm("fma.rn.f32x2 %0,%1,%2,%0;" : "+l"(d) : "l"(a), "l"(b));
}
__device__ __forceinline__ unsigned long long mul2(unsigned long long a, unsigned long long b) {
    unsigned long long r;
    asm("mul.rn.f32x2 %0,%1,%2;" : "=l"(r) : "l"(a), "l"(b));
    return r;
}
__device__ __forceinline__ unsigned smem_u32(const void* p) {
    return (unsigned)__cvta_generic_to_shared(p);
}

// ---------------------------------------------------------------------------
// Fused dictionary projections
// ---------------------------------------------------------------------------
__global__ void dict_kernel(const float* __restrict__ td,
                            const float* __restrict__ wk_w, const float* __restrict__ wk_b,
                            const float* __restrict__ wv_w, const float* __restrict__ wv_b,
                            const float* __restrict__ ftd_w, const float* __restrict__ ftd_b,
                            float* __restrict__ kkn, float* __restrict__ vv,
                            float* __restrict__ tdpr) {
    int r = blockIdx.x;
    __shared__ float as[DIMC];
    __shared__ float kbuf[RDIM];
    int tid = threadIdx.x;
    const float* ar = td + (size_t)r * DIMC;
    if (tid < DIMC) as[tid] = ar[tid];
    __syncthreads();
    if (tid < DIMC) {
        float acc = wv_b[tid];
        #pragma unroll 4
        for (int k = 0; k < DIMC; k++) acc += as[k] * wv_w[(size_t)k * DIMC + tid];
        vv[(size_t)r * DIMC + tid] = acc;
    } else if (tid < DIMC + DTD) {
        int c = tid - DIMC;
        float acc = ftd_b[c];
        #pragma unroll 4
        for (int k = 0; k < DIMC; k++) acc += as[k] * ftd_w[(size_t)k * DTD + c];
        tdpr[(size_t)r * DTD + c] = acc;
    } else if (tid < DIMC + DTD + RDIM) {
        int c = tid - DIMC - DTD;
        float acc = wk_b[c];
        #pragma unroll 4
        for (int k = 0; k < DIMC; k++) acc += as[k] * wk_w[(size_t)k * RDIM + c];
        kbuf[c] = acc;
    }
    __syncthreads();
    if (tid >= DIMC + DTD && tid < DIMC + DTD + RDIM) {
        int c = tid - DIMC - DTD;
        float ss = 0.f;
        #pragma unroll
        for (int j = 0; j < RDIM; j++) ss += kbuf[j] * kbuf[j];
        float inv = 1.f / fmaxf(sqrtf(ss), 1e-12f);
        kkn[(size_t)r * RDIM + c] = kbuf[c] * inv;
    }
}

// ---------------------------------------------------------------------------
// Window attention bias expansion
// ---------------------------------------------------------------------------
__global__ void wbias_kernel(const int* __restrict__ rpi, const float* __restrict__ rpb) {
    int e = blockIdx.x * blockDim.x + threadIdx.x;
    if (e < WINN * WINN) {
        int idx = rpi[e];
        #pragma unroll
        for (int h = 0; h < HEADS; h++) g_wbias[h * WINN * WINN + e] = rpb[idx * HEADS + h];
    }
}

// ---------------------------------------------------------------------------
// LayerNorm (+ optional fused 10-dim q projection)
// ---------------------------------------------------------------------------
__global__ void ln_kernel(const float* __restrict__ x, const float* __restrict__ g,
                          const float* __restrict__ b, float* __restrict__ out,
                          const float* __restrict__ wq, const float* __restrict__ bq,
                          float* __restrict__ qout) {
    __shared__ float ws[1920];
    __shared__ float bqs[16];
    int tid = threadIdx.x;
    if (wq) {
        for (int i = tid; i < 1920; i += 256) ws[i] = (i < DIMC * RDIM) ? wq[i] : 0.f;
        if (tid < RDIM) bqs[tid] = bq[tid];
        __syncthreads();
    }
    int row = (blockIdx.x * blockDim.x + tid) >> 5;
    if (row >= ROWS) return;
    int lane = tid & 31;
    const float* xr = x + (size_t)row * DIMC;
    float v[6], s = 0.f, s2 = 0.f;
    #pragma unroll
    for (int k = 0; k < 6; k++) {
        int c = lane + k * 32;
        v[k] = (c < DIMC) ? xr[c] : 0.f;
        s += v[k]; s2 += v[k] * v[k];
    }
    s = warp_sum(s); s2 = warp_sum(s2);
    float mu = s * (1.f / DIMC);
    float var = s2 * (1.f / DIMC) - mu * mu;
    float rstd = rsqrtf(var + 1e-5f);
    float nv[6];
    float* orow = out + (size_t)row * DIMC;
    #pragma unroll
    for (int k = 0; k < 6; k++) {
        int c = lane + k * 32;
        nv[k] = (c < DIMC) ? ((v[k] - mu) * rstd * g[c] + b[c]) : 0.f;
        if (c < DIMC) orow[c] = nv[k];
    }
    if (wq) {
        float myq = 0.f;
        #pragma unroll
        for (int o = 0; o < RDIM; o++) {
            float p = 0.f;
            #pragma unroll
            for (int k = 0; k < 6; k++) p += nv[k] * ws[(lane + 32 * k) * RDIM + o];
            p = warp_sum(p);
            if (lane == o) myq = p + bqs[o];
        }
        if (lane < RDIM) qout[(size_t)row * RDIM + lane] = myq;
    }
}

// ---------------------------------------------------------------------------
// Tensor-core tf32 GEMM, 3-stage cp.async pipeline (one sync per ktile),
// up to 3 fused passes. Dynamic smem = 3*(128*28 + 16*68)*4 = 56064 B.
// ---------------------------------------------------------------------------
#define AS_STRIDE (128*28)
#define WS_STRIDE (16*68)
#define GEMM_SMEM (3*(AS_STRIDE + WS_STRIDE)*4)

struct GPass { const float* A; const float* W; int K; int kt; };

__global__ __launch_bounds__(256) void gemm_tc(
        const float* __restrict__ A1, const float* __restrict__ W1, int K1,
        const float* __restrict__ A2, const float* __restrict__ W2, int K2,
        const float* __restrict__ A3, const float* __restrict__ W3base, long w3_stride, int K3,
        const float* __restrict__ b1, const float* __restrict__ b2,
        const float* __restrict__ add1,
        float* __restrict__ C, int M, int N, int ldc, int act) {
    extern __shared__ float smg[];
    float* AsB = smg;                    // 3 buffers of [128][28]
    float* WsB = smg + 3 * AS_STRIDE;    // 3 buffers of [16][68]
    int tid  = threadIdx.x;
    int lane = tid & 31;
    int warp = tid >> 5;
    int warpM = warp & 3;
    int warpN = warp >> 2;
    int gId = lane >> 2;
    int tig = lane & 3;
    int row0 = blockIdx.y * 128;
    int col0 = blockIdx.x * 64;

    GPass ps[3];
    int np = 0;
    if (A1 && K1 > 0) ps[np++] = {A1, W1, K1, (K1 + 15) >> 4};
    if (A2 && K2 > 0) ps[np++] = {A2, W2, K2, (K2 + 15) >> 4};
    if (A3 && K3 > 0) ps[np++] = {A3, W3base + (size_t)(row0 >> 12) * w3_stride, K3, (K3 + 15) >> 4};
    int total = 0;
    for (int p = 0; p < np; p++) total += ps[p].kt;

    auto copy_tile = [&](int gi, int buf) {
        int p = 0, loc = gi;
        while (loc >= ps[p].kt) { loc -= ps[p].kt; p++; }
        const float* A = ps[p].A;
        const float* W = ps[p].W;
        int K = ps[p].K;
        int k0 = loc << 4;
        float* Asb = AsB + buf * AS_STRIDE;
        float* Wsb = WsB + buf * WS_STRIDE;
        #pragma unroll
        for (int f = 0; f < 2; f++) {
            int cch = tid + f * 256;
            int m = cch >> 2, kk = (cch & 3) << 2;
            int gk = k0 + kk;
            int rem = K - gk;
            int bytes = (rem <= 0) ? 0 : ((rem >= 4) ? 16 : rem * 4);
            const float* src = bytes ? (A + (size_t)(row0 + m) * K + gk) : A;
            unsigned dst = smem_u32(Asb + m * 28 + kk);
            asm volatile("cp.async.ca.shared.global [%0], [%1], 16, %2;"
                         :: "r"(dst), "l"(src), "r"(bytes));
        }
        {
            int kk = tid >> 4, n4 = (tid & 15) << 2;
            int gk = k0 + kk, gn = col0 + n4;
            int bytes = 0;
            if (gk < K) {
                int nb = N - gn;
                bytes = (nb <= 0) ? 0 : ((nb >= 4) ? 16 : nb * 4);
            }
            const float* src = bytes ? (W + (size_t)gk * N + gn) : W;
            unsigned dst = smem_u32(Wsb + kk * 68 + n4);
            asm volatile("cp.async.ca.shared.global [%0], [%1], 16, %2;"
                         :: "r"(dst), "l"(src), "r"(bytes));
        }
    };

    float d[2][4][4];
    #pragma unroll
    for (int mt = 0; mt < 2; mt++)
        #pragma unroll
        for (int nt = 0; nt < 4; nt++)
            #pragma unroll
            for (int i = 0; i < 4; i++) d[mt][nt][i] = 0.f;

    // prologue: stage 0 and 1
    copy_tile(0, 0);
    asm volatile("cp.async.commit_group;");
    copy_tile(1, 1);
    asm volatile("cp.async.commit_group;");

    for (int i = 0; i < total; i++) {
        if (i + 1 < total) { asm volatile("cp.async.wait_group 1;"); }
        else               { asm volatile("cp.async.wait_group 0;"); }
        __syncthreads();
        int buf = i % 3;
        const float* Asb = AsB + buf * AS_STRIDE;
        const float* Wsb = WsB + buf * WS_STRIDE;
        #pragma unroll
        for (int ks = 0; ks < 2; ks++) {
            int kb = ks * 8;
            unsigned a[2][4], bfr[4][2];
            #pragma unroll
            for (int mt = 0; mt < 2; mt++) {
                int m0 = warpM * 32 + mt * 16;
                a[mt][0] = __float_as_uint(Asb[(m0 + gId    ) * 28 + kb + tig    ]);
                a[mt][1] = __float_as_uint(Asb[(m0 + gId + 8) * 28 + kb + tig    ]);
                a[mt][2] = __float_as_uint(Asb[(m0 + gId    ) * 28 + kb + tig + 4]);
                a[mt][3] = __float_as_uint(Asb[(m0 + gId + 8) * 28 + kb + tig + 4]);
            }
            #pragma unroll
            for (int nt = 0; nt < 4; nt++) {
                int n0 = warpN * 32 + nt * 8;
                bfr[nt][0] = __float_as_uint(Wsb[(kb + tig    ) * 68 + n0 + gId]);
                bfr[nt][1] = __float_as_uint(Wsb[(kb + tig + 4) * 68 + n0 + gId]);
            }
            #pragma unroll
            for (int mt = 0; mt < 2; mt++)
                #pragma unroll
                for (int nt = 0; nt < 4; nt++) {
                    asm volatile(
                        "mma.sync.aligned.m16n8k8.row.col.f32.tf32.tf32.f32 "
                        "{%0,%1,%2,%3},{%4,%5,%6,%7},{%8,%9},{%0,%1,%2,%3};"
                        : "+f"(d[mt][nt][0]), "+f"(d[mt][nt][1]),
                          "+f"(d[mt][nt][2]), "+f"(d[mt][nt][3])
                        : "r"(a[mt][0]), "r"(a[mt][1]), "r"(a[mt][2]), "r"(a[mt][3]),
                          "r"(bfr[nt][0]), "r"(bfr[nt][1]));
                }
        }
        // issue copy for tile i+2 (targets buffer (i-1)%3, safe after sync)
        if (i + 2 < total) {
            copy_tile(i + 2, (i + 2) % 3);
            asm volatile("cp.async.commit_group;");
        }
    }

    #pragma unroll
    for (int mt = 0; mt < 2; mt++) {
        #pragma unroll
        for (int nt = 0; nt < 4; nt++) {
            #pragma unroll
            for (int i = 0; i < 4; i++) {
                int r = row0 + warpM * 32 + mt * 16 + gId + (i >> 1) * 8;
                int c = col0 + warpN * 32 + nt * 8 + tig * 2 + (i & 1);
                if (c < N) {
                    float v = d[mt][nt][i];
                    if (b1)   v += b1[c];
                    if (b2)   v += b2[c];
                    if (add1) v += add1[(size_t)r * N + c];
                    if (act)  v = gelu_exact(v);
                    C[(size_t)r * ldc + c] = v;
                }
            }
        }
    }
}

// ---------------------------------------------------------------------------
// ATD: softmax probs P[ROWS][64] + argmax tkid. One warp per token.
// ---------------------------------------------------------------------------
__global__ void atd_kernel(const float* __restrict__ qatd, const float* __restrict__ kkn,
                           const float* __restrict__ scale,
                           float* __restrict__ P, int* __restrict__ tkid) {
    int t = (blockIdx.x * blockDim.x + threadIdx.x) >> 5;
    int lane = threadIdx.x & 31;
    if (t >= ROWS) return;
    int b = t >> 12;
    float q = (lane < RDIM) ? qatd[(size_t)t * RDIM + lane] : 0.f;
    float ss = warp_sum(q * q);
    float qn = q * (1.f / fmaxf(sqrtf(ss), 1e-12f));
    const float* kb = kkn + (size_t)b * MTOK * RDIM;
    float s0 = 0.f, s1 = 0.f;
    #pragma unroll
    for (int d = 0; d < RDIM; d++) {
        float qd = __shfl_sync(0xffffffffu, qn, d);
        s0 += qd * kb[lane * RDIM + d];
        s1 += qd * kb[(lane + 32) * RDIM + d];
    }
    float sc = fminf(fmaxf(scale[0], 0.f), 3.f);
    float ls = 1.f + sc * 4.15888308335967186f;  // log(64)
    s0 *= ls; s1 *= ls;
    float mv = fmaxf(s0, s1);
    int mi = (s0 >= s1) ? lane : lane + 32;
    #pragma unroll
    for (int o = 16; o; o >>= 1) {
        float ov = __shfl_xor_sync(0xffffffffu, mv, o);
        int   oi = __shfl_xor_sync(0xffffffffu, mi, o);
        if (ov > mv || (ov == mv && oi < mi)) { mv = ov; mi = oi; }
    }
    float p0 = __expf(s0 - mv), p1 = __expf(s1 - mv);
    float sum = warp_sum(p0 + p1);
    float inv = 1.f / sum;
    P[(size_t)t * MTOK + lane]      = p0 * inv;
    P[(size_t)t * MTOK + lane + 32] = p1 * inv;
    if (lane == 0) tkid[t] = mi;
}

// ---------------------------------------------------------------------------
// Single-pass stable counting sort scatter: block = (batch, bin).
// ---------------------------------------------------------------------------
__global__ void sortscatter_kernel(const int* __restrict__ tkid, int* __restrict__ sidx) {
    int b = blockIdx.x >> 6, bin = blockIdx.x & 63;
    const int* tk = tkid + b * NTOK;
    __shared__ int sc[256];
    int t = threadIdx.x;
    int start = t * 16;
    int eq = 0, less = 0;
    int vals[16];
    #pragma unroll
    for (int k = 0; k < 16; k++) {
        vals[k] = tk[start + k];
        eq += (vals[k] == bin);
        less += (vals[k] < bin);
    }
    sc[t] = (less << 16) | eq;
    __syncthreads();
    #pragma unroll
    for (int d = 1; d < 256; d <<= 1) {
        int v = (t >= d) ? sc[t - d] : 0;
        __syncthreads();
        sc[t] += v;
        __syncthreads();
    }
    int base = sc[255] >> 16;
    int pos = base + (sc[t] & 0xffff) - eq;
    #pragma unroll
    for (int k = 0; k < 16; k++)
        if (vals[k] == bin) sidx[b * NTOK + pos++] = start + k;
}

// ---------------------------------------------------------------------------
// AC_MSA grouped attention: 64 threads, 2 queries/thread, shared K/V stream.
// ---------------------------------------------------------------------------
__global__ __launch_bounds__(64) void acmsa_kernel(
        const float* __restrict__ qkv, const int* __restrict__ sidx,
        float* __restrict__ yout) {
    int bi = blockIdx.x;
    int hh = bi % HEADS;
    int g  = (bi / HEADS) % NG;
    int b  = bi / (HEADS * NG);
    int t = threadIdx.x;               // 0..63
    int lane = t & 31;
    int warp = t >> 5;                 // 0..1
    __shared__ __align__(16) float Ks[GS][32], Vs[GS][32];
    const int* sb = sidx + b * NTOK + g * GS;
    // cooperative coalesced fill: each warp fills 64 rows
    #pragma unroll 4
    for (int u = 0; u < 64; u++) {
        int rr = warp * 64 + u;
        int r_u = sb[rr];
        size_t rb = ((size_t)(b * NTOK + r_u)) * QKVW + hh * HD;
        float kv = 0.f, vv_ = 0.f;
        if (lane < HD) {
            kv  = qkv[rb + 180 + lane];
            vv_ = qkv[rb + 360 + lane];
        }
        Ks[rr][lane] = kv;
        Vs[rr][lane] = vv_;
    }
    // two queries: rows t and t+64
    const float scale = 0.18257418583505536f;   // 30^-0.5
    int rna = sb[t], rnb = sb[t + 64];
    const float2* qpa = (const float2*)(qkv + ((size_t)(b * NTOK + rna)) * QKVW + hh * HD);
    const float2* qpb = (const float2*)(qkv + ((size_t)(b * NTOK + rnb)) * QKVW + hh * HD);
    unsigned long long q2a[15], q2b[15];
    #pragma unroll
    for (int i = 0; i < 15; i++) {
        float2 va = qpa[i], vb = qpb[i];
        q2a[i] = pack2(va.x * scale, va.y * scale);
        q2b[i] = pack2(vb.x * scale, vb.y * scale);
    }
    __syncthreads();
    float ma = -1e30f, la = 0.f, mb = -1e30f, lb = 0.f;
    unsigned long long acc2a[15], acc2b[15];
    #pragma unroll
    for (int i = 0; i < 15; i++) { acc2a[i] = pack2(0.f, 0.f); acc2b[i] = pack2(0.f, 0.f); }
    for (int jc = 0; jc < GS; jc += 8) {
        float sa[8], sb_[8];
        #pragma unroll
        for (int u = 0; u < 8; u++) {
            const unsigned long long* k2 = (const unsigned long long*)Ks[jc + u];
            unsigned long long s2a = pack2(0.f, 0.f), s2b = pack2(0.f, 0.f);
            #pragma unroll
            for (int i = 0; i < 15; i++) {
                unsigned long long kk = k2[i];
                fma2(s2a, q2a[i], kk);
                fma2(s2b, q2b[i], kk);
            }
            float lo, hi;
            unpack2(s2a, lo, hi); sa[u]  = lo + hi;
            unpack2(s2b, lo, hi); sb_[u] = lo + hi;
        }
        float cma = sa[0], cmb = sb_[0];
        #pragma unroll
        for (int u = 1; u < 8; u++) { cma = fmaxf(cma, sa[u]); cmb = fmaxf(cmb, sb_[u]); }
        float mna = fmaxf(ma, cma), mnb = fmaxf(mb, cmb);
        float coa = __expf(ma - mna), cob = __expf(mb - mnb);
        ma = mna; mb = mnb;
        la *= coa; lb *= cob;
        unsigned long long coa2 = pack2(coa, coa), cob2 = pack2(cob, cob);
        #pragma unroll
        for (int i = 0; i < 15; i++) { acc2a[i] = mul2(acc2a[i], coa2); acc2b[i] = mul2(acc2b[i], cob2); }
        #pragma unroll
        for (int u = 0; u < 8; u++) {
            float pa = __expf(sa[u] - mna), pb = __expf(sb_[u] - mnb);
            la += pa; lb += pb;
            unsigned long long pa2 = pack2(pa, pa), pb2 = pack2(pb, pb);
            const unsigned long long* v2 = (const unsigned long long*)Vs[jc + u];
            #pragma unroll
            for (int i = 0; i < 15; i++) {
                unsigned long long vv_ = v2[i];
                fma2(acc2a[i], pa2, vv_);
                fma2(acc2b[i], pb2, vv_);
            }
        }
    }
    float inva = 1.f / la, invb = 1.f / lb;
    float2* ora = (float2*)(yout + ((size_t)(b * NTOK + rna)) * DIMC + hh * HD);
    float2* orb = (float2*)(yout + ((size_t)(b * NTOK + rnb)) * DIMC + hh * HD);
    #pragma unroll
    for (int i = 0; i < 15; i++) {
        float lo, hi;
        unpack2(acc2a[i], lo, hi); ora[i] = make_float2(lo * inva, hi * inva);
        unpack2(acc2b[i], lo, hi); orb[i] = make_float2(lo * invb, hi * invb);
    }
}

// ---------------------------------------------------------------------------
// Window attention: 128 threads, 2 queries/thread, shared K/V stream.
// ---------------------------------------------------------------------------
__global__ __launch_bounds__(128) void winattn_kernel(const float* __restrict__ qkv,
                                                      float* __restrict__ yout) {
    extern __shared__ float sm[];
    float* Ks = sm;
    float* Vs = sm + WINN * 32;
    int bi = blockIdx.x;
    int hh = bi % HEADS;
    int wdx = bi / HEADS;
    int b = wdx >> 4;
    int wy = (wdx >> 2) & 3;
    int wx = wdx & 3;
    int t = threadIdx.x;               // 0..127
    int lane = t & 31;
    int warp = t >> 5;                 // 0..3
    // cooperative coalesced fill: each warp fills 64 rows
    #pragma unroll 4
    for (int u = 0; u < 64; u++) {
        int rr = warp * 64 + u;
        int ny = (wy * WS + (rr >> 4)) * WW + wx * WS + (rr & 15);
        size_t rb = ((size_t)(b * NTOK + ny)) * QKVW + hh * HD;
        float kv = 0.f, vv_ = 0.f;
        if (lane < HD) {
            kv  = qkv[rb + 180 + lane];
            vv_ = qkv[rb + 360 + lane];
        }
        Ks[rr * 32 + lane] = kv;
        Vs[rr * 32 + lane] = vv_;
    }
    // two queries: rows t and t+128 of the window
    const float scale = 0.18257418583505536f;
    int qa_i = t, qb_i = t + 128;
    int na = (wy * WS + (qa_i >> 4)) * WW + wx * WS + (qa_i & 15);
    int nb = (wy * WS + (qb_i >> 4)) * WW + wx * WS + (qb_i & 15);
    const float2* qpa = (const float2*)(qkv + ((size_t)(b * NTOK + na)) * QKVW + hh * HD);
    const float2* qpb = (const float2*)(qkv + ((size_t)(b * NTOK + nb)) * QKVW + hh * HD);
    unsigned long long q2a[15], q2b[15];
    #pragma unroll
    for (int i = 0; i < 15; i++) {
        float2 va = qpa[i], vb = qpb[i];
        q2a[i] = pack2(va.x * scale, va.y * scale);
        q2b[i] = pack2(vb.x * scale, vb.y * scale);
    }
    __syncthreads();
    const float* browa = g_wbias + ((size_t)hh * WINN + qa_i) * WINN;
    const float* browb = g_wbias + ((size_t)hh * WINN + qb_i) * WINN;
    float ma = -1e30f, la = 0.f, mb = -1e30f, lb = 0.f;
    unsigned long long acc2a[15], acc2b[15];
    #pragma unroll
    for (int i = 0; i < 15; i++) { acc2a[i] = pack2(0.f, 0.f); acc2b[i] = pack2(0.f, 0.f); }
    for (int jc = 0; jc < WINN; jc += 8) {
        float sa[8], sb_[8];
        #pragma unroll
        for (int u = 0; u < 8; u++) {
            const unsigned long long* k2 = (const unsigned long long*)(Ks + (jc + u) * 32);
            unsigned long long s2a = pack2(0.f, 0.f), s2b = pack2(0.f, 0.f);
            #pragma unroll
            for (int i = 0; i < 15; i++) {
                unsigned long long kk = k2[i];
                fma2(s2a, q2a[i], kk);
                fma2(s2b, q2b[i], kk);
            }
            float lo, hi;
            unpack2(s2a, lo, hi); sa[u]  = lo + hi + browa[jc + u];
            unpack2(s2b, lo, hi); sb_[u] = lo + hi + browb[jc + u];
        }
        float cma = sa[0], cmb = sb_[0];
        #pragma unroll
        for (int u = 1; u < 8; u++) { cma = fmaxf(cma, sa[u]); cmb = fmaxf(cmb, sb_[u]); }
        float mna = fmaxf(ma, cma), mnb = fmaxf(mb, cmb);
        float coa = __expf(ma - mna), cob = __expf(mb - mnb);
        ma = mna; mb = mnb;
        la *= coa; lb *= cob;
        unsigned long long coa2 = pack2(coa, coa), cob2 = pack2(cob, cob);
        #pragma unroll
        for (int i = 0; i < 15; i++) { acc2a[i] = mul2(acc2a[i], coa2); acc2b[i] = mul2(acc2b[i], cob2); }
        #pragma unroll
        for (int u = 0; u < 8; u++) {
            float pa = __expf(sa[u] - mna), pb = __expf(sb_[u] - mnb);
            la += pa; lb += pb;
            unsigned long long pa2 = pack2(pa, pa), pb2 = pack2(pb, pb);
            const unsigned long long* v2 = (const unsigned long long*)(Vs + (jc + u) * 32);
            #pragma unroll
            for (int i = 0; i < 15; i++) {
                unsigned long long vv_ = v2[i];
                fma2(acc2a[i], pa2, vv_);
                fma2(acc2b[i], pb2, vv_);
            }
        }
    }
    float inva = 1.f / la, invb = 1.f / lb;
    float2* ora = (float2*)(yout + ((size_t)(b * NTOK + na)) * DIMC + hh * HD);
    float2* orb = (float2*)(yout + ((size_t)(b * NTOK + nb)) * DIMC + hh * HD);
    #pragma unroll
    for (int i = 0; i < 15; i++) {
        float lo, hi;
        unpack2(acc2a[i], lo, hi); ora[i] = make_float2(lo * inva, hi * inva);
        unpack2(acc2b[i], lo, hi); orb[i] = make_float2(lo * invb, hi * invb);
    }
}

// ---------------------------------------------------------------------------
// Gather per-token dictionary features into hc[:, 360:424]
// ---------------------------------------------------------------------------
__global__ void gathertd_kernel(const float* __restrict__ tdproj, const int* __restrict__ tkid,
                                float* __restrict__ hc) {
    int e = blockIdx.x * blockDim.x + threadIdx.x;
    if (e < ROWS * DTD) {
        int r = e >> 6, j = e & 63;
        int b = r >> 12;
        hc[(size_t)r * CFF + MLP_HID + j] = tdproj[((size_t)b * MTOK + tkid[r]) * DTD + j];
    }
}

// ---------------------------------------------------------------------------
// Depthwise 5x5 conv, tiled: 16x16 pixels x 8 channels per block.
// ---------------------------------------------------------------------------
#define DWCH 8
__global__ void dwconv_kernel(const float* __restrict__ hc, const float* __restrict__ w,
                              const float* __restrict__ bias, float* __restrict__ hc2) {
    __shared__ float smd[20 * 20 * DWCH];
    __shared__ float wsm[25][DWCH];
    __shared__ float bsm[DWCH];
    int tid = threadIdx.x;
    int c0 = blockIdx.y * DWCH;
    int b  = blockIdx.z;
    int tileY = (blockIdx.x >> 2) * 16, tileX = (blockIdx.x & 3) * 16;
    if (tid < 200) { int t5 = tid % 25, j = tid / 25; wsm[t5][j] = w[(c0 + j) * 25 + t5]; }
    if (tid < DWCH) bsm[tid] = bias[c0 + tid];
    for (int i = tid; i < 800; i += 256) {
        int cell = i >> 1, half = i & 1;
        int cy = cell / 20, cx = cell % 20;
        int gy = tileY + cy - 2, gx = tileX + cx - 2;
        float4 v = {0.f, 0.f, 0.f, 0.f};
        if (gy >= 0 && gy < 64 && gx >= 0 && gx < 64)
            v = *(const float4*)&hc[(((size_t)b << 12) + (gy << 6) + gx) * CFF + c0 + half * 4];
        *(float4*)&smd[cell * 8 + half * 4] = v;
    }
    __syncthreads();
    int ty = tid >> 4, tx = tid & 15;
    float acc[DWCH];
    #pragma unroll
    for (int j = 0; j < DWCH; j++) acc[j] = 0.f;
    #pragma unroll
    for (int ky = 0; ky < 5; ky++) {
        #pragma unroll
        for (int kx = 0; kx < 5; kx++) {
            const float* cp = &smd[((ty + ky) * 20 + tx + kx) * 8];
            float4 a0 = *(const float4*)cp;
            float4 a1 = *(const float4*)(cp + 4);
            int t5 = ky * 5 + kx;
            acc[0] += a0.x * wsm[t5][0];
            acc[1] += a0.y * wsm[t5][1];
            acc[2] += a0.z * wsm[t5][2];
            acc[3] += a0.w * wsm[t5][3];
            acc[4] += a1.x * wsm[t5][4];
            acc[5] += a1.y * wsm[t5][5];
            acc[6] += a1.z * wsm[t5][6];
            acc[7] += a1.w * wsm[t5][7];
        }
    }
    const float* ctr = &smd[((ty + 2) * 20 + tx + 2) * 8];
    size_t idx = (((size_t)b << 12) + ((size_t)(tileY + ty) << 6) + (tileX + tx)) * CFF + c0;
    float4 o0, o1;
    o0.x = ctr[0] + gelu_exact(acc[0] + bsm[0]);
    o0.y = ctr[1] + gelu_exact(acc[1] + bsm[1]);
    o0.z = ctr[2] + gelu_exact(acc[2] + bsm[2]);
    o0.w = ctr[3] + gelu_exact(acc[3] + bsm[3]);
    o1.x = ctr[4] + gelu_exact(acc[4] + bsm[4]);
    o1.y = ctr[5] + gelu_exact(acc[5] + bsm[5]);
    o1.z = ctr[6] + gelu_exact(acc[6] + bsm[6]);
    o1.w = ctr[7] + gelu_exact(acc[7] + bsm[7]);
    *(float4*)&hc2[idx] = o0;
    *(float4*)&hc2[idx + 4] = o1;
}

// ---------------------------------------------------------------------------
// Launch
// ---------------------------------------------------------------------------
extern "C" void kernel_launch(void* const* d_in, const int* in_sizes, int n_in,
                              void* d_out, int out_size) {
    const float* x        = (const float*)d_in[0];
    const float* td       = (const float*)d_in[1];
    const float* n1g      = (const float*)d_in[2];
    const float* n1b      = (const float*)d_in[3];
    const float* wqkv_w   = (const float*)d_in[4];
    const float* wqkv_b   = (const float*)d_in[5];
    const float* atd_wq_w = (const float*)d_in[6];
    const float* atd_wq_b = (const float*)d_in[7];
    const float* atd_wk_w = (const float*)d_in[8];
    const float* atd_wk_b = (const float*)d_in[9];
    const float* atd_wv_w = (const float*)d_in[10];
    const float* atd_wv_b = (const float*)d_in[11];
    const float* atd_sc   = (const float*)d_in[12];
    const float* aca_w    = (const float*)d_in[13];
    const float* aca_b    = (const float*)d_in[14];
    const float* win_rpb  = (const float*)d_in[15];
    const float* win_w    = (const float*)d_in[16];
    const float* win_b    = (const float*)d_in[17];
    const float* fctd_w   = (const float*)d_in[18];
    const float* fctd_b   = (const float*)d_in[19];
    const float* fc1_w    = (const float*)d_in[20];
    const float* fc1_b    = (const float*)d_in[21];
    const float* dw_w     = (const float*)d_in[22];
    const float* dw_b     = (const float*)d_in[23];
    const float* fc2_w    = (const float*)d_in[24];
    const float* fc2_b    = (const float*)d_in[25];
    const float* n2g      = (const float*)d_in[26];
    const float* n2b      = (const float*)d_in[27];
    const int*   rpi      = (const int*)d_in[28];
    float* out = (float*)d_out;

    float *xn, *qkv, *qatd, *kkn, *vv, *tdpr, *patd, *yaca, *ywin, *xsum, *x2n, *hc, *hc2;
    int *tkid, *sidx;
    cudaGetSymbolAddress((void**)&xn,   g_xn);
    cudaGetSymbolAddress((void**)&qkv,  g_qkv);
    cudaGetSymbolAddress((void**)&qatd, g_qatd);
    cudaGetSymbolAddress((void**)&kkn,  g_kkn);
    cudaGetSymbolAddress((void**)&vv,   g_vv);
    cudaGetSymbolAddress((void**)&tdpr, g_tdpr);
    cudaGetSymbolAddress((void**)&patd, g_patd);
    cudaGetSymbolAddress((void**)&yaca, g_yaca);
    cudaGetSymbolAddress((void**)&ywin, g_ywin);
    cudaGetSymbolAddress((void**)&xsum, g_xsum);
    cudaGetSymbolAddress((void**)&x2n,  g_x2n);
    cudaGetSymbolAddress((void**)&hc,   g_hc);
    cudaGetSymbolAddress((void**)&hc2,  g_hc2);
    cudaGetSymbolAddress((void**)&tkid, g_tkid);
    cudaGetSymbolAddress((void**)&sidx, g_sidx);

    cudaFuncSetAttribute(gemm_tc, cudaFuncAttributeMaxDynamicSharedMemorySize, GEMM_SMEM);
    cudaFuncSetAttribute(winattn_kernel, cudaFuncAttributeMaxDynamicSharedMemorySize, 65536);

    // 1. dictionary projections
    dict_kernel<<<BATCH*MTOK, 256>>>(td, atd_wk_w, atd_wk_b, atd_wv_w, atd_wv_b,
                                     fctd_w, fctd_b, kkn, vv, tdpr);
    // 2. window bias expansion
    wbias_kernel<<<WINN*WINN/256, 256>>>(rpi, win_rpb);
    // 3. LN1 (+ fused q_atd projection)
    ln_kernel<<<ROWS/8, 256>>>(x, n1g, n1b, xn, atd_wq_w, atd_wq_b, qatd);
    // 4. qkv = xn @ wqkv + b
    gemm_tc<<<dim3(9, ROWS/128), 256, GEMM_SMEM>>>(xn, wqkv_w, DIMC, nullptr, nullptr, 0,
                                        nullptr, nullptr, 0, 0,
                                        wqkv_b, nullptr, nullptr,
                                        qkv, ROWS, QKVW, QKVW, 0);
    // 5. ATD probs + tk_id
    atd_kernel<<<ROWS/8, 256>>>(qatd, kkn, atd_sc, patd, tkid);
    // 6. window attention  (<- ncu sample target)
    winattn_kernel<<<NWIN*HEADS, 128, 65536>>>(qkv, ywin);
    // 7. single-pass stable sort scatter
    sortscatter_kernel<<<BATCH*MTOK, 256>>>(tkid, sidx);
    // 8. grouped attention
    acmsa_kernel<<<BATCH*NG*HEADS, 64>>>(qkv, sidx, yaca);
    // 9. xsum = x + P@vv (batched) + yaca@aca_w + ywin@win_w + biases
    gemm_tc<<<dim3(3, ROWS/128), 256, GEMM_SMEM>>>(yaca, aca_w, DIMC, ywin, win_w, DIMC,
                                        patd, vv, (long)MTOK*DIMC, MTOK,
                                        aca_b, win_b, x,
                                        xsum, ROWS, DIMC, DIMC, 0);
    // 10. LN2
    ln_kernel<<<ROWS/8, 256>>>(xsum, n2g, n2b, x2n, nullptr, nullptr, nullptr);
    // 11. fc1 + GELU into hc[:, 0:360]
    gemm_tc<<<dim3(6, ROWS/128), 256, GEMM_SMEM>>>(x2n, fc1_w, DIMC, nullptr, nullptr, 0,
                                        nullptr, nullptr, 0, 0,
                                        fc1_b, nullptr, nullptr,
                                        hc, ROWS, MLP_HID, CFF, 1);
    // 12. gather td features into hc[:, 360:424]
    gathertd_kernel<<<ROWS*DTD/256, 256>>>(tdpr, tkid, hc);
    // 13. depthwise conv + gelu + residual (tiled)
    dwconv_kernel<<<dim3(16, CFF/DWCH, BATCH), 256>>>(hc, dw_w, dw_b, hc2);
    // 14. out = xsum + hc2 @ fc2_w + fc2_b
    gemm_tc<<<dim3(3, ROWS/128), 256, GEMM_SMEM>>>(hc2, fc2_w, CFF, nullptr, nullptr, 0,
                                        nullptr, nullptr, 0, 0,
                                        fc2_b, nullptr, xsum,
                                        out, ROWS, DIMC, DIMC, 0);
}

// round 8
// speedup vs baseline: 1.0742x; 1.0742x over previous
#include <cuda_runtime.h>
#include <cuda_bf16.h>
#include <math.h>

// ---------------------------------------------------------------------------
// Problem constants
// ---------------------------------------------------------------------------
#define BATCH 8
#define NTOK 4096
#define ROWS (BATCH*NTOK)
#define DIMC 180
#define HEADS 6
#define HD 30
#define QKVW 540
#define MTOK 64
#define RDIM 10
#define GS 128
#define NG 32
#define WS 16
#define WINN 256
#define NWIN 128
#define MLP_HID 360
#define DTD 64
#define CFF 424
#define HH 64
#define WW 64

// ---------------------------------------------------------------------------
// Scratch
// ---------------------------------------------------------------------------
__device__ float g_xn   [ROWS*DIMC];
__device__ float g_qkv  [ROWS*QKVW];
__device__ float g_qatd [ROWS*RDIM];
__device__ float g_kkn  [BATCH*MTOK*RDIM];
__device__ float g_vv   [BATCH*MTOK*DIMC];
__device__ float g_tdpr [BATCH*MTOK*DTD];
__device__ float g_patd [ROWS*MTOK];
__device__ int   g_tkid [ROWS];
__device__ int   g_sidx [ROWS];
__device__ float g_yaca [ROWS*DIMC];
__device__ float g_ywin [ROWS*DIMC];
__device__ float g_xsum [ROWS*DIMC];
__device__ float g_x2n  [ROWS*DIMC];
__device__ float g_hc   [ROWS*CFF];
__device__ float g_hc2  [ROWS*CFF];
__device__ float g_wbias[HEADS*WINN*WINN];

// ---------------------------------------------------------------------------
// Helpers
// ---------------------------------------------------------------------------
__device__ __forceinline__ float warp_sum(float v) {
    #pragma unroll
    for (int o = 16; o; o >>= 1) v += __shfl_xor_sync(0xffffffffu, v, o);
    return v;
}
__device__ __forceinline__ float gelu_exact(float v) {
    return 0.5f * v * (1.0f + erff(v * 0.70710678118654752440f));
}
__device__ __forceinline__ unsigned long long pack2(float lo, float hi) {
    unsigned long long r;
    asm("mov.b64 %0,{%1,%2};" : "=l"(r) : "f"(lo), "f"(hi));
    return r;
}
__device__ __forceinline__ void unpack2(unsigned long long v, float& lo, float& hi) {
    asm("mov.b64 {%0,%1},%2;" : "=f"(lo), "=f"(hi) : "l"(v));
}
__device__ __forceinline__ void fma2(unsigned long long& d, unsigned long long a,
                                     unsigned long long b) {
    asm("fma.rn.f32x2 %0,%1,%2,%0;" : "+l"(d) : "l"(a), "l"(b));
}
__device__ __forceinline__ unsigned long long mul2(unsigned long long a, unsigned long long b) {
    unsigned long long r;
    asm("mul.rn.f32x2 %0,%1,%2;" : "=l"(r) : "l"(a), "l"(b));
    return r;
}
__device__ __forceinline__ unsigned smem_u32(const void* p) {
    return (unsigned)__cvta_generic_to_shared(p);
}

// ---------------------------------------------------------------------------
// Fused dictionary projections
// ---------------------------------------------------------------------------
__global__ void dict_kernel(const float* __restrict__ td,
                            const float* __restrict__ wk_w, const float* __restrict__ wk_b,
                            const float* __restrict__ wv_w, const float* __restrict__ wv_b,
                            const float* __restrict__ ftd_w, const float* __restrict__ ftd_b,
                            float* __restrict__ kkn, float* __restrict__ vv,
                            float* __restrict__ tdpr) {
    int r = blockIdx.x;
    __shared__ float as[DIMC];
    __shared__ float kbuf[RDIM];
    int tid = threadIdx.x;
    const float* ar = td + (size_t)r * DIMC;
    if (tid < DIMC) as[tid] = ar[tid];
    __syncthreads();
    if (tid < DIMC) {
        float acc = wv_b[tid];
        #pragma unroll 4
        for (int k = 0; k < DIMC; k++) acc += as[k] * wv_w[(size_t)k * DIMC + tid];
        vv[(size_t)r * DIMC + tid] = acc;
    } else if (tid < DIMC + DTD) {
        int c = tid - DIMC;
        float acc = ftd_b[c];
        #pragma unroll 4
        for (int k = 0; k < DIMC; k++) acc += as[k] * ftd_w[(size_t)k * DTD + c];
        tdpr[(size_t)r * DTD + c] = acc;
    } else if (tid < DIMC + DTD + RDIM) {
        int c = tid - DIMC - DTD;
        float acc = wk_b[c];
        #pragma unroll 4
        for (int k = 0; k < DIMC; k++) acc += as[k] * wk_w[(size_t)k * RDIM + c];
        kbuf[c] = acc;
    }
    __syncthreads();
    if (tid >= DIMC + DTD && tid < DIMC + DTD + RDIM) {
        int c = tid - DIMC - DTD;
        float ss = 0.f;
        #pragma unroll
        for (int j = 0; j < RDIM; j++) ss += kbuf[j] * kbuf[j];
        float inv = 1.f / fmaxf(sqrtf(ss), 1e-12f);
        kkn[(size_t)r * RDIM + c] = kbuf[c] * inv;
    }
}

// ---------------------------------------------------------------------------
// Window attention bias expansion
// ---------------------------------------------------------------------------
__global__ void wbias_kernel(const int* __restrict__ rpi, const float* __restrict__ rpb) {
    int e = blockIdx.x * blockDim.x + threadIdx.x;
    if (e < WINN * WINN) {
        int idx = rpi[e];
        #pragma unroll
        for (int h = 0; h < HEADS; h++) g_wbias[h * WINN * WINN + e] = rpb[idx * HEADS + h];
    }
}

// ---------------------------------------------------------------------------
// LayerNorm (+ optional fused 10-dim q projection)
// ---------------------------------------------------------------------------
__global__ void ln_kernel(const float* __restrict__ x, const float* __restrict__ g,
                          const float* __restrict__ b, float* __restrict__ out,
                          const float* __restrict__ wq, const float* __restrict__ bq,
                          float* __restrict__ qout) {
    __shared__ float ws[1920];
    __shared__ float bqs[16];
    int tid = threadIdx.x;
    if (wq) {
        for (int i = tid; i < 1920; i += 256) ws[i] = (i < DIMC * RDIM) ? wq[i] : 0.f;
        if (tid < RDIM) bqs[tid] = bq[tid];
        __syncthreads();
    }
    int row = (blockIdx.x * blockDim.x + tid) >> 5;
    if (row >= ROWS) return;
    int lane = tid & 31;
    const float* xr = x + (size_t)row * DIMC;
    float v[6], s = 0.f, s2 = 0.f;
    #pragma unroll
    for (int k = 0; k < 6; k++) {
        int c = lane + k * 32;
        v[k] = (c < DIMC) ? xr[c] : 0.f;
        s += v[k]; s2 += v[k] * v[k];
    }
    s = warp_sum(s); s2 = warp_sum(s2);
    float mu = s * (1.f / DIMC);
    float var = s2 * (1.f / DIMC) - mu * mu;
    float rstd = rsqrtf(var + 1e-5f);
    float nv[6];
    float* orow = out + (size_t)row * DIMC;
    #pragma unroll
    for (int k = 0; k < 6; k++) {
        int c = lane + k * 32;
        nv[k] = (c < DIMC) ? ((v[k] - mu) * rstd * g[c] + b[c]) : 0.f;
        if (c < DIMC) orow[c] = nv[k];
    }
    if (wq) {
        float myq = 0.f;
        #pragma unroll
        for (int o = 0; o < RDIM; o++) {
            float p = 0.f;
            #pragma unroll
            for (int k = 0; k < 6; k++) p += nv[k] * ws[(lane + 32 * k) * RDIM + o];
            p = warp_sum(p);
            if (lane == o) myq = p + bqs[o];
        }
        if (lane < RDIM) qout[(size_t)row * RDIM + lane] = myq;
    }
}

// ---------------------------------------------------------------------------
// Tensor-core tf32 GEMM, static 2-buffer cp.async pipeline with ONE
// __syncthreads per ktile. Copy for tile i+1 is issued AFTER the sync of
// iteration i, targeting the buffer last read at iteration i-1 (race-free).
// ---------------------------------------------------------------------------
struct GPass { const float* A; const float* W; int K; int kt; };

__global__ __launch_bounds__(256) void gemm_tc(
        const float* __restrict__ A1, const float* __restrict__ W1, int K1,
        const float* __restrict__ A2, const float* __restrict__ W2, int K2,
        const float* __restrict__ A3, const float* __restrict__ W3base, long w3_stride, int K3,
        const float* __restrict__ b1, const float* __restrict__ b2,
        const float* __restrict__ add1,
        float* __restrict__ C, int M, int N, int ldc, int act) {
    __shared__ float As[2][128][28];
    __shared__ float Ws[2][16][68];
    int tid  = threadIdx.x;
    int lane = tid & 31;
    int warp = tid >> 5;
    int warpM = warp & 3;
    int warpN = warp >> 2;
    int gId = lane >> 2;
    int tig = lane & 3;
    int row0 = blockIdx.y * 128;
    int col0 = blockIdx.x * 64;

    GPass ps[3];
    int np = 0;
    if (A1 && K1 > 0) ps[np++] = {A1, W1, K1, (K1 + 15) >> 4};
    if (A2 && K2 > 0) ps[np++] = {A2, W2, K2, (K2 + 15) >> 4};
    if (A3 && K3 > 0) ps[np++] = {A3, W3base + (size_t)(row0 >> 12) * w3_stride, K3, (K3 + 15) >> 4};
    int total = 0;
    for (int p = 0; p < np; p++) total += ps[p].kt;

    auto copy_tile = [&](int gi, int buf) {
        int p = 0, loc = gi;
        while (loc >= ps[p].kt) { loc -= ps[p].kt; p++; }
        const float* A = ps[p].A;
        const float* W = ps[p].W;
        int K = ps[p].K;
        int k0 = loc << 4;
        #pragma unroll
        for (int f = 0; f < 2; f++) {
            int cch = tid + f * 256;
            int m = cch >> 2, kk = (cch & 3) << 2;
            int gk = k0 + kk;
            int rem = K - gk;
            int bytes = (rem <= 0) ? 0 : ((rem >= 4) ? 16 : rem * 4);
            const float* src = bytes ? (A + (size_t)(row0 + m) * K + gk) : A;
            unsigned dst = smem_u32(&As[buf][m][kk]);
            asm volatile("cp.async.ca.shared.global [%0], [%1], 16, %2;"
                         :: "r"(dst), "l"(src), "r"(bytes));
        }
        {
            int kk = tid >> 4, n4 = (tid & 15) << 2;
            int gk = k0 + kk, gn = col0 + n4;
            int bytes = 0;
            if (gk < K) {
                int nb = N - gn;
                bytes = (nb <= 0) ? 0 : ((nb >= 4) ? 16 : nb * 4);
            }
            const float* src = bytes ? (W + (size_t)gk * N + gn) : W;
            unsigned dst = smem_u32(&Ws[buf][kk][n4]);
            asm volatile("cp.async.ca.shared.global [%0], [%1], 16, %2;"
                         :: "r"(dst), "l"(src), "r"(bytes));
        }
    };

    float d[2][4][4];
    #pragma unroll
    for (int mt = 0; mt < 2; mt++)
        #pragma unroll
        for (int nt = 0; nt < 4; nt++)
            #pragma unroll
            for (int i = 0; i < 4; i++) d[mt][nt][i] = 0.f;

    copy_tile(0, 0);
    asm volatile("cp.async.commit_group;");
    for (int i = 0; i < total; i++) {
        asm volatile("cp.async.wait_group 0;");   // tile i copies (this thread) done
        __syncthreads();                          // all threads' copies visible; all
                                                  // reads of buf (i+1)&1 (iter i-1) done
        if (i + 1 < total) {
            copy_tile(i + 1, (i + 1) & 1);        // overlaps compute below
            asm volatile("cp.async.commit_group;");
        }
        int buf = i & 1;
        #pragma unroll
        for (int ks = 0; ks < 2; ks++) {
            int kb = ks * 8;
            unsigned a[2][4], bfr[4][2];
            #pragma unroll
            for (int mt = 0; mt < 2; mt++) {
                int m0 = warpM * 32 + mt * 16;
                a[mt][0] = __float_as_uint(As[buf][m0 + gId    ][kb + tig    ]);
                a[mt][1] = __float_as_uint(As[buf][m0 + gId + 8][kb + tig    ]);
                a[mt][2] = __float_as_uint(As[buf][m0 + gId    ][kb + tig + 4]);
                a[mt][3] = __float_as_uint(As[buf][m0 + gId + 8][kb + tig + 4]);
            }
            #pragma unroll
            for (int nt = 0; nt < 4; nt++) {
                int n0 = warpN * 32 + nt * 8;
                bfr[nt][0] = __float_as_uint(Ws[buf][kb + tig    ][n0 + gId]);
                bfr[nt][1] = __float_as_uint(Ws[buf][kb + tig + 4][n0 + gId]);
            }
            #pragma unroll
            for (int mt = 0; mt < 2; mt++)
                #pragma unroll
                for (int nt = 0; nt < 4; nt++) {
                    asm volatile(
                        "mma.sync.aligned.m16n8k8.row.col.f32.tf32.tf32.f32 "
                        "{%0,%1,%2,%3},{%4,%5,%6,%7},{%8,%9},{%0,%1,%2,%3};"
                        : "+f"(d[mt][nt][0]), "+f"(d[mt][nt][1]),
                          "+f"(d[mt][nt][2]), "+f"(d[mt][nt][3])
                        : "r"(a[mt][0]), "r"(a[mt][1]), "r"(a[mt][2]), "r"(a[mt][3]),
                          "r"(bfr[nt][0]), "r"(bfr[nt][1]));
                }
        }
    }

    #pragma unroll
    for (int mt = 0; mt < 2; mt++) {
        #pragma unroll
        for (int nt = 0; nt < 4; nt++) {
            #pragma unroll
            for (int i = 0; i < 4; i++) {
                int r = row0 + warpM * 32 + mt * 16 + gId + (i >> 1) * 8;
                int c = col0 + warpN * 32 + nt * 8 + tig * 2 + (i & 1);
                if (c < N) {
                    float v = d[mt][nt][i];
                    if (b1)   v += b1[c];
                    if (b2)   v += b2[c];
                    if (add1) v += add1[(size_t)r * N + c];
                    if (act)  v = gelu_exact(v);
                    C[(size_t)r * ldc + c] = v;
                }
            }
        }
    }
}

// ---------------------------------------------------------------------------
// ATD: softmax probs P[ROWS][64] + argmax tkid. One warp per token.
// ---------------------------------------------------------------------------
__global__ void atd_kernel(const float* __restrict__ qatd, const float* __restrict__ kkn,
                           const float* __restrict__ scale,
                           float* __restrict__ P, int* __restrict__ tkid) {
    int t = (blockIdx.x * blockDim.x + threadIdx.x) >> 5;
    int lane = threadIdx.x & 31;
    if (t >= ROWS) return;
    int b = t >> 12;
    float q = (lane < RDIM) ? qatd[(size_t)t * RDIM + lane] : 0.f;
    float ss = warp_sum(q * q);
    float qn = q * (1.f / fmaxf(sqrtf(ss), 1e-12f));
    const float* kb = kkn + (size_t)b * MTOK * RDIM;
    float s0 = 0.f, s1 = 0.f;
    #pragma unroll
    for (int d = 0; d < RDIM; d++) {
        float qd = __shfl_sync(0xffffffffu, qn, d);
        s0 += qd * kb[lane * RDIM + d];
        s1 += qd * kb[(lane + 32) * RDIM + d];
    }
    float sc = fminf(fmaxf(scale[0], 0.f), 3.f);
    float ls = 1.f + sc * 4.15888308335967186f;  // log(64)
    s0 *= ls; s1 *= ls;
    float mv = fmaxf(s0, s1);
    int mi = (s0 >= s1) ? lane : lane + 32;
    #pragma unroll
    for (int o = 16; o; o >>= 1) {
        float ov = __shfl_xor_sync(0xffffffffu, mv, o);
        int   oi = __shfl_xor_sync(0xffffffffu, mi, o);
        if (ov > mv || (ov == mv && oi < mi)) { mv = ov; mi = oi; }
    }
    float p0 = __expf(s0 - mv), p1 = __expf(s1 - mv);
    float sum = warp_sum(p0 + p1);
    float inv = 1.f / sum;
    P[(size_t)t * MTOK + lane]      = p0 * inv;
    P[(size_t)t * MTOK + lane + 32] = p1 * inv;
    if (lane == 0) tkid[t] = mi;
}

// ---------------------------------------------------------------------------
// Single-pass stable counting sort scatter: block = (batch, bin).
// ---------------------------------------------------------------------------
__global__ void sortscatter_kernel(const int* __restrict__ tkid, int* __restrict__ sidx) {
    int b = blockIdx.x >> 6, bin = blockIdx.x & 63;
    const int* tk = tkid + b * NTOK;
    __shared__ int sc[256];
    int t = threadIdx.x;
    int start = t * 16;
    int eq = 0, less = 0;
    int vals[16];
    #pragma unroll
    for (int k = 0; k < 16; k++) {
        vals[k] = tk[start + k];
        eq += (vals[k] == bin);
        less += (vals[k] < bin);
    }
    sc[t] = (less << 16) | eq;
    __syncthreads();
    #pragma unroll
    for (int d = 1; d < 256; d <<= 1) {
        int v = (t >= d) ? sc[t - d] : 0;
        __syncthreads();
        sc[t] += v;
        __syncthreads();
    }
    int base = sc[255] >> 16;
    int pos = base + (sc[t] & 0xffff) - eq;
    #pragma unroll
    for (int k = 0; k < 16; k++)
        if (vals[k] == bin) sidx[b * NTOK + pos++] = start + k;
}

// ---------------------------------------------------------------------------
// AC_MSA grouped attention: 64 threads, 2 queries/thread, shared K/V stream.
// ---------------------------------------------------------------------------
__global__ __launch_bounds__(64) void acmsa_kernel(
        const float* __restrict__ qkv, const int* __restrict__ sidx,
        float* __restrict__ yout) {
    int bi = blockIdx.x;
    int hh = bi % HEADS;
    int g  = (bi / HEADS) % NG;
    int b  = bi / (HEADS * NG);
    int t = threadIdx.x;               // 0..63
    int lane = t & 31;
    int warp = t >> 5;                 // 0..1
    __shared__ __align__(16) float Ks[GS][32], Vs[GS][32];
    const int* sb = sidx + b * NTOK + g * GS;
    #pragma unroll 4
    for (int u = 0; u < 64; u++) {
        int rr = warp * 64 + u;
        int r_u = sb[rr];
        size_t rb = ((size_t)(b * NTOK + r_u)) * QKVW + hh * HD;
        float kv = 0.f, vv_ = 0.f;
        if (lane < HD) {
            kv  = qkv[rb + 180 + lane];
            vv_ = qkv[rb + 360 + lane];
        }
        Ks[rr][lane] = kv;
        Vs[rr][lane] = vv_;
    }
    const float scale = 0.18257418583505536f;   // 30^-0.5
    int rna = sb[t], rnb = sb[t + 64];
    const float2* qpa = (const float2*)(qkv + ((size_t)(b * NTOK + rna)) * QKVW + hh * HD);
    const float2* qpb = (const float2*)(qkv + ((size_t)(b * NTOK + rnb)) * QKVW + hh * HD);
    unsigned long long q2a[15], q2b[15];
    #pragma unroll
    for (int i = 0; i < 15; i++) {
        float2 va = qpa[i], vb = qpb[i];
        q2a[i] = pack2(va.x * scale, va.y * scale);
        q2b[i] = pack2(vb.x * scale, vb.y * scale);
    }
    __syncthreads();
    float ma = -1e30f, la = 0.f, mb = -1e30f, lb = 0.f;
    unsigned long long acc2a[15], acc2b[15];
    #pragma unroll
    for (int i = 0; i < 15; i++) { acc2a[i] = pack2(0.f, 0.f); acc2b[i] = pack2(0.f, 0.f); }
    for (int jc = 0; jc < GS; jc += 8) {
        float sa[8], sb_[8];
        #pragma unroll
        for (int u = 0; u < 8; u++) {
            const unsigned long long* k2 = (const unsigned long long*)Ks[jc + u];
            unsigned long long s2a = pack2(0.f, 0.f), s2b = pack2(0.f, 0.f);
            #pragma unroll
            for (int i = 0; i < 15; i++) {
                unsigned long long kk = k2[i];
                fma2(s2a, q2a[i], kk);
                fma2(s2b, q2b[i], kk);
            }
            float lo, hi;
            unpack2(s2a, lo, hi); sa[u]  = lo + hi;
            unpack2(s2b, lo, hi); sb_[u] = lo + hi;
        }
        float cma = sa[0], cmb = sb_[0];
        #pragma unroll
        for (int u = 1; u < 8; u++) { cma = fmaxf(cma, sa[u]); cmb = fmaxf(cmb, sb_[u]); }
        float mna = fmaxf(ma, cma), mnb = fmaxf(mb, cmb);
        float coa = __expf(ma - mna), cob = __expf(mb - mnb);
        ma = mna; mb = mnb;
        la *= coa; lb *= cob;
        unsigned long long coa2 = pack2(coa, coa), cob2 = pack2(cob, cob);
        #pragma unroll
        for (int i = 0; i < 15; i++) { acc2a[i] = mul2(acc2a[i], coa2); acc2b[i] = mul2(acc2b[i], cob2); }
        #pragma unroll
        for (int u = 0; u < 8; u++) {
            float pa = __expf(sa[u] - mna), pb = __expf(sb_[u] - mnb);
            la += pa; lb += pb;
            unsigned long long pa2 = pack2(pa, pa), pb2 = pack2(pb, pb);
            const unsigned long long* v2 = (const unsigned long long*)Vs[jc + u];
            #pragma unroll
            for (int i = 0; i < 15; i++) {
                unsigned long long vv_ = v2[i];
                fma2(acc2a[i], pa2, vv_);
                fma2(acc2b[i], pb2, vv_);
            }
        }
    }
    float inva = 1.f / la, invb = 1.f / lb;
    float2* ora = (float2*)(yout + ((size_t)(b * NTOK + rna)) * DIMC + hh * HD);
    float2* orb = (float2*)(yout + ((size_t)(b * NTOK + rnb)) * DIMC + hh * HD);
    #pragma unroll
    for (int i = 0; i < 15; i++) {
        float lo, hi;
        unpack2(acc2a[i], lo, hi); ora[i] = make_float2(lo * inva, hi * inva);
        unpack2(acc2b[i], lo, hi); orb[i] = make_float2(lo * invb, hi * invb);
    }
}

// ---------------------------------------------------------------------------
// Window attention: 128 threads, 2 queries/thread, shared K/V stream.
// ---------------------------------------------------------------------------
__global__ __launch_bounds__(128) void winattn_kernel(const float* __restrict__ qkv,
                                                      float* __restrict__ yout) {
    extern __shared__ float sm[];
    float* Ks = sm;
    float* Vs = sm + WINN * 32;
    int bi = blockIdx.x;
    int hh = bi % HEADS;
    int wdx = bi / HEADS;
    int b = wdx >> 4;
    int wy = (wdx >> 2) & 3;
    int wx = wdx & 3;
    int t = threadIdx.x;               // 0..127
    int lane = t & 31;
    int warp = t >> 5;                 // 0..3
    #pragma unroll 4
    for (int u = 0; u < 64; u++) {
        int rr = warp * 64 + u;
        int ny = (wy * WS + (rr >> 4)) * WW + wx * WS + (rr & 15);
        size_t rb = ((size_t)(b * NTOK + ny)) * QKVW + hh * HD;
        float kv = 0.f, vv_ = 0.f;
        if (lane < HD) {
            kv  = qkv[rb + 180 + lane];
            vv_ = qkv[rb + 360 + lane];
        }
        Ks[rr * 32 + lane] = kv;
        Vs[rr * 32 + lane] = vv_;
    }
    const float scale = 0.18257418583505536f;
    int qa_i = t, qb_i = t + 128;
    int na = (wy * WS + (qa_i >> 4)) * WW + wx * WS + (qa_i & 15);
    int nb = (wy * WS + (qb_i >> 4)) * WW + wx * WS + (qb_i & 15);
    const float2* qpa = (const float2*)(qkv + ((size_t)(b * NTOK + na)) * QKVW + hh * HD);
    const float2* qpb = (const float2*)(qkv + ((size_t)(b * NTOK + nb)) * QKVW + hh * HD);
    unsigned long long q2a[15], q2b[15];
    #pragma unroll
    for (int i = 0; i < 15; i++) {
        float2 va = qpa[i], vb = qpb[i];
        q2a[i] = pack2(va.x * scale, va.y * scale);
        q2b[i] = pack2(vb.x * scale, vb.y * scale);
    }
    __syncthreads();
    const float* browa = g_wbias + ((size_t)hh * WINN + qa_i) * WINN;
    const float* browb = g_wbias + ((size_t)hh * WINN + qb_i) * WINN;
    float ma = -1e30f, la = 0.f, mb = -1e30f, lb = 0.f;
    unsigned long long acc2a[15], acc2b[15];
    #pragma unroll
    for (int i = 0; i < 15; i++) { acc2a[i] = pack2(0.f, 0.f); acc2b[i] = pack2(0.f, 0.f); }
    for (int jc = 0; jc < WINN; jc += 8) {
        float sa[8], sb_[8];
        #pragma unroll
        for (int u = 0; u < 8; u++) {
            const unsigned long long* k2 = (const unsigned long long*)(Ks + (jc + u) * 32);
            unsigned long long s2a = pack2(0.f, 0.f), s2b = pack2(0.f, 0.f);
            #pragma unroll
            for (int i = 0; i < 15; i++) {
                unsigned long long kk = k2[i];
                fma2(s2a, q2a[i], kk);
                fma2(s2b, q2b[i], kk);
            }
            float lo, hi;
            unpack2(s2a, lo, hi); sa[u]  = lo + hi + browa[jc + u];
            unpack2(s2b, lo, hi); sb_[u] = lo + hi + browb[jc + u];
        }
        float cma = sa[0], cmb = sb_[0];
        #pragma unroll
        for (int u = 1; u < 8; u++) { cma = fmaxf(cma, sa[u]); cmb = fmaxf(cmb, sb_[u]); }
        float mna = fmaxf(ma, cma), mnb = fmaxf(mb, cmb);
        float coa = __expf(ma - mna), cob = __expf(mb - mnb);
        ma = mna; mb = mnb;
        la *= coa; lb *= cob;
        unsigned long long coa2 = pack2(coa, coa), cob2 = pack2(cob, cob);
        #pragma unroll
        for (int i = 0; i < 15; i++) { acc2a[i] = mul2(acc2a[i], coa2); acc2b[i] = mul2(acc2b[i], cob2); }
        #pragma unroll
        for (int u = 0; u < 8; u++) {
            float pa = __expf(sa[u] - mna), pb = __expf(sb_[u] - mnb);
            la += pa; lb += pb;
            unsigned long long pa2 = pack2(pa, pa), pb2 = pack2(pb, pb);
            const unsigned long long* v2 = (const unsigned long long*)(Vs + (jc + u) * 32);
            #pragma unroll
            for (int i = 0; i < 15; i++) {
                unsigned long long vv_ = v2[i];
                fma2(acc2a[i], pa2, vv_);
                fma2(acc2b[i], pb2, vv_);
            }
        }
    }
    float inva = 1.f / la, invb = 1.f / lb;
    float2* ora = (float2*)(yout + ((size_t)(b * NTOK + na)) * DIMC + hh * HD);
    float2* orb = (float2*)(yout + ((size_t)(b * NTOK + nb)) * DIMC + hh * HD);
    #pragma unroll
    for (int i = 0; i < 15; i++) {
        float lo, hi;
        unpack2(acc2a[i], lo, hi); ora[i] = make_float2(lo * inva, hi * inva);
        unpack2(acc2b[i], lo, hi); orb[i] = make_float2(lo * invb, hi * invb);
    }
}

// ---------------------------------------------------------------------------
// Gather per-token dictionary features into hc[:, 360:424]
// ---------------------------------------------------------------------------
__global__ void gathertd_kernel(const float* __restrict__ tdproj, const int* __restrict__ tkid,
                                float* __restrict__ hc) {
    int e = blockIdx.x * blockDim.x + threadIdx.x;
    if (e < ROWS * DTD) {
        int r = e >> 6, j = e & 63;
        int b = r >> 12;
        hc[(size_t)r * CFF + MLP_HID + j] = tdproj[((size_t)b * MTOK + tkid[r]) * DTD + j];
    }
}

// ---------------------------------------------------------------------------
// Depthwise 5x5 conv, tiled: 16x16 pixels x 8 channels per block.
// ---------------------------------------------------------------------------
#define DWCH 8
__global__ void dwconv_kernel(const float* __restrict__ hc, const float* __restrict__ w,
                              const float* __restrict__ bias, float* __restrict__ hc2) {
    __shared__ float smd[20 * 20 * DWCH];
    __shared__ float wsm[25][DWCH];
    __shared__ float bsm[DWCH];
    int tid = threadIdx.x;
    int c0 = blockIdx.y * DWCH;
    int b  = blockIdx.z;
    int tileY = (blockIdx.x >> 2) * 16, tileX = (blockIdx.x & 3) * 16;
    if (tid < 200) { int t5 = tid % 25, j = tid / 25; wsm[t5][j] = w[(c0 + j) * 25 + t5]; }
    if (tid < DWCH) bsm[tid] = bias[c0 + tid];
    for (int i = tid; i < 800; i += 256) {
        int cell = i >> 1, half = i & 1;
        int cy = cell / 20, cx = cell % 20;
        int gy = tileY + cy - 2, gx = tileX + cx - 2;
        float4 v = {0.f, 0.f, 0.f, 0.f};
        if (gy >= 0 && gy < 64 && gx >= 0 && gx < 64)
            v = *(const float4*)&hc[(((size_t)b << 12) + (gy << 6) + gx) * CFF + c0 + half * 4];
        *(float4*)&smd[cell * 8 + half * 4] = v;
    }
    __syncthreads();
    int ty = tid >> 4, tx = tid & 15;
    float acc[DWCH];
    #pragma unroll
    for (int j = 0; j < DWCH; j++) acc[j] = 0.f;
    #pragma unroll
    for (int ky = 0; ky < 5; ky++) {
        #pragma unroll
        for (int kx = 0; kx < 5; kx++) {
            const float* cp = &smd[((ty + ky) * 20 + tx + kx) * 8];
            float4 a0 = *(const float4*)cp;
            float4 a1 = *(const float4*)(cp + 4);
            int t5 = ky * 5 + kx;
            acc[0] += a0.x * wsm[t5][0];
            acc[1] += a0.y * wsm[t5][1];
            acc[2] += a0.z * wsm[t5][2];
            acc[3] += a0.w * wsm[t5][3];
            acc[4] += a1.x * wsm[t5][4];
            acc[5] += a1.y * wsm[t5][5];
            acc[6] += a1.z * wsm[t5][6];
            acc[7] += a1.w * wsm[t5][7];
        }
    }
    const float* ctr = &smd[((ty + 2) * 20 + tx + 2) * 8];
    size_t idx = (((size_t)b << 12) + ((size_t)(tileY + ty) << 6) + (tileX + tx)) * CFF + c0;
    float4 o0, o1;
    o0.x = ctr[0] + gelu_exact(acc[0] + bsm[0]);
    o0.y = ctr[1] + gelu_exact(acc[1] + bsm[1]);
    o0.z = ctr[2] + gelu_exact(acc[2] + bsm[2]);
    o0.w = ctr[3] + gelu_exact(acc[3] + bsm[3]);
    o1.x = ctr[4] + gelu_exact(acc[4] + bsm[4]);
    o1.y = ctr[5] + gelu_exact(acc[5] + bsm[5]);
    o1.z = ctr[6] + gelu_exact(acc[6] + bsm[6]);
    o1.w = ctr[7] + gelu_exact(acc[7] + bsm[7]);
    *(float4*)&hc2[idx] = o0;
    *(float4*)&hc2[idx + 4] = o1;
}

// ---------------------------------------------------------------------------
// Launch
// ---------------------------------------------------------------------------
extern "C" void kernel_launch(void* const* d_in, const int* in_sizes, int n_in,
                              void* d_out, int out_size) {
    const float* x        = (const float*)d_in[0];
    const float* td       = (const float*)d_in[1];
    const float* n1g      = (const float*)d_in[2];
    const float* n1b      = (const float*)d_in[3];
    const float* wqkv_w   = (const float*)d_in[4];
    const float* wqkv_b   = (const float*)d_in[5];
    const float* atd_wq_w = (const float*)d_in[6];
    const float* atd_wq_b = (const float*)d_in[7];
    const float* atd_wk_w = (const float*)d_in[8];
    const float* atd_wk_b = (const float*)d_in[9];
    const float* atd_wv_w = (const float*)d_in[10];
    const float* atd_wv_b = (const float*)d_in[11];
    const float* atd_sc   = (const float*)d_in[12];
    const float* aca_w    = (const float*)d_in[13];
    const float* aca_b    = (const float*)d_in[14];
    const float* win_rpb  = (const float*)d_in[15];
    const float* win_w    = (const float*)d_in[16];
    const float* win_b    = (const float*)d_in[17];
    const float* fctd_w   = (const float*)d_in[18];
    const float* fctd_b   = (const float*)d_in[19];
    const float* fc1_w    = (const float*)d_in[20];
    const float* fc1_b    = (const float*)d_in[21];
    const float* dw_w     = (const float*)d_in[22];
    const float* dw_b     = (const float*)d_in[23];
    const float* fc2_w    = (const float*)d_in[24];
    const float* fc2_b    = (const float*)d_in[25];
    const float* n2g      = (const float*)d_in[26];
    const float* n2b      = (const float*)d_in[27];
    const int*   rpi      = (const int*)d_in[28];
    float* out = (float*)d_out;

    float *xn, *qkv, *qatd, *kkn, *vv, *tdpr, *patd, *yaca, *ywin, *xsum, *x2n, *hc, *hc2;
    int *tkid, *sidx;
    cudaGetSymbolAddress((void**)&xn,   g_xn);
    cudaGetSymbolAddress((void**)&qkv,  g_qkv);
    cudaGetSymbolAddress((void**)&qatd, g_qatd);
    cudaGetSymbolAddress((void**)&kkn,  g_kkn);
    cudaGetSymbolAddress((void**)&vv,   g_vv);
    cudaGetSymbolAddress((void**)&tdpr, g_tdpr);
    cudaGetSymbolAddress((void**)&patd, g_patd);
    cudaGetSymbolAddress((void**)&yaca, g_yaca);
    cudaGetSymbolAddress((void**)&ywin, g_ywin);
    cudaGetSymbolAddress((void**)&xsum, g_xsum);
    cudaGetSymbolAddress((void**)&x2n,  g_x2n);
    cudaGetSymbolAddress((void**)&hc,   g_hc);
    cudaGetSymbolAddress((void**)&hc2,  g_hc2);
    cudaGetSymbolAddress((void**)&tkid, g_tkid);
    cudaGetSymbolAddress((void**)&sidx, g_sidx);

    cudaFuncSetAttribute(winattn_kernel, cudaFuncAttributeMaxDynamicSharedMemorySize, 65536);

    // 1. dictionary projections
    dict_kernel<<<BATCH*MTOK, 256>>>(td, atd_wk_w, atd_wk_b, atd_wv_w, atd_wv_b,
                                     fctd_w, fctd_b, kkn, vv, tdpr);
    // 2. window bias expansion
    wbias_kernel<<<WINN*WINN/256, 256>>>(rpi, win_rpb);
    // 3. LN1 (+ fused q_atd projection)
    ln_kernel<<<ROWS/8, 256>>>(x, n1g, n1b, xn, atd_wq_w, atd_wq_b, qatd);
    // 4. qkv = xn @ wqkv + b
    gemm_tc<<<dim3(9, ROWS/128), 256>>>(xn, wqkv_w, DIMC, nullptr, nullptr, 0,
                                        nullptr, nullptr, 0, 0,
                                        wqkv_b, nullptr, nullptr,
                                        qkv, ROWS, QKVW, QKVW, 0);
    // 5. ATD probs + tk_id
    atd_kernel<<<ROWS/8, 256>>>(qatd, kkn, atd_sc, patd, tkid);
    // 6. window attention  (<- ncu sample target)
    winattn_kernel<<<NWIN*HEADS, 128, 65536>>>(qkv, ywin);
    // 7. single-pass stable sort scatter
    sortscatter_kernel<<<BATCH*MTOK, 256>>>(tkid, sidx);
    // 8. grouped attention
    acmsa_kernel<<<BATCH*NG*HEADS, 64>>>(qkv, sidx, yaca);
    // 9. xsum = x + P@vv (batched) + yaca@aca_w + ywin@win_w + biases
    gemm_tc<<<dim3(3, ROWS/128), 256>>>(yaca, aca_w, DIMC, ywin, win_w, DIMC,
                                        patd, vv, (long)MTOK*DIMC, MTOK,
                                        aca_b, win_b, x,
                                        xsum, ROWS, DIMC, DIMC, 0);
    // 10. LN2
    ln_kernel<<<ROWS/8, 256>>>(xsum, n2g, n2b, x2n, nullptr, nullptr, nullptr);
    // 11. fc1 + GELU into hc[:, 0:360]
    gemm_tc<<<dim3(6, ROWS/128), 256>>>(x2n, fc1_w, DIMC, nullptr, nullptr, 0,
                                        nullptr, nullptr, 0, 0,
                                        fc1_b, nullptr, nullptr,
                                        hc, ROWS, MLP_HID, CFF, 1);
    // 12. gather td features into hc[:, 360:424]
    gathertd_kernel<<<ROWS*DTD/256, 256>>>(tdpr, tkid, hc);
    // 13. depthwise conv + gelu + residual (tiled)
    dwconv_kernel<<<dim3(16, CFF/DWCH, BATCH), 256>>>(hc, dw_w, dw_b, hc2);
    // 14. out = xsum + hc2 @ fc2_w + fc2_b
    gemm_tc<<<dim3(3, ROWS/128), 256>>>(hc2, fc2_w, CFF, nullptr, nullptr, 0,
                                        nullptr, nullptr, 0, 0,
                                        fc2_b, nullptr, xsum,
                                        out, ROWS, DIMC, DIMC, 0);
}

// round 10
// speedup vs baseline: 1.2526x; 1.1661x over previous
#include <cuda_runtime.h>
#include <cuda_bf16.h>
#include <math.h>

// ---------------------------------------------------------------------------
// Problem constants
// ---------------------------------------------------------------------------
#define BATCH 8
#define NTOK 4096
#define ROWS (BATCH*NTOK)
#define DIMC 180
#define HEADS 6
#define HD 30
#define QKVW 540
#define MTOK 64
#define RDIM 10
#define GS 128
#define NG 32
#define WS 16
#define WINN 256
#define NWIN 128
#define MLP_HID 360
#define DTD 64
#define CFF 424
#define HH 64
#define WW 64

// bf16 weight scratch offsets (elements)
#define WT_QKV 0
#define WT_ACA (WT_QKV + DIMC*QKVW)
#define WT_WIN (WT_ACA + DIMC*DIMC)
#define WT_FC1 (WT_WIN + DIMC*DIMC)
#define WT_FC2 (WT_FC1 + DIMC*MLP_HID)
#define WT_TOTAL (WT_FC2 + CFF*DIMC)

// ---------------------------------------------------------------------------
// Scratch
// ---------------------------------------------------------------------------
__device__ unsigned short g_xn  [ROWS*DIMC];        // bf16
__device__ float g_qkv  [ROWS*QKVW];
__device__ float g_qatd [ROWS*RDIM];
__device__ float g_kkn  [BATCH*MTOK*RDIM];
__device__ unsigned short g_vvt [BATCH*DIMC*MTOK];  // bf16, transposed [b][n][m]
__device__ float g_tdpr [BATCH*MTOK*DTD];
__device__ unsigned short g_patd[ROWS*MTOK];        // bf16
__device__ int   g_tkid [ROWS];
__device__ int   g_sidx [ROWS];
__device__ unsigned short g_yaca[ROWS*DIMC];        // bf16
__device__ unsigned short g_ywin[ROWS*DIMC];        // bf16
__device__ float g_xsum [ROWS*DIMC];
__device__ unsigned short g_x2n [ROWS*DIMC];        // bf16
__device__ float g_hc   [ROWS*CFF];
__device__ unsigned short g_hc2 [ROWS*CFF];         // bf16
__device__ float g_wbias[HEADS*WINN*WINN];
__device__ unsigned short g_wt  [WT_TOTAL];         // bf16 transposed weights

// ---------------------------------------------------------------------------
// Helpers
// ---------------------------------------------------------------------------
__device__ __forceinline__ float warp_sum(float v) {
    #pragma unroll
    for (int o = 16; o; o >>= 1) v += __shfl_xor_sync(0xffffffffu, v, o);
    return v;
}
__device__ __forceinline__ float gelu_exact(float v) {
    return 0.5f * v * (1.0f + erff(v * 0.70710678118654752440f));
}
__device__ __forceinline__ unsigned long long pack2(float lo, float hi) {
    unsigned long long r;
    asm("mov.b64 %0,{%1,%2};" : "=l"(r) : "f"(lo), "f"(hi));
    return r;
}
__device__ __forceinline__ void unpack2(unsigned long long v, float& lo, float& hi) {
    asm("mov.b64 {%0,%1},%2;" : "=f"(lo), "=f"(hi) : "l"(v));
}
__device__ __forceinline__ void fma2(unsigned long long& d, unsigned long long a,
                                     unsigned long long b) {
    asm("fma.rn.f32x2 %0,%1,%2,%0;" : "+l"(d) : "l"(a), "l"(b));
}
__device__ __forceinline__ unsigned long long mul2(unsigned long long a, unsigned long long b) {
    unsigned long long r;
    asm("mul.rn.f32x2 %0,%1,%2;" : "=l"(r) : "l"(a), "l"(b));
    return r;
}
__device__ __forceinline__ unsigned smem_u32(const void* p) {
    return (unsigned)__cvta_generic_to_shared(p);
}
__device__ __forceinline__ unsigned short f2bf(float v) {
    __nv_bfloat16 h = __float2bfloat16_rn(v);
    return *(unsigned short*)&h;
}
__device__ __forceinline__ unsigned bf2pack(float lo, float hi) {
    __nv_bfloat162 h = __floats2bfloat162_rn(lo, hi);
    return *(unsigned*)&h;
}

// ---------------------------------------------------------------------------
// Weight transpose+convert: Wt[n][k] = bf16(W[k][n])
// ---------------------------------------------------------------------------
__global__ void convw_kernel(const float* __restrict__ W, unsigned short* __restrict__ Wt,
                             int K, int N) {
    int i = blockIdx.x * blockDim.x + threadIdx.x;
    if (i < N * K) {
        int n = i / K, k = i % K;
        Wt[i] = f2bf(W[(size_t)k * N + n]);
    }
}

// ---------------------------------------------------------------------------
// Fused dictionary projections: kkn fp32 l2n, vvt bf16 transposed, tdpr fp32
// ---------------------------------------------------------------------------
__global__ void dict_kernel(const float* __restrict__ td,
                            const float* __restrict__ wk_w, const float* __restrict__ wk_b,
                            const float* __restrict__ wv_w, const float* __restrict__ wv_b,
                            const float* __restrict__ ftd_w, const float* __restrict__ ftd_b,
                            float* __restrict__ kkn, unsigned short* __restrict__ vvt,
                            float* __restrict__ tdpr) {
    int r = blockIdx.x;                 // 0..511
    int b = r >> 6, m = r & 63;
    __shared__ float as[DIMC];
    __shared__ float kbuf[RDIM];
    int tid = threadIdx.x;
    const float* ar = td + (size_t)r * DIMC;
    if (tid < DIMC) as[tid] = ar[tid];
    __syncthreads();
    if (tid < DIMC) {
        float acc = wv_b[tid];
        #pragma unroll 4
        for (int k = 0; k < DIMC; k++) acc += as[k] * wv_w[(size_t)k * DIMC + tid];
        vvt[((size_t)b * DIMC + tid) * MTOK + m] = f2bf(acc);
    } else if (tid < DIMC + DTD) {
        int c = tid - DIMC;
        float acc = ftd_b[c];
        #pragma unroll 4
        for (int k = 0; k < DIMC; k++) acc += as[k] * ftd_w[(size_t)k * DTD + c];
        tdpr[(size_t)r * DTD + c] = acc;
    } else if (tid < DIMC + DTD + RDIM) {
        int c = tid - DIMC - DTD;
        float acc = wk_b[c];
        #pragma unroll 4
        for (int k = 0; k < DIMC; k++) acc += as[k] * wk_w[(size_t)k * RDIM + c];
        kbuf[c] = acc;
    }
    __syncthreads();
    if (tid >= DIMC + DTD && tid < DIMC + DTD + RDIM) {
        int c = tid - DIMC - DTD;
        float ss = 0.f;
        #pragma unroll
        for (int j = 0; j < RDIM; j++) ss += kbuf[j] * kbuf[j];
        float inv = 1.f / fmaxf(sqrtf(ss), 1e-12f);
        kkn[(size_t)r * RDIM + c] = kbuf[c] * inv;
    }
}

// ---------------------------------------------------------------------------
// Window attention bias expansion
// ---------------------------------------------------------------------------
__global__ void wbias_kernel(const int* __restrict__ rpi, const float* __restrict__ rpb) {
    int e = blockIdx.x * blockDim.x + threadIdx.x;
    if (e < WINN * WINN) {
        int idx = rpi[e];
        #pragma unroll
        for (int h = 0; h < HEADS; h++) g_wbias[h * WINN * WINN + e] = rpb[idx * HEADS + h];
    }
}

// ---------------------------------------------------------------------------
// LayerNorm -> bf16 out (+ optional fused 10-dim q projection, fp32)
// ---------------------------------------------------------------------------
__global__ void ln_kernel(const float* __restrict__ x, const float* __restrict__ g,
                          const float* __restrict__ b, unsigned short* __restrict__ out,
                          const float* __restrict__ wq, const float* __restrict__ bq,
                          float* __restrict__ qout) {
    __shared__ float ws[1920];
    __shared__ float bqs[16];
    int tid = threadIdx.x;
    if (wq) {
        for (int i = tid; i < 1920; i += 256) ws[i] = (i < DIMC * RDIM) ? wq[i] : 0.f;
        if (tid < RDIM) bqs[tid] = bq[tid];
        __syncthreads();
    }
    int row = (blockIdx.x * blockDim.x + tid) >> 5;
    if (row >= ROWS) return;
    int lane = tid & 31;
    const float* xr = x + (size_t)row * DIMC;
    float v[6], s = 0.f, s2 = 0.f;
    #pragma unroll
    for (int k = 0; k < 6; k++) {
        int c = lane + k * 32;
        v[k] = (c < DIMC) ? xr[c] : 0.f;
        s += v[k]; s2 += v[k] * v[k];
    }
    s = warp_sum(s); s2 = warp_sum(s2);
    float mu = s * (1.f / DIMC);
    float var = s2 * (1.f / DIMC) - mu * mu;
    float rstd = rsqrtf(var + 1e-5f);
    float nv[6];
    unsigned short* orow = out + (size_t)row * DIMC;
    #pragma unroll
    for (int k = 0; k < 6; k++) {
        int c = lane + k * 32;
        nv[k] = (c < DIMC) ? ((v[k] - mu) * rstd * g[c] + b[c]) : 0.f;
        if (c < DIMC) orow[c] = f2bf(nv[k]);
    }
    if (wq) {
        float myq = 0.f;
        #pragma unroll
        for (int o = 0; o < RDIM; o++) {
            float p = 0.f;
            #pragma unroll
            for (int k = 0; k < 6; k++) p += nv[k] * ws[(lane + 32 * k) * RDIM + o];
            p = warp_sum(p);
            if (lane == o) myq = p + bqs[o];
        }
        if (lane < RDIM) qout[(size_t)row * RDIM + lane] = myq;
    }
}

// ---------------------------------------------------------------------------
// bf16 tensor-core GEMM (m16n8k16), 2-buffer cp.async (8-BYTE chunks — K=180
// rows are only 8B aligned in bf16), one sync per ktile. BK=32.
// A [M,K] bf16 row-major; W pre-transposed bf16 Wt[N][K].
// C = act( A1@W1 + A2@W2 + A3@W3(batched) + b1 + b2 + add1 ) fp32.
// ---------------------------------------------------------------------------
struct GPass { const unsigned short* A; const unsigned short* W; int K; int kt; };

__global__ __launch_bounds__(256) void gemm_bf(
        const unsigned short* __restrict__ A1, const unsigned short* __restrict__ W1, int K1,
        const unsigned short* __restrict__ A2, const unsigned short* __restrict__ W2, int K2,
        const unsigned short* __restrict__ A3, const unsigned short* __restrict__ W3base,
        long w3_stride, int K3,
        const float* __restrict__ b1, const float* __restrict__ b2,
        const float* __restrict__ add1,
        float* __restrict__ C, int M, int N, int ldc, int act) {
    __shared__ unsigned short As[2][128][40];   // 20.5 KB
    __shared__ unsigned short Ws[2][64][40];    // 10.25 KB
    int tid  = threadIdx.x;
    int lane = tid & 31;
    int warp = tid >> 5;
    int warpM = warp & 3;
    int warpN = warp >> 2;
    int gId = lane >> 2;
    int tig = lane & 3;
    int row0 = blockIdx.y * 128;
    int col0 = blockIdx.x * 64;

    GPass ps[3];
    int np = 0;
    if (A1 && K1 > 0) ps[np++] = {A1, W1, K1, (K1 + 31) >> 5};
    if (A2 && K2 > 0) ps[np++] = {A2, W2, K2, (K2 + 31) >> 5};
    if (A3 && K3 > 0) ps[np++] = {A3, W3base + (size_t)(row0 >> 12) * w3_stride, K3, (K3 + 31) >> 5};
    int total = 0;
    for (int p = 0; p < np; p++) total += ps[p].kt;

    auto copy_tile = [&](int gi, int buf) {
        int p = 0, loc = gi;
        while (loc >= ps[p].kt) { loc -= ps[p].kt; p++; }
        const unsigned short* A = ps[p].A;
        const unsigned short* W = ps[p].W;
        int K = ps[p].K;
        int k0 = loc << 5;
        // A tile: 128 rows x 32 k bf16 = 1024 chunks of 8B (4 bf16) -> 4/thread
        #pragma unroll
        for (int f = 0; f < 4; f++) {
            int c = tid + f * 256;
            int m = c >> 3, kc = (c & 7) << 2;
            int gk = k0 + kc;
            int rem = K - gk;
            int bytes = (rem <= 0) ? 0 : ((rem >= 4) ? 8 : rem * 2);
            const unsigned short* src = bytes ? (A + (size_t)(row0 + m) * K + gk) : A;
            unsigned dst = smem_u32(&As[buf][m][kc]);
            asm volatile("cp.async.ca.shared.global [%0], [%1], 8, %2;"
                         :: "r"(dst), "l"(src), "r"(bytes));
        }
        // W tile: 64 n-rows x 32 k bf16 = 512 chunks of 8B -> 2/thread
        #pragma unroll
        for (int f = 0; f < 2; f++) {
            int c = tid + f * 256;
            int n = c >> 3, kc = (c & 7) << 2;
            int gn = col0 + n, gk = k0 + kc;
            int bytes = 0;
            if (gn < N) {
                int rem = K - gk;
                bytes = (rem <= 0) ? 0 : ((rem >= 4) ? 8 : rem * 2);
            }
            const unsigned short* src = bytes ? (W + (size_t)gn * K + gk) : W;
            unsigned dst = smem_u32(&Ws[buf][n][kc]);
            asm volatile("cp.async.ca.shared.global [%0], [%1], 8, %2;"
                         :: "r"(dst), "l"(src), "r"(bytes));
        }
    };

    float d[2][4][4];
    #pragma unroll
    for (int mt = 0; mt < 2; mt++)
        #pragma unroll
        for (int nt = 0; nt < 4; nt++)
            #pragma unroll
            for (int i = 0; i < 4; i++) d[mt][nt][i] = 0.f;

    copy_tile(0, 0);
    asm volatile("cp.async.commit_group;");
    for (int i = 0; i < total; i++) {
        asm volatile("cp.async.wait_group 0;");
        __syncthreads();
        if (i + 1 < total) {
            copy_tile(i + 1, (i + 1) & 1);
            asm volatile("cp.async.commit_group;");
        }
        int buf = i & 1;
        #pragma unroll
        for (int ks = 0; ks < 2; ks++) {
            int kb = ks * 16;
            unsigned a[2][4], bfr[4][2];
            #pragma unroll
            for (int mt = 0; mt < 2; mt++) {
                int m0 = warpM * 32 + mt * 16;
                a[mt][0] = *(const unsigned*)&As[buf][m0 + gId    ][kb + 2*tig    ];
                a[mt][1] = *(const unsigned*)&As[buf][m0 + gId + 8][kb + 2*tig    ];
                a[mt][2] = *(const unsigned*)&As[buf][m0 + gId    ][kb + 2*tig + 8];
                a[mt][3] = *(const unsigned*)&As[buf][m0 + gId + 8][kb + 2*tig + 8];
            }
            #pragma unroll
            for (int nt = 0; nt < 4; nt++) {
                int n0 = warpN * 32 + nt * 8;
                bfr[nt][0] = *(const unsigned*)&Ws[buf][n0 + gId][kb + 2*tig    ];
                bfr[nt][1] = *(const unsigned*)&Ws[buf][n0 + gId][kb + 2*tig + 8];
            }
            #pragma unroll
            for (int mt = 0; mt < 2; mt++)
                #pragma unroll
                for (int nt = 0; nt < 4; nt++) {
                    asm volatile(
                        "mma.sync.aligned.m16n8k16.row.col.f32.bf16.bf16.f32 "
                        "{%0,%1,%2,%3},{%4,%5,%6,%7},{%8,%9},{%0,%1,%2,%3};"
                        : "+f"(d[mt][nt][0]), "+f"(d[mt][nt][1]),
                          "+f"(d[mt][nt][2]), "+f"(d[mt][nt][3])
                        : "r"(a[mt][0]), "r"(a[mt][1]), "r"(a[mt][2]), "r"(a[mt][3]),
                          "r"(bfr[nt][0]), "r"(bfr[nt][1]));
                }
        }
    }

    #pragma unroll
    for (int mt = 0; mt < 2; mt++) {
        #pragma unroll
        for (int nt = 0; nt < 4; nt++) {
            #pragma unroll
            for (int i = 0; i < 4; i++) {
                int r = row0 + warpM * 32 + mt * 16 + gId + (i >> 1) * 8;
                int c = col0 + warpN * 32 + nt * 8 + tig * 2 + (i & 1);
                if (c < N) {
                    float v = d[mt][nt][i];
                    if (b1)   v += b1[c];
                    if (b2)   v += b2[c];
                    if (add1) v += add1[(size_t)r * N + c];
                    if (act)  v = gelu_exact(v);
                    C[(size_t)r * ldc + c] = v;
                }
            }
        }
    }
}

// ---------------------------------------------------------------------------
// ATD: softmax probs P (bf16) + argmax tkid. One warp per token. fp32 math.
// ---------------------------------------------------------------------------
__global__ void atd_kernel(const float* __restrict__ qatd, const float* __restrict__ kkn,
                           const float* __restrict__ scale,
                           unsigned short* __restrict__ P, int* __restrict__ tkid) {
    int t = (blockIdx.x * blockDim.x + threadIdx.x) >> 5;
    int lane = threadIdx.x & 31;
    if (t >= ROWS) return;
    int b = t >> 12;
    float q = (lane < RDIM) ? qatd[(size_t)t * RDIM + lane] : 0.f;
    float ss = warp_sum(q * q);
    float qn = q * (1.f / fmaxf(sqrtf(ss), 1e-12f));
    const float* kb = kkn + (size_t)b * MTOK * RDIM;
    float s0 = 0.f, s1 = 0.f;
    #pragma unroll
    for (int d = 0; d < RDIM; d++) {
        float qd = __shfl_sync(0xffffffffu, qn, d);
        s0 += qd * kb[lane * RDIM + d];
        s1 += qd * kb[(lane + 32) * RDIM + d];
    }
    float sc = fminf(fmaxf(scale[0], 0.f), 3.f);
    float ls = 1.f + sc * 4.15888308335967186f;  // log(64)
    s0 *= ls; s1 *= ls;
    float mv = fmaxf(s0, s1);
    int mi = (s0 >= s1) ? lane : lane + 32;
    #pragma unroll
    for (int o = 16; o; o >>= 1) {
        float ov = __shfl_xor_sync(0xffffffffu, mv, o);
        int   oi = __shfl_xor_sync(0xffffffffu, mi, o);
        if (ov > mv || (ov == mv && oi < mi)) { mv = ov; mi = oi; }
    }
    float p0 = __expf(s0 - mv), p1 = __expf(s1 - mv);
    float sum = warp_sum(p0 + p1);
    float inv = 1.f / sum;
    P[(size_t)t * MTOK + lane]      = f2bf(p0 * inv);
    P[(size_t)t * MTOK + lane + 32] = f2bf(p1 * inv);
    if (lane == 0) tkid[t] = mi;
}

// ---------------------------------------------------------------------------
// Single-pass stable counting sort scatter: block = (batch, bin).
// ---------------------------------------------------------------------------
__global__ void sortscatter_kernel(const int* __restrict__ tkid, int* __restrict__ sidx) {
    int b = blockIdx.x >> 6, bin = blockIdx.x & 63;
    const int* tk = tkid + b * NTOK;
    __shared__ int sc[256];
    int t = threadIdx.x;
    int start = t * 16;
    int eq = 0, less = 0;
    int vals[16];
    #pragma unroll
    for (int k = 0; k < 16; k++) {
        vals[k] = tk[start + k];
        eq += (vals[k] == bin);
        less += (vals[k] < bin);
    }
    sc[t] = (less << 16) | eq;
    __syncthreads();
    #pragma unroll
    for (int d = 1; d < 256; d <<= 1) {
        int v = (t >= d) ? sc[t - d] : 0;
        __syncthreads();
        sc[t] += v;
        __syncthreads();
    }
    int base = sc[255] >> 16;
    int pos = base + (sc[t] & 0xffff) - eq;
    #pragma unroll
    for (int k = 0; k < 16; k++)
        if (vals[k] == bin) sidx[b * NTOK + pos++] = start + k;
}

// ---------------------------------------------------------------------------
// AC_MSA grouped attention: 64 threads, 2 queries/thread, bf16 output.
// ---------------------------------------------------------------------------
__global__ __launch_bounds__(64) void acmsa_kernel(
        const float* __restrict__ qkv, const int* __restrict__ sidx,
        unsigned short* __restrict__ yout) {
    int bi = blockIdx.x;
    int hh = bi % HEADS;
    int g  = (bi / HEADS) % NG;
    int b  = bi / (HEADS * NG);
    int t = threadIdx.x;               // 0..63
    int lane = t & 31;
    int warp = t >> 5;                 // 0..1
    __shared__ __align__(16) float Ks[GS][32], Vs[GS][32];
    const int* sb = sidx + b * NTOK + g * GS;
    #pragma unroll 4
    for (int u = 0; u < 64; u++) {
        int rr = warp * 64 + u;
        int r_u = sb[rr];
        size_t rb = ((size_t)(b * NTOK + r_u)) * QKVW + hh * HD;
        float kv = 0.f, vv_ = 0.f;
        if (lane < HD) {
            kv  = qkv[rb + 180 + lane];
            vv_ = qkv[rb + 360 + lane];
        }
        Ks[rr][lane] = kv;
        Vs[rr][lane] = vv_;
    }
    const float scale = 0.18257418583505536f;   // 30^-0.5
    int rna = sb[t], rnb = sb[t + 64];
    const float2* qpa = (const float2*)(qkv + ((size_t)(b * NTOK + rna)) * QKVW + hh * HD);
    const float2* qpb = (const float2*)(qkv + ((size_t)(b * NTOK + rnb)) * QKVW + hh * HD);
    unsigned long long q2a[15], q2b[15];
    #pragma unroll
    for (int i = 0; i < 15; i++) {
        float2 va = qpa[i], vb = qpb[i];
        q2a[i] = pack2(va.x * scale, va.y * scale);
        q2b[i] = pack2(vb.x * scale, vb.y * scale);
    }
    __syncthreads();
    float ma = -1e30f, la = 0.f, mb = -1e30f, lb = 0.f;
    unsigned long long acc2a[15], acc2b[15];
    #pragma unroll
    for (int i = 0; i < 15; i++) { acc2a[i] = pack2(0.f, 0.f); acc2b[i] = pack2(0.f, 0.f); }
    for (int jc = 0; jc < GS; jc += 8) {
        float sa[8], sb_[8];
        #pragma unroll
        for (int u = 0; u < 8; u++) {
            const unsigned long long* k2 = (const unsigned long long*)Ks[jc + u];
            unsigned long long s2a = pack2(0.f, 0.f), s2b = pack2(0.f, 0.f);
            #pragma unroll
            for (int i = 0; i < 15; i++) {
                unsigned long long kk = k2[i];
                fma2(s2a, q2a[i], kk);
                fma2(s2b, q2b[i], kk);
            }
            float lo, hi;
            unpack2(s2a, lo, hi); sa[u]  = lo + hi;
            unpack2(s2b, lo, hi); sb_[u] = lo + hi;
        }
        float cma = sa[0], cmb = sb_[0];
        #pragma unroll
        for (int u = 1; u < 8; u++) { cma = fmaxf(cma, sa[u]); cmb = fmaxf(cmb, sb_[u]); }
        float mna = fmaxf(ma, cma), mnb = fmaxf(mb, cmb);
        float coa = __expf(ma - mna), cob = __expf(mb - mnb);
        ma = mna; mb = mnb;
        la *= coa; lb *= cob;
        unsigned long long coa2 = pack2(coa, coa), cob2 = pack2(cob, cob);
        #pragma unroll
        for (int i = 0; i < 15; i++) { acc2a[i] = mul2(acc2a[i], coa2); acc2b[i] = mul2(acc2b[i], cob2); }
        #pragma unroll
        for (int u = 0; u < 8; u++) {
            float pa = __expf(sa[u] - mna), pb = __expf(sb_[u] - mnb);
            la += pa; lb += pb;
            unsigned long long pa2 = pack2(pa, pa), pb2 = pack2(pb, pb);
            const unsigned long long* v2 = (const unsigned long long*)Vs[jc + u];
            #pragma unroll
            for (int i = 0; i < 15; i++) {
                unsigned long long vv_ = v2[i];
                fma2(acc2a[i], pa2, vv_);
                fma2(acc2b[i], pb2, vv_);
            }
        }
    }
    float inva = 1.f / la, invb = 1.f / lb;
    unsigned* ora = (unsigned*)(yout + ((size_t)(b * NTOK + rna)) * DIMC + hh * HD);
    unsigned* orb = (unsigned*)(yout + ((size_t)(b * NTOK + rnb)) * DIMC + hh * HD);
    #pragma unroll
    for (int i = 0; i < 15; i++) {
        float lo, hi;
        unpack2(acc2a[i], lo, hi); ora[i] = bf2pack(lo * inva, hi * inva);
        unpack2(acc2b[i], lo, hi); orb[i] = bf2pack(lo * invb, hi * invb);
    }
}

// ---------------------------------------------------------------------------
// Window attention: 128 threads, 2 queries/thread, bf16 output.
// ---------------------------------------------------------------------------
__global__ __launch_bounds__(128) void winattn_kernel(const float* __restrict__ qkv,
                                                      unsigned short* __restrict__ yout) {
    extern __shared__ float sm[];
    float* Ks = sm;
    float* Vs = sm + WINN * 32;
    int bi = blockIdx.x;
    int hh = bi % HEADS;
    int wdx = bi / HEADS;
    int b = wdx >> 4;
    int wy = (wdx >> 2) & 3;
    int wx = wdx & 3;
    int t = threadIdx.x;               // 0..127
    int lane = t & 31;
    int warp = t >> 5;                 // 0..3
    #pragma unroll 4
    for (int u = 0; u < 64; u++) {
        int rr = warp * 64 + u;
        int ny = (wy * WS + (rr >> 4)) * WW + wx * WS + (rr & 15);
        size_t rb = ((size_t)(b * NTOK + ny)) * QKVW + hh * HD;
        float kv = 0.f, vv_ = 0.f;
        if (lane < HD) {
            kv  = qkv[rb + 180 + lane];
            vv_ = qkv[rb + 360 + lane];
        }
        Ks[rr * 32 + lane] = kv;
        Vs[rr * 32 + lane] = vv_;
    }
    const float scale = 0.18257418583505536f;
    int qa_i = t, qb_i = t + 128;
    int na = (wy * WS + (qa_i >> 4)) * WW + wx * WS + (qa_i & 15);
    int nb = (wy * WS + (qb_i >> 4)) * WW + wx * WS + (qb_i & 15);
    const float2* qpa = (const float2*)(qkv + ((size_t)(b * NTOK + na)) * QKVW + hh * HD);
    const float2* qpb = (const float2*)(qkv + ((size_t)(b * NTOK + nb)) * QKVW + hh * HD);
    unsigned long long q2a[15], q2b[15];
    #pragma unroll
    for (int i = 0; i < 15; i++) {
        float2 va = qpa[i], vb = qpb[i];
        q2a[i] = pack2(va.x * scale, va.y * scale);
        q2b[i] = pack2(vb.x * scale, vb.y * scale);
    }
    __syncthreads();
    const float* browa = g_wbias + ((size_t)hh * WINN + qa_i) * WINN;
    const float* browb = g_wbias + ((size_t)hh * WINN + qb_i) * WINN;
    float ma = -1e30f, la = 0.f, mb = -1e30f, lb = 0.f;
    unsigned long long acc2a[15], acc2b[15];
    #pragma unroll
    for (int i = 0; i < 15; i++) { acc2a[i] = pack2(0.f, 0.f); acc2b[i] = pack2(0.f, 0.f); }
    for (int jc = 0; jc < WINN; jc += 8) {
        float sa[8], sb_[8];
        #pragma unroll
        for (int u = 0; u < 8; u++) {
            const unsigned long long* k2 = (const unsigned long long*)(Ks + (jc + u) * 32);
            unsigned long long s2a = pack2(0.f, 0.f), s2b = pack2(0.f, 0.f);
            #pragma unroll
            for (int i = 0; i < 15; i++) {
                unsigned long long kk = k2[i];
                fma2(s2a, q2a[i], kk);
                fma2(s2b, q2b[i], kk);
            }
            float lo, hi;
            unpack2(s2a, lo, hi); sa[u]  = lo + hi + browa[jc + u];
            unpack2(s2b, lo, hi); sb_[u] = lo + hi + browb[jc + u];
        }
        float cma = sa[0], cmb = sb_[0];
        #pragma unroll
        for (int u = 1; u < 8; u++) { cma = fmaxf(cma, sa[u]); cmb = fmaxf(cmb, sb_[u]); }
        float mna = fmaxf(ma, cma), mnb = fmaxf(mb, cmb);
        float coa = __expf(ma - mna), cob = __expf(mb - mnb);
        ma = mna; mb = mnb;
        la *= coa; lb *= cob;
        unsigned long long coa2 = pack2(coa, coa), cob2 = pack2(cob, cob);
        #pragma unroll
        for (int i = 0; i < 15; i++) { acc2a[i] = mul2(acc2a[i], coa2); acc2b[i] = mul2(acc2b[i], cob2); }
        #pragma unroll
        for (int u = 0; u < 8; u++) {
            float pa = __expf(sa[u] - mna), pb = __expf(sb_[u] - mnb);
            la += pa; lb += pb;
            unsigned long long pa2 = pack2(pa, pa), pb2 = pack2(pb, pb);
            const unsigned long long* v2 = (const unsigned long long*)(Vs + (jc + u) * 32);
            #pragma unroll
            for (int i = 0; i < 15; i++) {
                unsigned long long vv_ = v2[i];
                fma2(acc2a[i], pa2, vv_);
                fma2(acc2b[i], pb2, vv_);
            }
        }
    }
    float inva = 1.f / la, invb = 1.f / lb;
    unsigned* ora = (unsigned*)(yout + ((size_t)(b * NTOK + na)) * DIMC + hh * HD);
    unsigned* orb = (unsigned*)(yout + ((size_t)(b * NTOK + nb)) * DIMC + hh * HD);
    #pragma unroll
    for (int i = 0; i < 15; i++) {
        float lo, hi;
        unpack2(acc2a[i], lo, hi); ora[i] = bf2pack(lo * inva, hi * inva);
        unpack2(acc2b[i], lo, hi); orb[i] = bf2pack(lo * invb, hi * invb);
    }
}

// ---------------------------------------------------------------------------
// Gather per-token dictionary features into hc[:, 360:424] (fp32)
// ---------------------------------------------------------------------------
__global__ void gathertd_kernel(const float* __restrict__ tdproj, const int* __restrict__ tkid,
                                float* __restrict__ hc) {
    int e = blockIdx.x * blockDim.x + threadIdx.x;
    if (e < ROWS * DTD) {
        int r = e >> 6, j = e & 63;
        int b = r >> 12;
        hc[(size_t)r * CFF + MLP_HID + j] = tdproj[((size_t)b * MTOK + tkid[r]) * DTD + j];
    }
}

// ---------------------------------------------------------------------------
// Depthwise 5x5 conv + GELU + residual; bf16 output hc2.
// ---------------------------------------------------------------------------
#define DWCH 8
__global__ void dwconv_kernel(const float* __restrict__ hc, const float* __restrict__ w,
                              const float* __restrict__ bias, unsigned short* __restrict__ hc2) {
    __shared__ float smd[20 * 20 * DWCH];
    __shared__ float wsm[25][DWCH];
    __shared__ float bsm[DWCH];
    int tid = threadIdx.x;
    int c0 = blockIdx.y * DWCH;
    int b  = blockIdx.z;
    int tileY = (blockIdx.x >> 2) * 16, tileX = (blockIdx.x & 3) * 16;
    if (tid < 200) { int t5 = tid % 25, j = tid / 25; wsm[t5][j] = w[(c0 + j) * 25 + t5]; }
    if (tid < DWCH) bsm[tid] = bias[c0 + tid];
    for (int i = tid; i < 800; i += 256) {
        int cell = i >> 1, half = i & 1;
        int cy = cell / 20, cx = cell % 20;
        int gy = tileY + cy - 2, gx = tileX + cx - 2;
        float4 v = {0.f, 0.f, 0.f, 0.f};
        if (gy >= 0 && gy < 64 && gx >= 0 && gx < 64)
            v = *(const float4*)&hc[(((size_t)b << 12) + (gy << 6) + gx) * CFF + c0 + half * 4];
        *(float4*)&smd[cell * 8 + half * 4] = v;
    }
    __syncthreads();
    int ty = tid >> 4, tx = tid & 15;
    float acc[DWCH];
    #pragma unroll
    for (int j = 0; j < DWCH; j++) acc[j] = 0.f;
    #pragma unroll
    for (int ky = 0; ky < 5; ky++) {
        #pragma unroll
        for (int kx = 0; kx < 5; kx++) {
            const float* cp = &smd[((ty + ky) * 20 + tx + kx) * 8];
            float4 a0 = *(const float4*)cp;
            float4 a1 = *(const float4*)(cp + 4);
            int t5 = ky * 5 + kx;
            acc[0] += a0.x * wsm[t5][0];
            acc[1] += a0.y * wsm[t5][1];
            acc[2] += a0.z * wsm[t5][2];
            acc[3] += a0.w * wsm[t5][3];
            acc[4] += a1.x * wsm[t5][4];
            acc[5] += a1.y * wsm[t5][5];
            acc[6] += a1.z * wsm[t5][6];
            acc[7] += a1.w * wsm[t5][7];
        }
    }
    const float* ctr = &smd[((ty + 2) * 20 + tx + 2) * 8];
    size_t idx = (((size_t)b << 12) + ((size_t)(tileY + ty) << 6) + (tileX + tx)) * CFF + c0;
    float o[8];
    #pragma unroll
    for (int j = 0; j < 8; j++) o[j] = ctr[j] + gelu_exact(acc[j] + bsm[j]);
    uint4 pk;
    pk.x = bf2pack(o[0], o[1]);
    pk.y = bf2pack(o[2], o[3]);
    pk.z = bf2pack(o[4], o[5]);
    pk.w = bf2pack(o[6], o[7]);
    *(uint4*)&hc2[idx] = pk;
}

// ---------------------------------------------------------------------------
// Launch (order: launch #6 = bf16 qkv GEMM for ncu -s 5 -c 1)
// ---------------------------------------------------------------------------
extern "C" void kernel_launch(void* const* d_in, const int* in_sizes, int n_in,
                              void* d_out, int out_size) {
    const float* x        = (const float*)d_in[0];
    const float* td       = (const float*)d_in[1];
    const float* n1g      = (const float*)d_in[2];
    const float* n1b      = (const float*)d_in[3];
    const float* wqkv_w   = (const float*)d_in[4];
    const float* wqkv_b   = (const float*)d_in[5];
    const float* atd_wq_w = (const float*)d_in[6];
    const float* atd_wq_b = (const float*)d_in[7];
    const float* atd_wk_w = (const float*)d_in[8];
    const float* atd_wk_b = (const float*)d_in[9];
    const float* atd_wv_w = (const float*)d_in[10];
    const float* atd_wv_b = (const float*)d_in[11];
    const float* atd_sc   = (const float*)d_in[12];
    const float* aca_w    = (const float*)d_in[13];
    const float* aca_b    = (const float*)d_in[14];
    const float* win_rpb  = (const float*)d_in[15];
    const float* win_w    = (const float*)d_in[16];
    const float* win_b    = (const float*)d_in[17];
    const float* fctd_w   = (const float*)d_in[18];
    const float* fctd_b   = (const float*)d_in[19];
    const float* fc1_w    = (const float*)d_in[20];
    const float* fc1_b    = (const float*)d_in[21];
    const float* dw_w     = (const float*)d_in[22];
    const float* dw_b     = (const float*)d_in[23];
    const float* fc2_w    = (const float*)d_in[24];
    const float* fc2_b    = (const float*)d_in[25];
    const float* n2g      = (const float*)d_in[26];
    const float* n2b      = (const float*)d_in[27];
    const int*   rpi      = (const int*)d_in[28];
    float* out = (float*)d_out;

    float *qkv, *qatd, *kkn, *tdpr, *xsum, *hc;
    unsigned short *xn, *x2n, *yaca, *ywin, *patd, *hc2, *vvt, *wt;
    int *tkid, *sidx;
    cudaGetSymbolAddress((void**)&xn,   g_xn);
    cudaGetSymbolAddress((void**)&qkv,  g_qkv);
    cudaGetSymbolAddress((void**)&qatd, g_qatd);
    cudaGetSymbolAddress((void**)&kkn,  g_kkn);
    cudaGetSymbolAddress((void**)&vvt,  g_vvt);
    cudaGetSymbolAddress((void**)&tdpr, g_tdpr);
    cudaGetSymbolAddress((void**)&patd, g_patd);
    cudaGetSymbolAddress((void**)&yaca, g_yaca);
    cudaGetSymbolAddress((void**)&ywin, g_ywin);
    cudaGetSymbolAddress((void**)&xsum, g_xsum);
    cudaGetSymbolAddress((void**)&x2n,  g_x2n);
    cudaGetSymbolAddress((void**)&hc,   g_hc);
    cudaGetSymbolAddress((void**)&hc2,  g_hc2);
    cudaGetSymbolAddress((void**)&tkid, g_tkid);
    cudaGetSymbolAddress((void**)&sidx, g_sidx);
    cudaGetSymbolAddress((void**)&wt,   g_wt);

    cudaFuncSetAttribute(winattn_kernel, cudaFuncAttributeMaxDynamicSharedMemorySize, 65536);

    // 1. dictionary projections
    dict_kernel<<<BATCH*MTOK, 256>>>(td, atd_wk_w, atd_wk_b, atd_wv_w, atd_wv_b,
                                     fctd_w, fctd_b, kkn, vvt, tdpr);
    // 2. window bias expansion
    wbias_kernel<<<WINN*WINN/256, 256>>>(rpi, win_rpb);
    // 3. LN1 (+ fused q_atd projection), bf16 out
    ln_kernel<<<ROWS/8, 256>>>(x, n1g, n1b, xn, atd_wq_w, atd_wq_b, qatd);
    // 4-5. weight transpose/convert (qkv first — needed by launch 6)
    convw_kernel<<<(DIMC*QKVW + 255)/256, 256>>>(wqkv_w, wt + WT_QKV, DIMC, QKVW);
    convw_kernel<<<(DIMC*DIMC + 255)/256, 256>>>(aca_w,  wt + WT_ACA, DIMC, DIMC);
    // 6. qkv = xn @ wqkv + b  (bf16 TC)  <- ncu capture
    gemm_bf<<<dim3(9, ROWS/128), 256>>>(xn, wt + WT_QKV, DIMC, nullptr, nullptr, 0,
                                        nullptr, nullptr, 0, 0,
                                        wqkv_b, nullptr, nullptr,
                                        qkv, ROWS, QKVW, QKVW, 0);
    // 7-9. remaining weight conversions
    convw_kernel<<<(DIMC*DIMC + 255)/256, 256>>>(win_w, wt + WT_WIN, DIMC, DIMC);
    convw_kernel<<<(DIMC*MLP_HID + 255)/256, 256>>>(fc1_w, wt + WT_FC1, DIMC, MLP_HID);
    convw_kernel<<<(CFF*DIMC + 255)/256, 256>>>(fc2_w, wt + WT_FC2, CFF, DIMC);
    // 10. ATD probs + tk_id
    atd_kernel<<<ROWS/8, 256>>>(qatd, kkn, atd_sc, patd, tkid);
    // 11. window attention
    winattn_kernel<<<NWIN*HEADS, 128, 65536>>>(qkv, ywin);
    // 12. single-pass stable sort scatter
    sortscatter_kernel<<<BATCH*MTOK, 256>>>(tkid, sidx);
    // 13. grouped attention
    acmsa_kernel<<<BATCH*NG*HEADS, 64>>>(qkv, sidx, yaca);
    // 14. xsum = x + P@vv (batched) + yaca@aca_w + ywin@win_w + biases
    gemm_bf<<<dim3(3, ROWS/128), 256>>>(yaca, wt + WT_ACA, DIMC, ywin, wt + WT_WIN, DIMC,
                                        patd, vvt, (long)DIMC*MTOK, MTOK,
                                        aca_b, win_b, x,
                                        xsum, ROWS, DIMC, DIMC, 0);
    // 15. LN2 (bf16 out)
    ln_kernel<<<ROWS/8, 256>>>(xsum, n2g, n2b, x2n, nullptr, nullptr, nullptr);
    // 16. fc1 + GELU into hc[:, 0:360] (fp32)
    gemm_bf<<<dim3(6, ROWS/128), 256>>>(x2n, wt + WT_FC1, DIMC, nullptr, nullptr, 0,
                                        nullptr, nullptr, 0, 0,
                                        fc1_b, nullptr, nullptr,
                                        hc, ROWS, MLP_HID, CFF, 1);
    // 17. gather td features into hc[:, 360:424]
    gathertd_kernel<<<ROWS*DTD/256, 256>>>(tdpr, tkid, hc);
    // 18. depthwise conv + gelu + residual -> hc2 (bf16)
    dwconv_kernel<<<dim3(16, CFF/DWCH, BATCH), 256>>>(hc, dw_w, dw_b, hc2);
    // 19. out = xsum + hc2 @ fc2_w + fc2_b
    gemm_bf<<<dim3(3, ROWS/128), 256>>>(hc2, wt + WT_FC2, CFF, nullptr, nullptr, 0,
                                        nullptr, nullptr, 0, 0,
                                        fc2_b, nullptr, xsum,
                                        out, ROWS, DIMC, DIMC, 0);
}

// round 11
// speedup vs baseline: 1.2814x; 1.0230x over previous
#include <cuda_runtime.h>
#include <cuda_bf16.h>
#include <math.h>

// ---------------------------------------------------------------------------
// Problem constants
// ---------------------------------------------------------------------------
#define BATCH 8
#define NTOK 4096
#define ROWS (BATCH*NTOK)
#define DIMC 180
#define HEADS 6
#define HD 30
#define QKVW 540
#define MTOK 64
#define RDIM 10
#define GS 128
#define NG 32
#define WS 16
#define WINN 256
#define NWIN 128
#define MLP_HID 360
#define DTD 64
#define CFF 424
#define HH 64
#define WW 64

// bf16 weight scratch offsets (elements)
#define WT_QKV 0
#define WT_ACA (WT_QKV + DIMC*QKVW)
#define WT_WIN (WT_ACA + DIMC*DIMC)
#define WT_FC1 (WT_WIN + DIMC*DIMC)
#define WT_FC2 (WT_FC1 + DIMC*MLP_HID)
#define WT_TOTAL (WT_FC2 + CFF*DIMC)

// ---------------------------------------------------------------------------
// Scratch
// ---------------------------------------------------------------------------
__device__ unsigned short g_xn  [ROWS*DIMC];        // bf16
__device__ float g_qkv  [ROWS*QKVW];
__device__ float g_qatd [ROWS*RDIM];
__device__ float g_kkn  [BATCH*MTOK*RDIM];
__device__ unsigned short g_vvt [BATCH*DIMC*MTOK];  // bf16, transposed [b][n][m]
__device__ float g_tdpr [BATCH*MTOK*DTD];
__device__ unsigned short g_patd[ROWS*MTOK];        // bf16
__device__ int   g_tkid [ROWS];
__device__ int   g_sidx [ROWS];
__device__ unsigned short g_yaca[ROWS*DIMC];        // bf16
__device__ unsigned short g_ywin[ROWS*DIMC];        // bf16
__device__ float g_xsum [ROWS*DIMC];
__device__ unsigned short g_x2n [ROWS*DIMC];        // bf16
__device__ float g_hc   [ROWS*CFF];
__device__ unsigned short g_hc2 [ROWS*CFF];         // bf16
__device__ float g_wbias[HEADS*WINN*WINN];
__device__ unsigned short g_wt  [WT_TOTAL];         // bf16 transposed weights

// ---------------------------------------------------------------------------
// Helpers
// ---------------------------------------------------------------------------
__device__ __forceinline__ float warp_sum(float v) {
    #pragma unroll
    for (int o = 16; o; o >>= 1) v += __shfl_xor_sync(0xffffffffu, v, o);
    return v;
}
__device__ __forceinline__ float gelu_exact(float v) {
    return 0.5f * v * (1.0f + erff(v * 0.70710678118654752440f));
}
__device__ __forceinline__ unsigned long long pack2(float lo, float hi) {
    unsigned long long r;
    asm("mov.b64 %0,{%1,%2};" : "=l"(r) : "f"(lo), "f"(hi));
    return r;
}
__device__ __forceinline__ void unpack2(unsigned long long v, float& lo, float& hi) {
    asm("mov.b64 {%0,%1},%2;" : "=f"(lo), "=f"(hi) : "l"(v));
}
__device__ __forceinline__ void fma2(unsigned long long& d, unsigned long long a,
                                     unsigned long long b) {
    asm("fma.rn.f32x2 %0,%1,%2,%0;" : "+l"(d) : "l"(a), "l"(b));
}
__device__ __forceinline__ unsigned long long mul2(unsigned long long a, unsigned long long b) {
    unsigned long long r;
    asm("mul.rn.f32x2 %0,%1,%2;" : "=l"(r) : "l"(a), "l"(b));
    return r;
}
__device__ __forceinline__ unsigned smem_u32(const void* p) {
    return (unsigned)__cvta_generic_to_shared(p);
}
__device__ __forceinline__ unsigned short f2bf(float v) {
    __nv_bfloat16 h = __float2bfloat16_rn(v);
    return *(unsigned short*)&h;
}
__device__ __forceinline__ unsigned bf2pack(float lo, float hi) {
    __nv_bfloat162 h = __floats2bfloat162_rn(lo, hi);
    return *(unsigned*)&h;
}
__device__ __forceinline__ void ldsm4(unsigned& r0, unsigned& r1, unsigned& r2, unsigned& r3,
                                      unsigned addr) {
    asm volatile("ldmatrix.sync.aligned.m8n8.x4.shared.b16 {%0,%1,%2,%3}, [%4];"
                 : "=r"(r0), "=r"(r1), "=r"(r2), "=r"(r3) : "r"(addr));
}

// ---------------------------------------------------------------------------
// Merged weight transpose+convert for all five GEMM weights.
// ---------------------------------------------------------------------------
#define S_QKV (DIMC*QKVW)
#define S_ACA (DIMC*DIMC)
#define S_WIN (DIMC*DIMC)
#define S_FC1 (DIMC*MLP_HID)
#define S_FC2 (CFF*DIMC)
#define S_TOT (S_QKV+S_ACA+S_WIN+S_FC1+S_FC2)

__global__ void convw_all(const float* __restrict__ qkv_w, const float* __restrict__ aca_w,
                          const float* __restrict__ win_w, const float* __restrict__ fc1_w,
                          const float* __restrict__ fc2_w, unsigned short* __restrict__ wt) {
    int i = blockIdx.x * blockDim.x + threadIdx.x;
    if (i >= S_TOT) return;
    const float* W; int K, N, loc, base;
    if (i < S_QKV)                       { W = qkv_w; K = DIMC; N = QKVW;   loc = i;                         base = WT_QKV; }
    else if (i < S_QKV+S_ACA)            { W = aca_w; K = DIMC; N = DIMC;   loc = i - S_QKV;                 base = WT_ACA; }
    else if (i < S_QKV+S_ACA+S_WIN)      { W = win_w; K = DIMC; N = DIMC;   loc = i - S_QKV - S_ACA;         base = WT_WIN; }
    else if (i < S_QKV+S_ACA+S_WIN+S_FC1){ W = fc1_w; K = DIMC; N = MLP_HID;loc = i - S_QKV - S_ACA - S_WIN; base = WT_FC1; }
    else                                 { W = fc2_w; K = CFF;  N = DIMC;   loc = i - S_QKV-S_ACA-S_WIN-S_FC1; base = WT_FC2; }
    int n = loc / K, k = loc % K;
    wt[base + loc] = f2bf(W[(size_t)k * N + n]);
}

// ---------------------------------------------------------------------------
// Fused dictionary projections: kkn fp32 l2n, vvt bf16 transposed, tdpr fp32
// ---------------------------------------------------------------------------
__global__ void dict_kernel(const float* __restrict__ td,
                            const float* __restrict__ wk_w, const float* __restrict__ wk_b,
                            const float* __restrict__ wv_w, const float* __restrict__ wv_b,
                            const float* __restrict__ ftd_w, const float* __restrict__ ftd_b,
                            float* __restrict__ kkn, unsigned short* __restrict__ vvt,
                            float* __restrict__ tdpr) {
    int r = blockIdx.x;                 // 0..511
    int b = r >> 6, m = r & 63;
    __shared__ float as[DIMC];
    __shared__ float kbuf[RDIM];
    int tid = threadIdx.x;
    const float* ar = td + (size_t)r * DIMC;
    if (tid < DIMC) as[tid] = ar[tid];
    __syncthreads();
    if (tid < DIMC) {
        float acc = wv_b[tid];
        #pragma unroll 4
        for (int k = 0; k < DIMC; k++) acc += as[k] * wv_w[(size_t)k * DIMC + tid];
        vvt[((size_t)b * DIMC + tid) * MTOK + m] = f2bf(acc);
    } else if (tid < DIMC + DTD) {
        int c = tid - DIMC;
        float acc = ftd_b[c];
        #pragma unroll 4
        for (int k = 0; k < DIMC; k++) acc += as[k] * ftd_w[(size_t)k * DTD + c];
        tdpr[(size_t)r * DTD + c] = acc;
    } else if (tid < DIMC + DTD + RDIM) {
        int c = tid - DIMC - DTD;
        float acc = wk_b[c];
        #pragma unroll 4
        for (int k = 0; k < DIMC; k++) acc += as[k] * wk_w[(size_t)k * RDIM + c];
        kbuf[c] = acc;
    }
    __syncthreads();
    if (tid >= DIMC + DTD && tid < DIMC + DTD + RDIM) {
        int c = tid - DIMC - DTD;
        float ss = 0.f;
        #pragma unroll
        for (int j = 0; j < RDIM; j++) ss += kbuf[j] * kbuf[j];
        float inv = 1.f / fmaxf(sqrtf(ss), 1e-12f);
        kkn[(size_t)r * RDIM + c] = kbuf[c] * inv;
    }
}

// ---------------------------------------------------------------------------
// Window attention bias expansion
// ---------------------------------------------------------------------------
__global__ void wbias_kernel(const int* __restrict__ rpi, const float* __restrict__ rpb) {
    int e = blockIdx.x * blockDim.x + threadIdx.x;
    if (e < WINN * WINN) {
        int idx = rpi[e];
        #pragma unroll
        for (int h = 0; h < HEADS; h++) g_wbias[h * WINN * WINN + e] = rpb[idx * HEADS + h];
    }
}

// ---------------------------------------------------------------------------
// LayerNorm -> bf16 out (+ optional fused 10-dim q projection, fp32)
// ---------------------------------------------------------------------------
__global__ void ln_kernel(const float* __restrict__ x, const float* __restrict__ g,
                          const float* __restrict__ b, unsigned short* __restrict__ out,
                          const float* __restrict__ wq, const float* __restrict__ bq,
                          float* __restrict__ qout) {
    __shared__ float ws[1920];
    __shared__ float bqs[16];
    int tid = threadIdx.x;
    if (wq) {
        for (int i = tid; i < 1920; i += 256) ws[i] = (i < DIMC * RDIM) ? wq[i] : 0.f;
        if (tid < RDIM) bqs[tid] = bq[tid];
        __syncthreads();
    }
    int row = (blockIdx.x * blockDim.x + tid) >> 5;
    if (row >= ROWS) return;
    int lane = tid & 31;
    const float* xr = x + (size_t)row * DIMC;
    float v[6], s = 0.f, s2 = 0.f;
    #pragma unroll
    for (int k = 0; k < 6; k++) {
        int c = lane + k * 32;
        v[k] = (c < DIMC) ? xr[c] : 0.f;
        s += v[k]; s2 += v[k] * v[k];
    }
    s = warp_sum(s); s2 = warp_sum(s2);
    float mu = s * (1.f / DIMC);
    float var = s2 * (1.f / DIMC) - mu * mu;
    float rstd = rsqrtf(var + 1e-5f);
    float nv[6];
    unsigned short* orow = out + (size_t)row * DIMC;
    #pragma unroll
    for (int k = 0; k < 6; k++) {
        int c = lane + k * 32;
        nv[k] = (c < DIMC) ? ((v[k] - mu) * rstd * g[c] + b[c]) : 0.f;
        if (c < DIMC) orow[c] = f2bf(nv[k]);
    }
    if (wq) {
        float myq = 0.f;
        #pragma unroll
        for (int o = 0; o < RDIM; o++) {
            float p = 0.f;
            #pragma unroll
            for (int k = 0; k < 6; k++) p += nv[k] * ws[(lane + 32 * k) * RDIM + o];
            p = warp_sum(p);
            if (lane == o) myq = p + bqs[o];
        }
        if (lane < RDIM) qout[(size_t)row * RDIM + lane] = myq;
    }
}

// ---------------------------------------------------------------------------
// bf16 tensor-core GEMM (m16n8k16) with ldmatrix fragment loads.
// 2-buffer cp.async (8-byte chunks; K=180 rows are only 8B aligned), one
// sync per ktile. Smem rows padded to 40 bf16 (80 B) -> ldmatrix is
// conflict-free (8 rows hit the 8 disjoint 4-bank groups).
// ---------------------------------------------------------------------------
struct GPass { const unsigned short* A; const unsigned short* W; int K; int kt; };

__global__ __launch_bounds__(256) void gemm_bf(
        const unsigned short* __restrict__ A1, const unsigned short* __restrict__ W1, int K1,
        const unsigned short* __restrict__ A2, const unsigned short* __restrict__ W2, int K2,
        const unsigned short* __restrict__ A3, const unsigned short* __restrict__ W3base,
        long w3_stride, int K3,
        const float* __restrict__ b1, const float* __restrict__ b2,
        const float* __restrict__ add1,
        float* __restrict__ C, int M, int N, int ldc, int act) {
    __shared__ unsigned short As[2][128][40];
    __shared__ unsigned short Ws[2][64][40];
    int tid  = threadIdx.x;
    int lane = tid & 31;
    int warp = tid >> 5;
    int warpM = warp & 3;
    int warpN = warp >> 2;
    int gId = lane >> 2;
    int tig = lane & 3;
    int row0 = blockIdx.y * 128;
    int col0 = blockIdx.x * 64;

    GPass ps[3];
    int np = 0;
    if (A1 && K1 > 0) ps[np++] = {A1, W1, K1, (K1 + 31) >> 5};
    if (A2 && K2 > 0) ps[np++] = {A2, W2, K2, (K2 + 31) >> 5};
    if (A3 && K3 > 0) ps[np++] = {A3, W3base + (size_t)(row0 >> 12) * w3_stride, K3, (K3 + 31) >> 5};
    int total = 0;
    for (int p = 0; p < np; p++) total += ps[p].kt;

    auto copy_tile = [&](int gi, int buf) {
        int p = 0, loc = gi;
        while (loc >= ps[p].kt) { loc -= ps[p].kt; p++; }
        const unsigned short* A = ps[p].A;
        const unsigned short* W = ps[p].W;
        int K = ps[p].K;
        int k0 = loc << 5;
        #pragma unroll
        for (int f = 0; f < 4; f++) {
            int c = tid + f * 256;
            int m = c >> 3, kc = (c & 7) << 2;
            int gk = k0 + kc;
            int rem = K - gk;
            int bytes = (rem <= 0) ? 0 : ((rem >= 4) ? 8 : rem * 2);
            const unsigned short* src = bytes ? (A + (size_t)(row0 + m) * K + gk) : A;
            unsigned dst = smem_u32(&As[buf][m][kc]);
            asm volatile("cp.async.ca.shared.global [%0], [%1], 8, %2;"
                         :: "r"(dst), "l"(src), "r"(bytes));
        }
        #pragma unroll
        for (int f = 0; f < 2; f++) {
            int c = tid + f * 256;
            int n = c >> 3, kc = (c & 7) << 2;
            int gn = col0 + n, gk = k0 + kc;
            int bytes = 0;
            if (gn < N) {
                int rem = K - gk;
                bytes = (rem <= 0) ? 0 : ((rem >= 4) ? 8 : rem * 2);
            }
            const unsigned short* src = bytes ? (W + (size_t)gn * K + gk) : W;
            unsigned dst = smem_u32(&Ws[buf][n][kc]);
            asm volatile("cp.async.ca.shared.global [%0], [%1], 8, %2;"
                         :: "r"(dst), "l"(src), "r"(bytes));
        }
    };

    float d[2][4][4];
    #pragma unroll
    for (int mt = 0; mt < 2; mt++)
        #pragma unroll
        for (int nt = 0; nt < 4; nt++)
            #pragma unroll
            for (int i = 0; i < 4; i++) d[mt][nt][i] = 0.f;

    copy_tile(0, 0);
    asm volatile("cp.async.commit_group;");
    for (int i = 0; i < total; i++) {
        asm volatile("cp.async.wait_group 0;");
        __syncthreads();
        if (i + 1 < total) {
            copy_tile(i + 1, (i + 1) & 1);
            asm volatile("cp.async.commit_group;");
        }
        int buf = i & 1;
        #pragma unroll
        for (int ks = 0; ks < 2; ks++) {
            int kb = ks * 16;
            unsigned a[2][4], bfr[4][2];
            // A fragments: ldmatrix x4 per 16x16 tile
            int arow = lane & 15;
            int acol = kb + ((lane >> 4) << 3);
            #pragma unroll
            for (int mt = 0; mt < 2; mt++) {
                int m0 = warpM * 32 + mt * 16;
                unsigned ad = smem_u32(&As[buf][m0 + arow][acol]);
                ldsm4(a[mt][0], a[mt][1], a[mt][2], a[mt][3], ad);
            }
            // W fragments: ldmatrix x4 covers two 8-wide n tiles x both k halves
            int wrow = ((lane >> 4) << 3) + (lane & 7);
            int wcol = kb + (((lane >> 3) & 1) << 3);
            #pragma unroll
            for (int np2 = 0; np2 < 2; np2++) {
                int n0 = warpN * 32 + np2 * 16;
                unsigned ad = smem_u32(&Ws[buf][n0 + wrow][wcol]);
                unsigned r0, r1, r2, r3;
                ldsm4(r0, r1, r2, r3, ad);
                bfr[2*np2][0] = r0;  bfr[2*np2][1] = r1;
                bfr[2*np2+1][0] = r2; bfr[2*np2+1][1] = r3;
            }
            #pragma unroll
            for (int mt = 0; mt < 2; mt++)
                #pragma unroll
                for (int nt = 0; nt < 4; nt++) {
                    asm volatile(
                        "mma.sync.aligned.m16n8k16.row.col.f32.bf16.bf16.f32 "
                        "{%0,%1,%2,%3},{%4,%5,%6,%7},{%8,%9},{%0,%1,%2,%3};"
                        : "+f"(d[mt][nt][0]), "+f"(d[mt][nt][1]),
                          "+f"(d[mt][nt][2]), "+f"(d[mt][nt][3])
                        : "r"(a[mt][0]), "r"(a[mt][1]), "r"(a[mt][2]), "r"(a[mt][3]),
                          "r"(bfr[nt][0]), "r"(bfr[nt][1]));
                }
        }
    }

    #pragma unroll
    for (int mt = 0; mt < 2; mt++) {
        #pragma unroll
        for (int nt = 0; nt < 4; nt++) {
            #pragma unroll
            for (int i = 0; i < 4; i++) {
                int r = row0 + warpM * 32 + mt * 16 + gId + (i >> 1) * 8;
                int c = col0 + warpN * 32 + nt * 8 + tig * 2 + (i & 1);
                if (c < N) {
                    float v = d[mt][nt][i];
                    if (b1)   v += b1[c];
                    if (b2)   v += b2[c];
                    if (add1) v += add1[(size_t)r * N + c];
                    if (act)  v = gelu_exact(v);
                    C[(size_t)r * ldc + c] = v;
                }
            }
        }
    }
}

// ---------------------------------------------------------------------------
// ATD: softmax probs P (bf16) + argmax tkid. One warp per token. fp32 math.
// ---------------------------------------------------------------------------
__global__ void atd_kernel(const float* __restrict__ qatd, const float* __restrict__ kkn,
                           const float* __restrict__ scale,
                           unsigned short* __restrict__ P, int* __restrict__ tkid) {
    int t = (blockIdx.x * blockDim.x + threadIdx.x) >> 5;
    int lane = threadIdx.x & 31;
    if (t >= ROWS) return;
    int b = t >> 12;
    float q = (lane < RDIM) ? qatd[(size_t)t * RDIM + lane] : 0.f;
    float ss = warp_sum(q * q);
    float qn = q * (1.f / fmaxf(sqrtf(ss), 1e-12f));
    const float* kb = kkn + (size_t)b * MTOK * RDIM;
    float s0 = 0.f, s1 = 0.f;
    #pragma unroll
    for (int d = 0; d < RDIM; d++) {
        float qd = __shfl_sync(0xffffffffu, qn, d);
        s0 += qd * kb[lane * RDIM + d];
        s1 += qd * kb[(lane + 32) * RDIM + d];
    }
    float sc = fminf(fmaxf(scale[0], 0.f), 3.f);
    float ls = 1.f + sc * 4.15888308335967186f;  // log(64)
    s0 *= ls; s1 *= ls;
    float mv = fmaxf(s0, s1);
    int mi = (s0 >= s1) ? lane : lane + 32;
    #pragma unroll
    for (int o = 16; o; o >>= 1) {
        float ov = __shfl_xor_sync(0xffffffffu, mv, o);
        int   oi = __shfl_xor_sync(0xffffffffu, mi, o);
        if (ov > mv || (ov == mv && oi < mi)) { mv = ov; mi = oi; }
    }
    float p0 = __expf(s0 - mv), p1 = __expf(s1 - mv);
    float sum = warp_sum(p0 + p1);
    float inv = 1.f / sum;
    P[(size_t)t * MTOK + lane]      = f2bf(p0 * inv);
    P[(size_t)t * MTOK + lane + 32] = f2bf(p1 * inv);
    if (lane == 0) tkid[t] = mi;
}

// ---------------------------------------------------------------------------
// Single-pass stable counting sort scatter: block = (batch, bin).
// ---------------------------------------------------------------------------
__global__ void sortscatter_kernel(const int* __restrict__ tkid, int* __restrict__ sidx) {
    int b = blockIdx.x >> 6, bin = blockIdx.x & 63;
    const int* tk = tkid + b * NTOK;
    __shared__ int sc[256];
    int t = threadIdx.x;
    int start = t * 16;
    int eq = 0, less = 0;
    int vals[16];
    #pragma unroll
    for (int k = 0; k < 16; k++) {
        vals[k] = tk[start + k];
        eq += (vals[k] == bin);
        less += (vals[k] < bin);
    }
    sc[t] = (less << 16) | eq;
    __syncthreads();
    #pragma unroll
    for (int d = 1; d < 256; d <<= 1) {
        int v = (t >= d) ? sc[t - d] : 0;
        __syncthreads();
        sc[t] += v;
        __syncthreads();
    }
    int base = sc[255] >> 16;
    int pos = base + (sc[t] & 0xffff) - eq;
    #pragma unroll
    for (int k = 0; k < 16; k++)
        if (vals[k] == bin) sidx[b * NTOK + pos++] = start + k;
}

// ---------------------------------------------------------------------------
// AC_MSA grouped attention: 64 threads, 2 queries/thread, bf16 output.
// ---------------------------------------------------------------------------
__global__ __launch_bounds__(64) void acmsa_kernel(
        const float* __restrict__ qkv, const int* __restrict__ sidx,
        unsigned short* __restrict__ yout) {
    int bi = blockIdx.x;
    int hh = bi % HEADS;
    int g  = (bi / HEADS) % NG;
    int b  = bi / (HEADS * NG);
    int t = threadIdx.x;               // 0..63
    int lane = t & 31;
    int warp = t >> 5;                 // 0..1
    __shared__ __align__(16) float Ks[GS][32], Vs[GS][32];
    const int* sb = sidx + b * NTOK + g * GS;
    #pragma unroll 4
    for (int u = 0; u < 64; u++) {
        int rr = warp * 64 + u;
        int r_u = sb[rr];
        size_t rb = ((size_t)(b * NTOK + r_u)) * QKVW + hh * HD;
        float kv = 0.f, vv_ = 0.f;
        if (lane < HD) {
            kv  = qkv[rb + 180 + lane];
            vv_ = qkv[rb + 360 + lane];
        }
        Ks[rr][lane] = kv;
        Vs[rr][lane] = vv_;
    }
    const float scale = 0.18257418583505536f;   // 30^-0.5
    int rna = sb[t], rnb = sb[t + 64];
    const float2* qpa = (const float2*)(qkv + ((size_t)(b * NTOK + rna)) * QKVW + hh * HD);
    const float2* qpb = (const float2*)(qkv + ((size_t)(b * NTOK + rnb)) * QKVW + hh * HD);
    unsigned long long q2a[15], q2b[15];
    #pragma unroll
    for (int i = 0; i < 15; i++) {
        float2 va = qpa[i], vb = qpb[i];
        q2a[i] = pack2(va.x * scale, va.y * scale);
        q2b[i] = pack2(vb.x * scale, vb.y * scale);
    }
    __syncthreads();
    float ma = -1e30f, la = 0.f, mb = -1e30f, lb = 0.f;
    unsigned long long acc2a[15], acc2b[15];
    #pragma unroll
    for (int i = 0; i < 15; i++) { acc2a[i] = pack2(0.f, 0.f); acc2b[i] = pack2(0.f, 0.f); }
    for (int jc = 0; jc < GS; jc += 8) {
        float sa[8], sb_[8];
        #pragma unroll
        for (int u = 0; u < 8; u++) {
            const unsigned long long* k2 = (const unsigned long long*)Ks[jc + u];
            unsigned long long s2a = pack2(0.f, 0.f), s2b = pack2(0.f, 0.f);
            #pragma unroll
            for (int i = 0; i < 15; i++) {
                unsigned long long kk = k2[i];
                fma2(s2a, q2a[i], kk);
                fma2(s2b, q2b[i], kk);
            }
            float lo, hi;
            unpack2(s2a, lo, hi); sa[u]  = lo + hi;
            unpack2(s2b, lo, hi); sb_[u] = lo + hi;
        }
        float cma = sa[0], cmb = sb_[0];
        #pragma unroll
        for (int u = 1; u < 8; u++) { cma = fmaxf(cma, sa[u]); cmb = fmaxf(cmb, sb_[u]); }
        float mna = fmaxf(ma, cma), mnb = fmaxf(mb, cmb);
        float coa = __expf(ma - mna), cob = __expf(mb - mnb);
        ma = mna; mb = mnb;
        la *= coa; lb *= cob;
        unsigned long long coa2 = pack2(coa, coa), cob2 = pack2(cob, cob);
        #pragma unroll
        for (int i = 0; i < 15; i++) { acc2a[i] = mul2(acc2a[i], coa2); acc2b[i] = mul2(acc2b[i], cob2); }
        #pragma unroll
        for (int u = 0; u < 8; u++) {
            float pa = __expf(sa[u] - mna), pb = __expf(sb_[u] - mnb);
            la += pa; lb += pb;
            unsigned long long pa2 = pack2(pa, pa), pb2 = pack2(pb, pb);
            const unsigned long long* v2 = (const unsigned long long*)Vs[jc + u];
            #pragma unroll
            for (int i = 0; i < 15; i++) {
                unsigned long long vv_ = v2[i];
                fma2(acc2a[i], pa2, vv_);
                fma2(acc2b[i], pb2, vv_);
            }
        }
    }
    float inva = 1.f / la, invb = 1.f / lb;
    unsigned* ora = (unsigned*)(yout + ((size_t)(b * NTOK + rna)) * DIMC + hh * HD);
    unsigned* orb = (unsigned*)(yout + ((size_t)(b * NTOK + rnb)) * DIMC + hh * HD);
    #pragma unroll
    for (int i = 0; i < 15; i++) {
        float lo, hi;
        unpack2(acc2a[i], lo, hi); ora[i] = bf2pack(lo * inva, hi * inva);
        unpack2(acc2b[i], lo, hi); orb[i] = bf2pack(lo * invb, hi * invb);
    }
}

// ---------------------------------------------------------------------------
// Window attention: 128 threads, 2 queries/thread, bf16 output.
// ---------------------------------------------------------------------------
__global__ __launch_bounds__(128) void winattn_kernel(const float* __restrict__ qkv,
                                                      unsigned short* __restrict__ yout) {
    extern __shared__ float sm[];
    float* Ks = sm;
    float* Vs = sm + WINN * 32;
    int bi = blockIdx.x;
    int hh = bi % HEADS;
    int wdx = bi / HEADS;
    int b = wdx >> 4;
    int wy = (wdx >> 2) & 3;
    int wx = wdx & 3;
    int t = threadIdx.x;               // 0..127
    int lane = t & 31;
    int warp = t >> 5;                 // 0..3
    #pragma unroll 4
    for (int u = 0; u < 64; u++) {
        int rr = warp * 64 + u;
        int ny = (wy * WS + (rr >> 4)) * WW + wx * WS + (rr & 15);
        size_t rb = ((size_t)(b * NTOK + ny)) * QKVW + hh * HD;
        float kv = 0.f, vv_ = 0.f;
        if (lane < HD) {
            kv  = qkv[rb + 180 + lane];
            vv_ = qkv[rb + 360 + lane];
        }
        Ks[rr * 32 + lane] = kv;
        Vs[rr * 32 + lane] = vv_;
    }
    const float scale = 0.18257418583505536f;
    int qa_i = t, qb_i = t + 128;
    int na = (wy * WS + (qa_i >> 4)) * WW + wx * WS + (qa_i & 15);
    int nb = (wy * WS + (qb_i >> 4)) * WW + wx * WS + (qb_i & 15);
    const float2* qpa = (const float2*)(qkv + ((size_t)(b * NTOK + na)) * QKVW + hh * HD);
    const float2* qpb = (const float2*)(qkv + ((size_t)(b * NTOK + nb)) * QKVW + hh * HD);
    unsigned long long q2a[15], q2b[15];
    #pragma unroll
    for (int i = 0; i < 15; i++) {
        float2 va = qpa[i], vb = qpb[i];
        q2a[i] = pack2(va.x * scale, va.y * scale);
        q2b[i] = pack2(vb.x * scale, vb.y * scale);
    }
    __syncthreads();
    const float* browa = g_wbias + ((size_t)hh * WINN + qa_i) * WINN;
    const float* browb = g_wbias + ((size_t)hh * WINN + qb_i) * WINN;
    float ma = -1e30f, la = 0.f, mb = -1e30f, lb = 0.f;
    unsigned long long acc2a[15], acc2b[15];
    #pragma unroll
    for (int i = 0; i < 15; i++) { acc2a[i] = pack2(0.f, 0.f); acc2b[i] = pack2(0.f, 0.f); }
    for (int jc = 0; jc < WINN; jc += 8) {
        float sa[8], sb_[8];
        #pragma unroll
        for (int u = 0; u < 8; u++) {
            const unsigned long long* k2 = (const unsigned long long*)(Ks + (jc + u) * 32);
            unsigned long long s2a = pack2(0.f, 0.f), s2b = pack2(0.f, 0.f);
            #pragma unroll
            for (int i = 0; i < 15; i++) {
                unsigned long long kk = k2[i];
                fma2(s2a, q2a[i], kk);
                fma2(s2b, q2b[i], kk);
            }
            float lo, hi;
            unpack2(s2a, lo, hi); sa[u]  = lo + hi + browa[jc + u];
            unpack2(s2b, lo, hi); sb_[u] = lo + hi + browb[jc + u];
        }
        float cma = sa[0], cmb = sb_[0];
        #pragma unroll
        for (int u = 1; u < 8; u++) { cma = fmaxf(cma, sa[u]); cmb = fmaxf(cmb, sb_[u]); }
        float mna = fmaxf(ma, cma), mnb = fmaxf(mb, cmb);
        float coa = __expf(ma - mna), cob = __expf(mb - mnb);
        ma = mna; mb = mnb;
        la *= coa; lb *= cob;
        unsigned long long coa2 = pack2(coa, coa), cob2 = pack2(cob, cob);
        #pragma unroll
        for (int i = 0; i < 15; i++) { acc2a[i] = mul2(acc2a[i], coa2); acc2b[i] = mul2(acc2b[i], cob2); }
        #pragma unroll
        for (int u = 0; u < 8; u++) {
            float pa = __expf(sa[u] - mna), pb = __expf(sb_[u] - mnb);
            la += pa; lb += pb;
            unsigned long long pa2 = pack2(pa, pa), pb2 = pack2(pb, pb);
            const unsigned long long* v2 = (const unsigned long long*)(Vs + (jc + u) * 32);
            #pragma unroll
            for (int i = 0; i < 15; i++) {
                unsigned long long vv_ = v2[i];
                fma2(acc2a[i], pa2, vv_);
                fma2(acc2b[i], pb2, vv_);
            }
        }
    }
    float inva = 1.f / la, invb = 1.f / lb;
    unsigned* ora = (unsigned*)(yout + ((size_t)(b * NTOK + na)) * DIMC + hh * HD);
    unsigned* orb = (unsigned*)(yout + ((size_t)(b * NTOK + nb)) * DIMC + hh * HD);
    #pragma unroll
    for (int i = 0; i < 15; i++) {
        float lo, hi;
        unpack2(acc2a[i], lo, hi); ora[i] = bf2pack(lo * inva, hi * inva);
        unpack2(acc2b[i], lo, hi); orb[i] = bf2pack(lo * invb, hi * invb);
    }
}

// ---------------------------------------------------------------------------
// Gather per-token dictionary features into hc[:, 360:424] (fp32)
// ---------------------------------------------------------------------------
__global__ void gathertd_kernel(const float* __restrict__ tdproj, const int* __restrict__ tkid,
                                float* __restrict__ hc) {
    int e = blockIdx.x * blockDim.x + threadIdx.x;
    if (e < ROWS * DTD) {
        int r = e >> 6, j = e & 63;
        int b = r >> 12;
        hc[(size_t)r * CFF + MLP_HID + j] = tdproj[((size_t)b * MTOK + tkid[r]) * DTD + j];
    }
}

// ---------------------------------------------------------------------------
// Depthwise 5x5 conv + GELU + residual; bf16 output hc2.
// ---------------------------------------------------------------------------
#define DWCH 8
__global__ void dwconv_kernel(const float* __restrict__ hc, const float* __restrict__ w,
                              const float* __restrict__ bias, unsigned short* __restrict__ hc2) {
    __shared__ float smd[20 * 20 * DWCH];
    __shared__ float wsm[25][DWCH];
    __shared__ float bsm[DWCH];
    int tid = threadIdx.x;
    int c0 = blockIdx.y * DWCH;
    int b  = blockIdx.z;
    int tileY = (blockIdx.x >> 2) * 16, tileX = (blockIdx.x & 3) * 16;
    if (tid < 200) { int t5 = tid % 25, j = tid / 25; wsm[t5][j] = w[(c0 + j) * 25 + t5]; }
    if (tid < DWCH) bsm[tid] = bias[c0 + tid];
    for (int i = tid; i < 800; i += 256) {
        int cell = i >> 1, half = i & 1;
        int cy = cell / 20, cx = cell % 20;
        int gy = tileY + cy - 2, gx = tileX + cx - 2;
        float4 v = {0.f, 0.f, 0.f, 0.f};
        if (gy >= 0 && gy < 64 && gx >= 0 && gx < 64)
            v = *(const float4*)&hc[(((size_t)b << 12) + (gy << 6) + gx) * CFF + c0 + half * 4];
        *(float4*)&smd[cell * 8 + half * 4] = v;
    }
    __syncthreads();
    int ty = tid >> 4, tx = tid & 15;
    float acc[DWCH];
    #pragma unroll
    for (int j = 0; j < DWCH; j++) acc[j] = 0.f;
    #pragma unroll
    for (int ky = 0; ky < 5; ky++) {
        #pragma unroll
        for (int kx = 0; kx < 5; kx++) {
            const float* cp = &smd[((ty + ky) * 20 + tx + kx) * 8];
            float4 a0 = *(const float4*)cp;
            float4 a1 = *(const float4*)(cp + 4);
            int t5 = ky * 5 + kx;
            acc[0] += a0.x * wsm[t5][0];
            acc[1] += a0.y * wsm[t5][1];
            acc[2] += a0.z * wsm[t5][2];
            acc[3] += a0.w * wsm[t5][3];
            acc[4] += a1.x * wsm[t5][4];
            acc[5] += a1.y * wsm[t5][5];
            acc[6] += a1.z * wsm[t5][6];
            acc[7] += a1.w * wsm[t5][7];
        }
    }
    const float* ctr = &smd[((ty + 2) * 20 + tx + 2) * 8];
    size_t idx = (((size_t)b << 12) + ((size_t)(tileY + ty) << 6) + (tileX + tx)) * CFF + c0;
    float o[8];
    #pragma unroll
    for (int j = 0; j < 8; j++) o[j] = ctr[j] + gelu_exact(acc[j] + bsm[j]);
    uint4 pk;
    pk.x = bf2pack(o[0], o[1]);
    pk.y = bf2pack(o[2], o[3]);
    pk.z = bf2pack(o[4], o[5]);
    pk.w = bf2pack(o[6], o[7]);
    *(uint4*)&hc2[idx] = pk;
}

// ---------------------------------------------------------------------------
// Launch (launch #6 = bf16 qkv GEMM for ncu -s 5 -c 1)
// ---------------------------------------------------------------------------
extern "C" void kernel_launch(void* const* d_in, const int* in_sizes, int n_in,
                              void* d_out, int out_size) {
    const float* x        = (const float*)d_in[0];
    const float* td       = (const float*)d_in[1];
    const float* n1g      = (const float*)d_in[2];
    const float* n1b      = (const float*)d_in[3];
    const float* wqkv_w   = (const float*)d_in[4];
    const float* wqkv_b   = (const float*)d_in[5];
    const float* atd_wq_w = (const float*)d_in[6];
    const float* atd_wq_b = (const float*)d_in[7];
    const float* atd_wk_w = (const float*)d_in[8];
    const float* atd_wk_b = (const float*)d_in[9];
    const float* atd_wv_w = (const float*)d_in[10];
    const float* atd_wv_b = (const float*)d_in[11];
    const float* atd_sc   = (const float*)d_in[12];
    const float* aca_w    = (const float*)d_in[13];
    const float* aca_b    = (const float*)d_in[14];
    const float* win_rpb  = (const float*)d_in[15];
    const float* win_w    = (const float*)d_in[16];
    const float* win_b    = (const float*)d_in[17];
    const float* fctd_w   = (const float*)d_in[18];
    const float* fctd_b   = (const float*)d_in[19];
    const float* fc1_w    = (const float*)d_in[20];
    const float* fc1_b    = (const float*)d_in[21];
    const float* dw_w     = (const float*)d_in[22];
    const float* dw_b     = (const float*)d_in[23];
    const float* fc2_w    = (const float*)d_in[24];
    const float* fc2_b    = (const float*)d_in[25];
    const float* n2g      = (const float*)d_in[26];
    const float* n2b      = (const float*)d_in[27];
    const int*   rpi      = (const int*)d_in[28];
    float* out = (float*)d_out;

    float *qkv, *qatd, *kkn, *tdpr, *xsum, *hc;
    unsigned short *xn, *x2n, *yaca, *ywin, *patd, *hc2, *vvt, *wt;
    int *tkid, *sidx;
    cudaGetSymbolAddress((void**)&xn,   g_xn);
    cudaGetSymbolAddress((void**)&qkv,  g_qkv);
    cudaGetSymbolAddress((void**)&qatd, g_qatd);
    cudaGetSymbolAddress((void**)&kkn,  g_kkn);
    cudaGetSymbolAddress((void**)&vvt,  g_vvt);
    cudaGetSymbolAddress((void**)&tdpr, g_tdpr);
    cudaGetSymbolAddress((void**)&patd, g_patd);
    cudaGetSymbolAddress((void**)&yaca, g_yaca);
    cudaGetSymbolAddress((void**)&ywin, g_ywin);
    cudaGetSymbolAddress((void**)&xsum, g_xsum);
    cudaGetSymbolAddress((void**)&x2n,  g_x2n);
    cudaGetSymbolAddress((void**)&hc,   g_hc);
    cudaGetSymbolAddress((void**)&hc2,  g_hc2);
    cudaGetSymbolAddress((void**)&tkid, g_tkid);
    cudaGetSymbolAddress((void**)&sidx, g_sidx);
    cudaGetSymbolAddress((void**)&wt,   g_wt);

    cudaFuncSetAttribute(winattn_kernel, cudaFuncAttributeMaxDynamicSharedMemorySize, 65536);

    // 1. dictionary projections
    dict_kernel<<<BATCH*MTOK, 256>>>(td, atd_wk_w, atd_wk_b, atd_wv_w, atd_wv_b,
                                     fctd_w, fctd_b, kkn, vvt, tdpr);
    // 2. window bias expansion
    wbias_kernel<<<WINN*WINN/256, 256>>>(rpi, win_rpb);
    // 3. LN1 (+ fused q_atd projection), bf16 out
    ln_kernel<<<ROWS/8, 256>>>(x, n1g, n1b, xn, atd_wq_w, atd_wq_b, qatd);
    // 4. all weight transposes/conversions in one kernel
    convw_all<<<(S_TOT + 255)/256, 256>>>(wqkv_w, aca_w, win_w, fc1_w, fc2_w, wt);
    // 5. ATD probs + tk_id
    atd_kernel<<<ROWS/8, 256>>>(qatd, kkn, atd_sc, patd, tkid);
    // 6. qkv = xn @ wqkv + b  (bf16 TC + ldmatrix)  <- ncu capture
    gemm_bf<<<dim3(9, ROWS/128), 256>>>(xn, wt + WT_QKV, DIMC, nullptr, nullptr, 0,
                                        nullptr, nullptr, 0, 0,
                                        wqkv_b, nullptr, nullptr,
                                        qkv, ROWS, QKVW, QKVW, 0);
    // 7. window attention
    winattn_kernel<<<NWIN*HEADS, 128, 65536>>>(qkv, ywin);
    // 8. single-pass stable sort scatter
    sortscatter_kernel<<<BATCH*MTOK, 256>>>(tkid, sidx);
    // 9. grouped attention
    acmsa_kernel<<<BATCH*NG*HEADS, 64>>>(qkv, sidx, yaca);
    // 10. xsum = x + P@vv (batched) + yaca@aca_w + ywin@win_w + biases
    gemm_bf<<<dim3(3, ROWS/128), 256>>>(yaca, wt + WT_ACA, DIMC, ywin, wt + WT_WIN, DIMC,
                                        patd, vvt, (long)DIMC*MTOK, MTOK,
                                        aca_b, win_b, x,
                                        xsum, ROWS, DIMC, DIMC, 0);
    // 11. LN2 (bf16 out)
    ln_kernel<<<ROWS/8, 256>>>(xsum, n2g, n2b, x2n, nullptr, nullptr, nullptr);
    // 12. fc1 + GELU into hc[:, 0:360] (fp32)
    gemm_bf<<<dim3(6, ROWS/128), 256>>>(x2n, wt + WT_FC1, DIMC, nullptr, nullptr, 0,
                                        nullptr, nullptr, 0, 0,
                                        fc1_b, nullptr, nullptr,
                                        hc, ROWS, MLP_HID, CFF, 1);
    // 13. gather td features into hc[:, 360:424]
    gathertd_kernel<<<ROWS*DTD/256, 256>>>(tdpr, tkid, hc);
    // 14. depthwise conv + gelu + residual -> hc2 (bf16)
    dwconv_kernel<<<dim3(16, CFF/DWCH, BATCH), 256>>>(hc, dw_w, dw_b, hc2);
    // 15. out = xsum + hc2 @ fc2_w + fc2_b
    gemm_bf<<<dim3(3, ROWS/128), 256>>>(hc2, wt + WT_FC2, CFF, nullptr, nullptr, 0,
                                        nullptr, nullptr, 0, 0,
                                        fc2_b, nullptr, xsum,
                                        out, ROWS, DIMC, DIMC, 0);
}

// round 12
// speedup vs baseline: 1.4177x; 1.1064x over previous
#include <cuda_runtime.h>
#include <cuda_bf16.h>
#include <math.h>

// ---------------------------------------------------------------------------
// Problem constants
// ---------------------------------------------------------------------------
#define BATCH 8
#define NTOK 4096
#define ROWS (BATCH*NTOK)
#define DIMC 180
#define HEADS 6
#define HD 30
#define QKVW 540
#define MTOK 64
#define RDIM 10
#define GS 128
#define NG 32
#define WS 16
#define WINN 256
#define NWIN 128
#define MLP_HID 360
#define DTD 64
#define CFF 424
#define HH 64
#define WW 64

// bf16 weight scratch offsets (elements)
#define WT_QKV 0
#define WT_ACA (WT_QKV + DIMC*QKVW)
#define WT_WIN (WT_ACA + DIMC*DIMC)
#define WT_FC1 (WT_WIN + DIMC*DIMC)
#define WT_FC2 (WT_FC1 + DIMC*MLP_HID)
#define WT_TOTAL (WT_FC2 + CFF*DIMC)

// ---------------------------------------------------------------------------
// Scratch
// ---------------------------------------------------------------------------
__device__ unsigned short g_xn  [ROWS*DIMC];        // bf16
__device__ float g_qkv  [ROWS*QKVW];
__device__ float g_qatd [ROWS*RDIM];
__device__ float g_kkn  [BATCH*MTOK*RDIM];
__device__ unsigned short g_vvt [BATCH*DIMC*MTOK];  // bf16, transposed [b][n][m]
__device__ float g_tdpr [BATCH*MTOK*DTD];
__device__ unsigned short g_patd[ROWS*MTOK];        // bf16
__device__ int   g_tkid [ROWS];
__device__ int   g_sidx [ROWS];
__device__ unsigned short g_yaca[ROWS*DIMC];        // bf16
__device__ unsigned short g_ywin[ROWS*DIMC];        // bf16
__device__ float g_xsum [ROWS*DIMC];
__device__ unsigned short g_x2n [ROWS*DIMC];        // bf16
__device__ float g_hc   [ROWS*CFF];
__device__ unsigned short g_hc2 [ROWS*CFF];         // bf16
__device__ float g_wbias[HEADS*WINN*WINN];
__device__ unsigned short g_wt  [WT_TOTAL];         // bf16 transposed weights

// ---------------------------------------------------------------------------
// Helpers
// ---------------------------------------------------------------------------
__device__ __forceinline__ float warp_sum(float v) {
    #pragma unroll
    for (int o = 16; o; o >>= 1) v += __shfl_xor_sync(0xffffffffu, v, o);
    return v;
}
__device__ __forceinline__ float gelu_exact(float v) {
    return 0.5f * v * (1.0f + erff(v * 0.70710678118654752440f));
}
__device__ __forceinline__ unsigned long long pack2(float lo, float hi) {
    unsigned long long r;
    asm("mov.b64 %0,{%1,%2};" : "=l"(r) : "f"(lo), "f"(hi));
    return r;
}
__device__ __forceinline__ void unpack2(unsigned long long v, float& lo, float& hi) {
    asm("mov.b64 {%0,%1},%2;" : "=f"(lo), "=f"(hi) : "l"(v));
}
__device__ __forceinline__ void fma2(unsigned long long& d, unsigned long long a,
                                     unsigned long long b) {
    asm("fma.rn.f32x2 %0,%1,%2,%0;" : "+l"(d) : "l"(a), "l"(b));
}
__device__ __forceinline__ unsigned long long mul2(unsigned long long a, unsigned long long b) {
    unsigned long long r;
    asm("mul.rn.f32x2 %0,%1,%2;" : "=l"(r) : "l"(a), "l"(b));
    return r;
}
__device__ __forceinline__ unsigned smem_u32(const void* p) {
    return (unsigned)__cvta_generic_to_shared(p);
}
__device__ __forceinline__ unsigned short f2bf(float v) {
    __nv_bfloat16 h = __float2bfloat16_rn(v);
    return *(unsigned short*)&h;
}
__device__ __forceinline__ unsigned bf2pack(float lo, float hi) {
    __nv_bfloat162 h = __floats2bfloat162_rn(lo, hi);
    return *(unsigned*)&h;
}
__device__ __forceinline__ void ldsm4(unsigned& r0, unsigned& r1, unsigned& r2, unsigned& r3,
                                      unsigned addr) {
    asm volatile("ldmatrix.sync.aligned.m8n8.x4.shared.b16 {%0,%1,%2,%3}, [%4];"
                 : "=r"(r0), "=r"(r1), "=r"(r2), "=r"(r3) : "r"(addr));
}

// ---------------------------------------------------------------------------
// Merged weight transpose+convert for all five GEMM weights.
// ---------------------------------------------------------------------------
#define S_QKV (DIMC*QKVW)
#define S_ACA (DIMC*DIMC)
#define S_WIN (DIMC*DIMC)
#define S_FC1 (DIMC*MLP_HID)
#define S_FC2 (CFF*DIMC)
#define S_TOT (S_QKV+S_ACA+S_WIN+S_FC1+S_FC2)

__global__ void convw_all(const float* __restrict__ qkv_w, const float* __restrict__ aca_w,
                          const float* __restrict__ win_w, const float* __restrict__ fc1_w,
                          const float* __restrict__ fc2_w, unsigned short* __restrict__ wt) {
    int i = blockIdx.x * blockDim.x + threadIdx.x;
    if (i >= S_TOT) return;
    const float* W; int K, N, loc, base;
    if (i < S_QKV)                       { W = qkv_w; K = DIMC; N = QKVW;   loc = i;                         base = WT_QKV; }
    else if (i < S_QKV+S_ACA)            { W = aca_w; K = DIMC; N = DIMC;   loc = i - S_QKV;                 base = WT_ACA; }
    else if (i < S_QKV+S_ACA+S_WIN)      { W = win_w; K = DIMC; N = DIMC;   loc = i - S_QKV - S_ACA;         base = WT_WIN; }
    else if (i < S_QKV+S_ACA+S_WIN+S_FC1){ W = fc1_w; K = DIMC; N = MLP_HID;loc = i - S_QKV - S_ACA - S_WIN; base = WT_FC1; }
    else                                 { W = fc2_w; K = CFF;  N = DIMC;   loc = i - S_QKV-S_ACA-S_WIN-S_FC1; base = WT_FC2; }
    int n = loc / K, k = loc % K;
    wt[base + loc] = f2bf(W[(size_t)k * N + n]);
}

// ---------------------------------------------------------------------------
// Fused dictionary projections: kkn fp32 l2n, vvt bf16 transposed, tdpr fp32
// ---------------------------------------------------------------------------
__global__ void dict_kernel(const float* __restrict__ td,
                            const float* __restrict__ wk_w, const float* __restrict__ wk_b,
                            const float* __restrict__ wv_w, const float* __restrict__ wv_b,
                            const float* __restrict__ ftd_w, const float* __restrict__ ftd_b,
                            float* __restrict__ kkn, unsigned short* __restrict__ vvt,
                            float* __restrict__ tdpr) {
    int r = blockIdx.x;                 // 0..511
    int b = r >> 6, m = r & 63;
    __shared__ float as[DIMC];
    __shared__ float kbuf[RDIM];
    int tid = threadIdx.x;
    const float* ar = td + (size_t)r * DIMC;
    if (tid < DIMC) as[tid] = ar[tid];
    __syncthreads();
    if (tid < DIMC) {
        float acc = wv_b[tid];
        #pragma unroll 4
        for (int k = 0; k < DIMC; k++) acc += as[k] * wv_w[(size_t)k * DIMC + tid];
        vvt[((size_t)b * DIMC + tid) * MTOK + m] = f2bf(acc);
    } else if (tid < DIMC + DTD) {
        int c = tid - DIMC;
        float acc = ftd_b[c];
        #pragma unroll 4
        for (int k = 0; k < DIMC; k++) acc += as[k] * ftd_w[(size_t)k * DTD + c];
        tdpr[(size_t)r * DTD + c] = acc;
    } else if (tid < DIMC + DTD + RDIM) {
        int c = tid - DIMC - DTD;
        float acc = wk_b[c];
        #pragma unroll 4
        for (int k = 0; k < DIMC; k++) acc += as[k] * wk_w[(size_t)k * RDIM + c];
        kbuf[c] = acc;
    }
    __syncthreads();
    if (tid >= DIMC + DTD && tid < DIMC + DTD + RDIM) {
        int c = tid - DIMC - DTD;
        float ss = 0.f;
        #pragma unroll
        for (int j = 0; j < RDIM; j++) ss += kbuf[j] * kbuf[j];
        float inv = 1.f / fmaxf(sqrtf(ss), 1e-12f);
        kkn[(size_t)r * RDIM + c] = kbuf[c] * inv;
    }
}

// ---------------------------------------------------------------------------
// Window attention bias expansion
// ---------------------------------------------------------------------------
__global__ void wbias_kernel(const int* __restrict__ rpi, const float* __restrict__ rpb) {
    int e = blockIdx.x * blockDim.x + threadIdx.x;
    if (e < WINN * WINN) {
        int idx = rpi[e];
        #pragma unroll
        for (int h = 0; h < HEADS; h++) g_wbias[h * WINN * WINN + e] = rpb[idx * HEADS + h];
    }
}

// ---------------------------------------------------------------------------
// LayerNorm -> bf16 out (+ optional fused 10-dim q projection, fp32)
// ---------------------------------------------------------------------------
__global__ void ln_kernel(const float* __restrict__ x, const float* __restrict__ g,
                          const float* __restrict__ b, unsigned short* __restrict__ out,
                          const float* __restrict__ wq, const float* __restrict__ bq,
                          float* __restrict__ qout) {
    __shared__ float ws[1920];
    __shared__ float bqs[16];
    int tid = threadIdx.x;
    if (wq) {
        for (int i = tid; i < 1920; i += 256) ws[i] = (i < DIMC * RDIM) ? wq[i] : 0.f;
        if (tid < RDIM) bqs[tid] = bq[tid];
        __syncthreads();
    }
    int row = (blockIdx.x * blockDim.x + tid) >> 5;
    if (row >= ROWS) return;
    int lane = tid & 31;
    const float* xr = x + (size_t)row * DIMC;
    float v[6], s = 0.f, s2 = 0.f;
    #pragma unroll
    for (int k = 0; k < 6; k++) {
        int c = lane + k * 32;
        v[k] = (c < DIMC) ? xr[c] : 0.f;
        s += v[k]; s2 += v[k] * v[k];
    }
    s = warp_sum(s); s2 = warp_sum(s2);
    float mu = s * (1.f / DIMC);
    float var = s2 * (1.f / DIMC) - mu * mu;
    float rstd = rsqrtf(var + 1e-5f);
    float nv[6];
    unsigned short* orow = out + (size_t)row * DIMC;
    #pragma unroll
    for (int k = 0; k < 6; k++) {
        int c = lane + k * 32;
        nv[k] = (c < DIMC) ? ((v[k] - mu) * rstd * g[c] + b[c]) : 0.f;
        if (c < DIMC) orow[c] = f2bf(nv[k]);
    }
    if (wq) {
        float myq = 0.f;
        #pragma unroll
        for (int o = 0; o < RDIM; o++) {
            float p = 0.f;
            #pragma unroll
            for (int k = 0; k < 6; k++) p += nv[k] * ws[(lane + 32 * k) * RDIM + o];
            p = warp_sum(p);
            if (lane == o) myq = p + bqs[o];
        }
        if (lane < RDIM) qout[(size_t)row * RDIM + lane] = myq;
    }
}

// ---------------------------------------------------------------------------
// bf16 tensor-core GEMM (m16n8k16) with ldmatrix fragment loads.
// ---------------------------------------------------------------------------
struct GPass { const unsigned short* A; const unsigned short* W; int K; int kt; };

__global__ __launch_bounds__(256) void gemm_bf(
        const unsigned short* __restrict__ A1, const unsigned short* __restrict__ W1, int K1,
        const unsigned short* __restrict__ A2, const unsigned short* __restrict__ W2, int K2,
        const unsigned short* __restrict__ A3, const unsigned short* __restrict__ W3base,
        long w3_stride, int K3,
        const float* __restrict__ b1, const float* __restrict__ b2,
        const float* __restrict__ add1,
        float* __restrict__ C, int M, int N, int ldc, int act) {
    __shared__ unsigned short As[2][128][40];
    __shared__ unsigned short Ws[2][64][40];
    int tid  = threadIdx.x;
    int lane = tid & 31;
    int warp = tid >> 5;
    int warpM = warp & 3;
    int warpN = warp >> 2;
    int gId = lane >> 2;
    int tig = lane & 3;
    int row0 = blockIdx.y * 128;
    int col0 = blockIdx.x * 64;

    GPass ps[3];
    int np = 0;
    if (A1 && K1 > 0) ps[np++] = {A1, W1, K1, (K1 + 31) >> 5};
    if (A2 && K2 > 0) ps[np++] = {A2, W2, K2, (K2 + 31) >> 5};
    if (A3 && K3 > 0) ps[np++] = {A3, W3base + (size_t)(row0 >> 12) * w3_stride, K3, (K3 + 31) >> 5};
    int total = 0;
    for (int p = 0; p < np; p++) total += ps[p].kt;

    auto copy_tile = [&](int gi, int buf) {
        int p = 0, loc = gi;
        while (loc >= ps[p].kt) { loc -= ps[p].kt; p++; }
        const unsigned short* A = ps[p].A;
        const unsigned short* W = ps[p].W;
        int K = ps[p].K;
        int k0 = loc << 5;
        #pragma unroll
        for (int f = 0; f < 4; f++) {
            int c = tid + f * 256;
            int m = c >> 3, kc = (c & 7) << 2;
            int gk = k0 + kc;
            int rem = K - gk;
            int bytes = (rem <= 0) ? 0 : ((rem >= 4) ? 8 : rem * 2);
            const unsigned short* src = bytes ? (A + (size_t)(row0 + m) * K + gk) : A;
            unsigned dst = smem_u32(&As[buf][m][kc]);
            asm volatile("cp.async.ca.shared.global [%0], [%1], 8, %2;"
                         :: "r"(dst), "l"(src), "r"(bytes));
        }
        #pragma unroll
        for (int f = 0; f < 2; f++) {
            int c = tid + f * 256;
            int n = c >> 3, kc = (c & 7) << 2;
            int gn = col0 + n, gk = k0 + kc;
            int bytes = 0;
            if (gn < N) {
                int rem = K - gk;
                bytes = (rem <= 0) ? 0 : ((rem >= 4) ? 8 : rem * 2);
            }
            const unsigned short* src = bytes ? (W + (size_t)gn * K + gk) : W;
            unsigned dst = smem_u32(&Ws[buf][n][kc]);
            asm volatile("cp.async.ca.shared.global [%0], [%1], 8, %2;"
                         :: "r"(dst), "l"(src), "r"(bytes));
        }
    };

    float d[2][4][4];
    #pragma unroll
    for (int mt = 0; mt < 2; mt++)
        #pragma unroll
        for (int nt = 0; nt < 4; nt++)
            #pragma unroll
            for (int i = 0; i < 4; i++) d[mt][nt][i] = 0.f;

    copy_tile(0, 0);
    asm volatile("cp.async.commit_group;");
    for (int i = 0; i < total; i++) {
        asm volatile("cp.async.wait_group 0;");
        __syncthreads();
        if (i + 1 < total) {
            copy_tile(i + 1, (i + 1) & 1);
            asm volatile("cp.async.commit_group;");
        }
        int buf = i & 1;
        #pragma unroll
        for (int ks = 0; ks < 2; ks++) {
            int kb = ks * 16;
            unsigned a[2][4], bfr[4][2];
            int arow = lane & 15;
            int acol = kb + ((lane >> 4) << 3);
            #pragma unroll
            for (int mt = 0; mt < 2; mt++) {
                int m0 = warpM * 32 + mt * 16;
                unsigned ad = smem_u32(&As[buf][m0 + arow][acol]);
                ldsm4(a[mt][0], a[mt][1], a[mt][2], a[mt][3], ad);
            }
            int wrow = ((lane >> 4) << 3) + (lane & 7);
            int wcol = kb + (((lane >> 3) & 1) << 3);
            #pragma unroll
            for (int np2 = 0; np2 < 2; np2++) {
                int n0 = warpN * 32 + np2 * 16;
                unsigned ad = smem_u32(&Ws[buf][n0 + wrow][wcol]);
                unsigned r0, r1, r2, r3;
                ldsm4(r0, r1, r2, r3, ad);
                bfr[2*np2][0] = r0;  bfr[2*np2][1] = r1;
                bfr[2*np2+1][0] = r2; bfr[2*np2+1][1] = r3;
            }
            #pragma unroll
            for (int mt = 0; mt < 2; mt++)
                #pragma unroll
                for (int nt = 0; nt < 4; nt++) {
                    asm volatile(
                        "mma.sync.aligned.m16n8k16.row.col.f32.bf16.bf16.f32 "
                        "{%0,%1,%2,%3},{%4,%5,%6,%7},{%8,%9},{%0,%1,%2,%3};"
                        : "+f"(d[mt][nt][0]), "+f"(d[mt][nt][1]),
                          "+f"(d[mt][nt][2]), "+f"(d[mt][nt][3])
                        : "r"(a[mt][0]), "r"(a[mt][1]), "r"(a[mt][2]), "r"(a[mt][3]),
                          "r"(bfr[nt][0]), "r"(bfr[nt][1]));
                }
        }
    }

    #pragma unroll
    for (int mt = 0; mt < 2; mt++) {
        #pragma unroll
        for (int nt = 0; nt < 4; nt++) {
            #pragma unroll
            for (int i = 0; i < 4; i++) {
                int r = row0 + warpM * 32 + mt * 16 + gId + (i >> 1) * 8;
                int c = col0 + warpN * 32 + nt * 8 + tig * 2 + (i & 1);
                if (c < N) {
                    float v = d[mt][nt][i];
                    if (b1)   v += b1[c];
                    if (b2)   v += b2[c];
                    if (add1) v += add1[(size_t)r * N + c];
                    if (act)  v = gelu_exact(v);
                    C[(size_t)r * ldc + c] = v;
                }
            }
        }
    }
}

// ---------------------------------------------------------------------------
// ATD: softmax probs P (bf16) + argmax tkid. One warp per token. fp32 math.
// ---------------------------------------------------------------------------
__global__ void atd_kernel(const float* __restrict__ qatd, const float* __restrict__ kkn,
                           const float* __restrict__ scale,
                           unsigned short* __restrict__ P, int* __restrict__ tkid) {
    int t = (blockIdx.x * blockDim.x + threadIdx.x) >> 5;
    int lane = threadIdx.x & 31;
    if (t >= ROWS) return;
    int b = t >> 12;
    float q = (lane < RDIM) ? qatd[(size_t)t * RDIM + lane] : 0.f;
    float ss = warp_sum(q * q);
    float qn = q * (1.f / fmaxf(sqrtf(ss), 1e-12f));
    const float* kb = kkn + (size_t)b * MTOK * RDIM;
    float s0 = 0.f, s1 = 0.f;
    #pragma unroll
    for (int d = 0; d < RDIM; d++) {
        float qd = __shfl_sync(0xffffffffu, qn, d);
        s0 += qd * kb[lane * RDIM + d];
        s1 += qd * kb[(lane + 32) * RDIM + d];
    }
    float sc = fminf(fmaxf(scale[0], 0.f), 3.f);
    float ls = 1.f + sc * 4.15888308335967186f;  // log(64)
    s0 *= ls; s1 *= ls;
    float mv = fmaxf(s0, s1);
    int mi = (s0 >= s1) ? lane : lane + 32;
    #pragma unroll
    for (int o = 16; o; o >>= 1) {
        float ov = __shfl_xor_sync(0xffffffffu, mv, o);
        int   oi = __shfl_xor_sync(0xffffffffu, mi, o);
        if (ov > mv || (ov == mv && oi < mi)) { mv = ov; mi = oi; }
    }
    float p0 = __expf(s0 - mv), p1 = __expf(s1 - mv);
    float sum = warp_sum(p0 + p1);
    float inv = 1.f / sum;
    P[(size_t)t * MTOK + lane]      = f2bf(p0 * inv);
    P[(size_t)t * MTOK + lane + 32] = f2bf(p1 * inv);
    if (lane == 0) tkid[t] = mi;
}

// ---------------------------------------------------------------------------
// Single-pass stable counting sort scatter: block = (batch, bin).
// ---------------------------------------------------------------------------
__global__ void sortscatter_kernel(const int* __restrict__ tkid, int* __restrict__ sidx) {
    int b = blockIdx.x >> 6, bin = blockIdx.x & 63;
    const int* tk = tkid + b * NTOK;
    __shared__ int sc[256];
    int t = threadIdx.x;
    int start = t * 16;
    int eq = 0, less = 0;
    int vals[16];
    #pragma unroll
    for (int k = 0; k < 16; k++) {
        vals[k] = tk[start + k];
        eq += (vals[k] == bin);
        less += (vals[k] < bin);
    }
    sc[t] = (less << 16) | eq;
    __syncthreads();
    #pragma unroll
    for (int d = 1; d < 256; d <<= 1) {
        int v = (t >= d) ? sc[t - d] : 0;
        __syncthreads();
        sc[t] += v;
        __syncthreads();
    }
    int base = sc[255] >> 16;
    int pos = base + (sc[t] & 0xffff) - eq;
    #pragma unroll
    for (int k = 0; k < 16; k++)
        if (vals[k] == bin) sidx[b * NTOK + pos++] = start + k;
}

// ---------------------------------------------------------------------------
// AC_MSA grouped attention: 64 threads, 2 queries/thread, bf16 output.
// ---------------------------------------------------------------------------
__global__ __launch_bounds__(64) void acmsa_kernel(
        const float* __restrict__ qkv, const int* __restrict__ sidx,
        unsigned short* __restrict__ yout) {
    int bi = blockIdx.x;
    int hh = bi % HEADS;
    int g  = (bi / HEADS) % NG;
    int b  = bi / (HEADS * NG);
    int t = threadIdx.x;               // 0..63
    int lane = t & 31;
    int warp = t >> 5;                 // 0..1
    __shared__ __align__(16) float Ks[GS][32], Vs[GS][32];
    const int* sb = sidx + b * NTOK + g * GS;
    #pragma unroll 4
    for (int u = 0; u < 64; u++) {
        int rr = warp * 64 + u;
        int r_u = sb[rr];
        size_t rb = ((size_t)(b * NTOK + r_u)) * QKVW + hh * HD;
        float kv = 0.f, vv_ = 0.f;
        if (lane < HD) {
            kv  = qkv[rb + 180 + lane];
            vv_ = qkv[rb + 360 + lane];
        }
        Ks[rr][lane] = kv;
        Vs[rr][lane] = vv_;
    }
    const float scale = 0.18257418583505536f;   // 30^-0.5
    int rna = sb[t], rnb = sb[t + 64];
    const float2* qpa = (const float2*)(qkv + ((size_t)(b * NTOK + rna)) * QKVW + hh * HD);
    const float2* qpb = (const float2*)(qkv + ((size_t)(b * NTOK + rnb)) * QKVW + hh * HD);
    unsigned long long q2a[15], q2b[15];
    #pragma unroll
    for (int i = 0; i < 15; i++) {
        float2 va = qpa[i], vb = qpb[i];
        q2a[i] = pack2(va.x * scale, va.y * scale);
        q2b[i] = pack2(vb.x * scale, vb.y * scale);
    }
    __syncthreads();
    float ma = -1e30f, la = 0.f, mb = -1e30f, lb = 0.f;
    unsigned long long acc2a[15], acc2b[15];
    #pragma unroll
    for (int i = 0; i < 15; i++) { acc2a[i] = pack2(0.f, 0.f); acc2b[i] = pack2(0.f, 0.f); }
    for (int jc = 0; jc < GS; jc += 8) {
        float sa[8], sb_[8];
        #pragma unroll
        for (int u = 0; u < 8; u++) {
            const unsigned long long* k2 = (const unsigned long long*)Ks[jc + u];
            unsigned long long s2a = pack2(0.f, 0.f), s2b = pack2(0.f, 0.f);
            #pragma unroll
            for (int i = 0; i < 15; i++) {
                unsigned long long kk = k2[i];
                fma2(s2a, q2a[i], kk);
                fma2(s2b, q2b[i], kk);
            }
            float lo, hi;
            unpack2(s2a, lo, hi); sa[u]  = lo + hi;
            unpack2(s2b, lo, hi); sb_[u] = lo + hi;
        }
        float cma = sa[0], cmb = sb_[0];
        #pragma unroll
        for (int u = 1; u < 8; u++) { cma = fmaxf(cma, sa[u]); cmb = fmaxf(cmb, sb_[u]); }
        float mna = fmaxf(ma, cma), mnb = fmaxf(mb, cmb);
        float coa = __expf(ma - mna), cob = __expf(mb - mnb);
        ma = mna; mb = mnb;
        la *= coa; lb *= cob;
        unsigned long long coa2 = pack2(coa, coa), cob2 = pack2(cob, cob);
        #pragma unroll
        for (int i = 0; i < 15; i++) { acc2a[i] = mul2(acc2a[i], coa2); acc2b[i] = mul2(acc2b[i], cob2); }
        #pragma unroll
        for (int u = 0; u < 8; u++) {
            float pa = __expf(sa[u] - mna), pb = __expf(sb_[u] - mnb);
            la += pa; lb += pb;
            unsigned long long pa2 = pack2(pa, pa), pb2 = pack2(pb, pb);
            const unsigned long long* v2 = (const unsigned long long*)Vs[jc + u];
            #pragma unroll
            for (int i = 0; i < 15; i++) {
                unsigned long long vv_ = v2[i];
                fma2(acc2a[i], pa2, vv_);
                fma2(acc2b[i], pb2, vv_);
            }
        }
    }
    float inva = 1.f / la, invb = 1.f / lb;
    unsigned* ora = (unsigned*)(yout + ((size_t)(b * NTOK + rna)) * DIMC + hh * HD);
    unsigned* orb = (unsigned*)(yout + ((size_t)(b * NTOK + rnb)) * DIMC + hh * HD);
    #pragma unroll
    for (int i = 0; i < 15; i++) {
        float lo, hi;
        unpack2(acc2a[i], lo, hi); ora[i] = bf2pack(lo * inva, hi * inva);
        unpack2(acc2b[i], lo, hi); orb[i] = bf2pack(lo * invb, hi * invb);
    }
}

// ---------------------------------------------------------------------------
// Window attention: 128 threads, 2 queries/thread, bf16 output.
// ---------------------------------------------------------------------------
__global__ __launch_bounds__(128) void winattn_kernel(const float* __restrict__ qkv,
                                                      unsigned short* __restrict__ yout) {
    extern __shared__ float sm[];
    float* Ks = sm;
    float* Vs = sm + WINN * 32;
    int bi = blockIdx.x;
    int hh = bi % HEADS;
    int wdx = bi / HEADS;
    int b = wdx >> 4;
    int wy = (wdx >> 2) & 3;
    int wx = wdx & 3;
    int t = threadIdx.x;               // 0..127
    int lane = t & 31;
    int warp = t >> 5;                 // 0..3
    #pragma unroll 4
    for (int u = 0; u < 64; u++) {
        int rr = warp * 64 + u;
        int ny = (wy * WS + (rr >> 4)) * WW + wx * WS + (rr & 15);
        size_t rb = ((size_t)(b * NTOK + ny)) * QKVW + hh * HD;
        float kv = 0.f, vv_ = 0.f;
        if (lane < HD) {
            kv  = qkv[rb + 180 + lane];
            vv_ = qkv[rb + 360 + lane];
        }
        Ks[rr * 32 + lane] = kv;
        Vs[rr * 32 + lane] = vv_;
    }
    const float scale = 0.18257418583505536f;
    int qa_i = t, qb_i = t + 128;
    int na = (wy * WS + (qa_i >> 4)) * WW + wx * WS + (qa_i & 15);
    int nb = (wy * WS + (qb_i >> 4)) * WW + wx * WS + (qb_i & 15);
    const float2* qpa = (const float2*)(qkv + ((size_t)(b * NTOK + na)) * QKVW + hh * HD);
    const float2* qpb = (const float2*)(qkv + ((size_t)(b * NTOK + nb)) * QKVW + hh * HD);
    unsigned long long q2a[15], q2b[15];
    #pragma unroll
    for (int i = 0; i < 15; i++) {
        float2 va = qpa[i], vb = qpb[i];
        q2a[i] = pack2(va.x * scale, va.y * scale);
        q2b[i] = pack2(vb.x * scale, vb.y * scale);
    }
    __syncthreads();
    const float* browa = g_wbias + ((size_t)hh * WINN + qa_i) * WINN;
    const float* browb = g_wbias + ((size_t)hh * WINN + qb_i) * WINN;
    float ma = -1e30f, la = 0.f, mb = -1e30f, lb = 0.f;
    unsigned long long acc2a[15], acc2b[15];
    #pragma unroll
    for (int i = 0; i < 15; i++) { acc2a[i] = pack2(0.f, 0.f); acc2b[i] = pack2(0.f, 0.f); }
    for (int jc = 0; jc < WINN; jc += 8) {
        float sa[8], sb_[8];
        #pragma unroll
        for (int u = 0; u < 8; u++) {
            const unsigned long long* k2 = (const unsigned long long*)(Ks + (jc + u) * 32);
            unsigned long long s2a = pack2(0.f, 0.f), s2b = pack2(0.f, 0.f);
            #pragma unroll
            for (int i = 0; i < 15; i++) {
                unsigned long long kk = k2[i];
                fma2(s2a, q2a[i], kk);
                fma2(s2b, q2b[i], kk);
            }
            float lo, hi;
            unpack2(s2a, lo, hi); sa[u]  = lo + hi + browa[jc + u];
            unpack2(s2b, lo, hi); sb_[u] = lo + hi + browb[jc + u];
        }
        float cma = sa[0], cmb = sb_[0];
        #pragma unroll
        for (int u = 1; u < 8; u++) { cma = fmaxf(cma, sa[u]); cmb = fmaxf(cmb, sb_[u]); }
        float mna = fmaxf(ma, cma), mnb = fmaxf(mb, cmb);
        float coa = __expf(ma - mna), cob = __expf(mb - mnb);
        ma = mna; mb = mnb;
        la *= coa; lb *= cob;
        unsigned long long coa2 = pack2(coa, coa), cob2 = pack2(cob, cob);
        #pragma unroll
        for (int i = 0; i < 15; i++) { acc2a[i] = mul2(acc2a[i], coa2); acc2b[i] = mul2(acc2b[i], cob2); }
        #pragma unroll
        for (int u = 0; u < 8; u++) {
            float pa = __expf(sa[u] - mna), pb = __expf(sb_[u] - mnb);
            la += pa; lb += pb;
            unsigned long long pa2 = pack2(pa, pa), pb2 = pack2(pb, pb);
            const unsigned long long* v2 = (const unsigned long long*)(Vs + (jc + u) * 32);
            #pragma unroll
            for (int i = 0; i < 15; i++) {
                unsigned long long vv_ = v2[i];
                fma2(acc2a[i], pa2, vv_);
                fma2(acc2b[i], pb2, vv_);
            }
        }
    }
    float inva = 1.f / la, invb = 1.f / lb;
    unsigned* ora = (unsigned*)(yout + ((size_t)(b * NTOK + na)) * DIMC + hh * HD);
    unsigned* orb = (unsigned*)(yout + ((size_t)(b * NTOK + nb)) * DIMC + hh * HD);
    #pragma unroll
    for (int i = 0; i < 15; i++) {
        float lo, hi;
        unpack2(acc2a[i], lo, hi); ora[i] = bf2pack(lo * inva, hi * inva);
        unpack2(acc2b[i], lo, hi); orb[i] = bf2pack(lo * invb, hi * invb);
    }
}

// ---------------------------------------------------------------------------
// Gather per-token dictionary features into hc[:, 360:424] (fp32)
// ---------------------------------------------------------------------------
__global__ void gathertd_kernel(const float* __restrict__ tdproj, const int* __restrict__ tkid,
                                float* __restrict__ hc) {
    int e = blockIdx.x * blockDim.x + threadIdx.x;
    if (e < ROWS * DTD) {
        int r = e >> 6, j = e & 63;
        int b = r >> 12;
        hc[(size_t)r * CFF + MLP_HID + j] = tdproj[((size_t)b * MTOK + tkid[r]) * DTD + j];
    }
}

// ---------------------------------------------------------------------------
// Depthwise 5x5 conv + GELU + residual; bf16 output hc2.
// ---------------------------------------------------------------------------
#define DWCH 8
__global__ void dwconv_kernel(const float* __restrict__ hc, const float* __restrict__ w,
                              const float* __restrict__ bias, unsigned short* __restrict__ hc2) {
    __shared__ float smd[20 * 20 * DWCH];
    __shared__ float wsm[25][DWCH];
    __shared__ float bsm[DWCH];
    int tid = threadIdx.x;
    int c0 = blockIdx.y * DWCH;
    int b  = blockIdx.z;
    int tileY = (blockIdx.x >> 2) * 16, tileX = (blockIdx.x & 3) * 16;
    if (tid < 200) { int t5 = tid % 25, j = tid / 25; wsm[t5][j] = w[(c0 + j) * 25 + t5]; }
    if (tid < DWCH) bsm[tid] = bias[c0 + tid];
    for (int i = tid; i < 800; i += 256) {
        int cell = i >> 1, half = i & 1;
        int cy = cell / 20, cx = cell % 20;
        int gy = tileY + cy - 2, gx = tileX + cx - 2;
        float4 v = {0.f, 0.f, 0.f, 0.f};
        if (gy >= 0 && gy < 64 && gx >= 0 && gx < 64)
            v = *(const float4*)&hc[(((size_t)b << 12) + (gy << 6) + gx) * CFF + c0 + half * 4];
        *(float4*)&smd[cell * 8 + half * 4] = v;
    }
    __syncthreads();
    int ty = tid >> 4, tx = tid & 15;
    float acc[DWCH];
    #pragma unroll
    for (int j = 0; j < DWCH; j++) acc[j] = 0.f;
    #pragma unroll
    for (int ky = 0; ky < 5; ky++) {
        #pragma unroll
        for (int kx = 0; kx < 5; kx++) {
            const float* cp = &smd[((ty + ky) * 20 + tx + kx) * 8];
            float4 a0 = *(const float4*)cp;
            float4 a1 = *(const float4*)(cp + 4);
            int t5 = ky * 5 + kx;
            acc[0] += a0.x * wsm[t5][0];
            acc[1] += a0.y * wsm[t5][1];
            acc[2] += a0.z * wsm[t5][2];
            acc[3] += a0.w * wsm[t5][3];
            acc[4] += a1.x * wsm[t5][4];
            acc[5] += a1.y * wsm[t5][5];
            acc[6] += a1.z * wsm[t5][6];
            acc[7] += a1.w * wsm[t5][7];
        }
    }
    const float* ctr = &smd[((ty + 2) * 20 + tx + 2) * 8];
    size_t idx = (((size_t)b << 12) + ((size_t)(tileY + ty) << 6) + (tileX + tx)) * CFF + c0;
    float o[8];
    #pragma unroll
    for (int j = 0; j < 8; j++) o[j] = ctr[j] + gelu_exact(acc[j] + bsm[j]);
    uint4 pk;
    pk.x = bf2pack(o[0], o[1]);
    pk.y = bf2pack(o[2], o[3]);
    pk.z = bf2pack(o[4], o[5]);
    pk.w = bf2pack(o[6], o[7]);
    *(uint4*)&hc2[idx] = pk;
}

// ---------------------------------------------------------------------------
// Launch: two-stream DAG. Side stream runs convw/wbias/dict + ATD chain
// concurrent with qkv GEMM + window attention on the main (default) stream.
// ---------------------------------------------------------------------------
extern "C" void kernel_launch(void* const* d_in, const int* in_sizes, int n_in,
                              void* d_out, int out_size) {
    const float* x        = (const float*)d_in[0];
    const float* td       = (const float*)d_in[1];
    const float* n1g      = (const float*)d_in[2];
    const float* n1b      = (const float*)d_in[3];
    const float* wqkv_w   = (const float*)d_in[4];
    const float* wqkv_b   = (const float*)d_in[5];
    const float* atd_wq_w = (const float*)d_in[6];
    const float* atd_wq_b = (const float*)d_in[7];
    const float* atd_wk_w = (const float*)d_in[8];
    const float* atd_wk_b = (const float*)d_in[9];
    const float* atd_wv_w = (const float*)d_in[10];
    const float* atd_wv_b = (const float*)d_in[11];
    const float* atd_sc   = (const float*)d_in[12];
    const float* aca_w    = (const float*)d_in[13];
    const float* aca_b    = (const float*)d_in[14];
    const float* win_rpb  = (const float*)d_in[15];
    const float* win_w    = (const float*)d_in[16];
    const float* win_b    = (const float*)d_in[17];
    const float* fctd_w   = (const float*)d_in[18];
    const float* fctd_b   = (const float*)d_in[19];
    const float* fc1_w    = (const float*)d_in[20];
    const float* fc1_b    = (const float*)d_in[21];
    const float* dw_w     = (const float*)d_in[22];
    const float* dw_b     = (const float*)d_in[23];
    const float* fc2_w    = (const float*)d_in[24];
    const float* fc2_b    = (const float*)d_in[25];
    const float* n2g      = (const float*)d_in[26];
    const float* n2b      = (const float*)d_in[27];
    const int*   rpi      = (const int*)d_in[28];
    float* out = (float*)d_out;

    float *qkv, *qatd, *kkn, *tdpr, *xsum, *hc;
    unsigned short *xn, *x2n, *yaca, *ywin, *patd, *hc2, *vvt, *wt;
    int *tkid, *sidx;
    cudaGetSymbolAddress((void**)&xn,   g_xn);
    cudaGetSymbolAddress((void**)&qkv,  g_qkv);
    cudaGetSymbolAddress((void**)&qatd, g_qatd);
    cudaGetSymbolAddress((void**)&kkn,  g_kkn);
    cudaGetSymbolAddress((void**)&vvt,  g_vvt);
    cudaGetSymbolAddress((void**)&tdpr, g_tdpr);
    cudaGetSymbolAddress((void**)&patd, g_patd);
    cudaGetSymbolAddress((void**)&yaca, g_yaca);
    cudaGetSymbolAddress((void**)&ywin, g_ywin);
    cudaGetSymbolAddress((void**)&xsum, g_xsum);
    cudaGetSymbolAddress((void**)&x2n,  g_x2n);
    cudaGetSymbolAddress((void**)&hc,   g_hc);
    cudaGetSymbolAddress((void**)&hc2,  g_hc2);
    cudaGetSymbolAddress((void**)&tkid, g_tkid);
    cudaGetSymbolAddress((void**)&sidx, g_sidx);
    cudaGetSymbolAddress((void**)&wt,   g_wt);

    // One-time stream/event setup (created during the uncaptured correctness
    // call; only record/wait appear inside graph capture).
    static cudaStream_t s1 = nullptr;
    static cudaEvent_t eRoot, eLn1, eConvw, eWbias, eQkv, eAcmsa, eGath;
    if (!s1) {
        cudaStreamCreateWithFlags(&s1, cudaStreamNonBlocking);
        cudaEventCreateWithFlags(&eRoot,  cudaEventDisableTiming);
        cudaEventCreateWithFlags(&eLn1,   cudaEventDisableTiming);
        cudaEventCreateWithFlags(&eConvw, cudaEventDisableTiming);
        cudaEventCreateWithFlags(&eWbias, cudaEventDisableTiming);
        cudaEventCreateWithFlags(&eQkv,   cudaEventDisableTiming);
        cudaEventCreateWithFlags(&eAcmsa, cudaEventDisableTiming);
        cudaEventCreateWithFlags(&eGath,  cudaEventDisableTiming);
        cudaFuncSetAttribute(winattn_kernel, cudaFuncAttributeMaxDynamicSharedMemorySize, 65536);
    }

    // ---- fork side stream from main ----
    cudaEventRecord(eRoot, 0);
    cudaStreamWaitEvent(s1, eRoot, 0);

    // ---- side stream: prologue kernels ----
    convw_all<<<(S_TOT + 255)/256, 256, 0, s1>>>(wqkv_w, aca_w, win_w, fc1_w, fc2_w, wt);
    cudaEventRecord(eConvw, s1);
    wbias_kernel<<<WINN*WINN/256, 256, 0, s1>>>(rpi, win_rpb);
    cudaEventRecord(eWbias, s1);
    dict_kernel<<<BATCH*MTOK, 256, 0, s1>>>(td, atd_wk_w, atd_wk_b, atd_wv_w, atd_wv_b,
                                            fctd_w, fctd_b, kkn, vvt, tdpr);

    // ---- main stream: LN1 (+ fused q_atd) ----
    ln_kernel<<<ROWS/8, 256>>>(x, n1g, n1b, xn, atd_wq_w, atd_wq_b, qatd);
    cudaEventRecord(eLn1, 0);

    // main: qkv GEMM (needs convw)
    cudaStreamWaitEvent(0, eConvw, 0);
    gemm_bf<<<dim3(9, ROWS/128), 256>>>(xn, wt + WT_QKV, DIMC, nullptr, nullptr, 0,
                                        nullptr, nullptr, 0, 0,
                                        wqkv_b, nullptr, nullptr,
                                        qkv, ROWS, QKVW, QKVW, 0);
    cudaEventRecord(eQkv, 0);

    // main: window attention (needs qkv + wbias)
    cudaStreamWaitEvent(0, eWbias, 0);
    winattn_kernel<<<NWIN*HEADS, 128, 65536>>>(qkv, ywin);

    // ---- side stream: ATD chain (needs ln1; acmsa needs qkv) ----
    cudaStreamWaitEvent(s1, eLn1, 0);
    atd_kernel<<<ROWS/8, 256, 0, s1>>>(qatd, kkn, atd_sc, patd, tkid);
    sortscatter_kernel<<<BATCH*MTOK, 256, 0, s1>>>(tkid, sidx);
    cudaStreamWaitEvent(s1, eQkv, 0);
    acmsa_kernel<<<BATCH*NG*HEADS, 64, 0, s1>>>(qkv, sidx, yaca);
    cudaEventRecord(eAcmsa, s1);
    // gathertd (needs tdpr + tkid, both on s1) — writes hc[:,360:424]
    gathertd_kernel<<<ROWS*DTD/256, 256, 0, s1>>>(tdpr, tkid, hc);
    cudaEventRecord(eGath, s1);

    // ---- main stream: join acmsa branch, fused residual GEMM ----
    cudaStreamWaitEvent(0, eAcmsa, 0);
    gemm_bf<<<dim3(3, ROWS/128), 256>>>(yaca, wt + WT_ACA, DIMC, ywin, wt + WT_WIN, DIMC,
                                        patd, vvt, (long)DIMC*MTOK, MTOK,
                                        aca_b, win_b, x,
                                        xsum, ROWS, DIMC, DIMC, 0);
    // LN2
    ln_kernel<<<ROWS/8, 256>>>(xsum, n2g, n2b, x2n, nullptr, nullptr, nullptr);
    // fc1 + GELU into hc[:, 0:360] (disjoint from gathertd's columns)
    gemm_bf<<<dim3(6, ROWS/128), 256>>>(x2n, wt + WT_FC1, DIMC, nullptr, nullptr, 0,
                                        nullptr, nullptr, 0, 0,
                                        fc1_b, nullptr, nullptr,
                                        hc, ROWS, MLP_HID, CFF, 1);
    // dwconv needs full hc (fc1 on main + gathertd on s1)
    cudaStreamWaitEvent(0, eGath, 0);
    dwconv_kernel<<<dim3(16, CFF/DWCH, BATCH), 256>>>(hc, dw_w, dw_b, hc2);
    // out = xsum + hc2 @ fc2 + b
    gemm_bf<<<dim3(3, ROWS/128), 256>>>(hc2, wt + WT_FC2, CFF, nullptr, nullptr, 0,
                                        nullptr, nullptr, 0, 0,
                                        fc2_b, nullptr, xsum,
                                        out, ROWS, DIMC, DIMC, 0);
}

// round 13
// speedup vs baseline: 1.9683x; 1.3884x over previous
#include <cuda_runtime.h>
#include <cuda_bf16.h>
#include <math.h>

// ---------------------------------------------------------------------------
// Problem constants
// ---------------------------------------------------------------------------
#define BATCH 8
#define NTOK 4096
#define ROWS (BATCH*NTOK)
#define DIMC 180
#define HEADS 6
#define HD 30
#define QKVW 540
#define MTOK 64
#define RDIM 10
#define GS 128
#define NG 32
#define WS 16
#define WINN 256
#define NWIN 128
#define MLP_HID 360
#define DTD 64
#define CFF 424
#define HH 64
#define WW 64

// bf16 weight scratch offsets (elements)
#define WT_QKV 0
#define WT_ACA (WT_QKV + DIMC*QKVW)
#define WT_WIN (WT_ACA + DIMC*DIMC)
#define WT_FC1 (WT_WIN + DIMC*DIMC)
#define WT_FC2 (WT_FC1 + DIMC*MLP_HID)
#define WT_TOTAL (WT_FC2 + CFF*DIMC)

// ---------------------------------------------------------------------------
// Scratch
// ---------------------------------------------------------------------------
__device__ unsigned short g_xn  [ROWS*DIMC];        // bf16
__device__ float g_qkv  [ROWS*QKVW];
__device__ float g_qatd [ROWS*RDIM];
__device__ float g_kkn  [BATCH*MTOK*RDIM];
__device__ unsigned short g_vvt [BATCH*DIMC*MTOK];  // bf16, transposed [b][n][m]
__device__ float g_tdpr [BATCH*MTOK*DTD];
__device__ unsigned short g_patd[ROWS*MTOK];        // bf16
__device__ int   g_tkid [ROWS];
__device__ int   g_sidx [ROWS];
__device__ unsigned short g_yaca[ROWS*DIMC];        // bf16
__device__ unsigned short g_ywin[ROWS*DIMC];        // bf16
__device__ float g_xsum [ROWS*DIMC];
__device__ unsigned short g_x2n [ROWS*DIMC];        // bf16
__device__ float g_hc   [ROWS*CFF];
__device__ unsigned short g_hc2 [ROWS*CFF];         // bf16
__device__ float g_wbias[HEADS*WINN*WINN];
__device__ unsigned short g_wt  [WT_TOTAL];         // bf16 transposed weights

// ---------------------------------------------------------------------------
// Helpers
// ---------------------------------------------------------------------------
__device__ __forceinline__ float warp_sum(float v) {
    #pragma unroll
    for (int o = 16; o; o >>= 1) v += __shfl_xor_sync(0xffffffffu, v, o);
    return v;
}
__device__ __forceinline__ float gelu_exact(float v) {
    return 0.5f * v * (1.0f + erff(v * 0.70710678118654752440f));
}
__device__ __forceinline__ unsigned long long pack2(float lo, float hi) {
    unsigned long long r;
    asm("mov.b64 %0,{%1,%2};" : "=l"(r) : "f"(lo), "f"(hi));
    return r;
}
__device__ __forceinline__ void unpack2(unsigned long long v, float& lo, float& hi) {
    asm("mov.b64 {%0,%1},%2;" : "=f"(lo), "=f"(hi) : "l"(v));
}
__device__ __forceinline__ void fma2(unsigned long long& d, unsigned long long a,
                                     unsigned long long b) {
    asm("fma.rn.f32x2 %0,%1,%2,%0;" : "+l"(d) : "l"(a), "l"(b));
}
__device__ __forceinline__ unsigned long long mul2(unsigned long long a, unsigned long long b) {
    unsigned long long r;
    asm("mul.rn.f32x2 %0,%1,%2;" : "=l"(r) : "l"(a), "l"(b));
    return r;
}
__device__ __forceinline__ unsigned smem_u32(const void* p) {
    return (unsigned)__cvta_generic_to_shared(p);
}
__device__ __forceinline__ unsigned short f2bf(float v) {
    __nv_bfloat16 h = __float2bfloat16_rn(v);
    return *(unsigned short*)&h;
}
__device__ __forceinline__ unsigned bf2pack(float lo, float hi) {
    __nv_bfloat162 h = __floats2bfloat162_rn(lo, hi);
    return *(unsigned*)&h;
}
__device__ __forceinline__ void ldsm4(unsigned& r0, unsigned& r1, unsigned& r2, unsigned& r3,
                                      unsigned addr) {
    asm volatile("ldmatrix.sync.aligned.m8n8.x4.shared.b16 {%0,%1,%2,%3}, [%4];"
                 : "=r"(r0), "=r"(r1), "=r"(r2), "=r"(r3) : "r"(addr));
}
__device__ __forceinline__ void mma_bf(float* d, const unsigned* a, unsigned b0, unsigned b1) {
    asm volatile(
        "mma.sync.aligned.m16n8k16.row.col.f32.bf16.bf16.f32 "
        "{%0,%1,%2,%3},{%4,%5,%6,%7},{%8,%9},{%0,%1,%2,%3};"
        : "+f"(d[0]), "+f"(d[1]), "+f"(d[2]), "+f"(d[3])
        : "r"(a[0]), "r"(a[1]), "r"(a[2]), "r"(a[3]), "r"(b0), "r"(b1));
}

// ---------------------------------------------------------------------------
// Merged weight transpose+convert for all five GEMM weights.
// ---------------------------------------------------------------------------
#define S_QKV (DIMC*QKVW)
#define S_ACA (DIMC*DIMC)
#define S_WIN (DIMC*DIMC)
#define S_FC1 (DIMC*MLP_HID)
#define S_FC2 (CFF*DIMC)
#define S_TOT (S_QKV+S_ACA+S_WIN+S_FC1+S_FC2)

__global__ void convw_all(const float* __restrict__ qkv_w, const float* __restrict__ aca_w,
                          const float* __restrict__ win_w, const float* __restrict__ fc1_w,
                          const float* __restrict__ fc2_w, unsigned short* __restrict__ wt) {
    int i = blockIdx.x * blockDim.x + threadIdx.x;
    if (i >= S_TOT) return;
    const float* W; int K, N, loc, base;
    if (i < S_QKV)                       { W = qkv_w; K = DIMC; N = QKVW;   loc = i;                         base = WT_QKV; }
    else if (i < S_QKV+S_ACA)            { W = aca_w; K = DIMC; N = DIMC;   loc = i - S_QKV;                 base = WT_ACA; }
    else if (i < S_QKV+S_ACA+S_WIN)      { W = win_w; K = DIMC; N = DIMC;   loc = i - S_QKV - S_ACA;         base = WT_WIN; }
    else if (i < S_QKV+S_ACA+S_WIN+S_FC1){ W = fc1_w; K = DIMC; N = MLP_HID;loc = i - S_QKV - S_ACA - S_WIN; base = WT_FC1; }
    else                                 { W = fc2_w; K = CFF;  N = DIMC;   loc = i - S_QKV-S_ACA-S_WIN-S_FC1; base = WT_FC2; }
    int n = loc / K, k = loc % K;
    wt[base + loc] = f2bf(W[(size_t)k * N + n]);
}

// ---------------------------------------------------------------------------
// Fused dictionary projections: kkn fp32 l2n, vvt bf16 transposed, tdpr fp32
// ---------------------------------------------------------------------------
__global__ void dict_kernel(const float* __restrict__ td,
                            const float* __restrict__ wk_w, const float* __restrict__ wk_b,
                            const float* __restrict__ wv_w, const float* __restrict__ wv_b,
                            const float* __restrict__ ftd_w, const float* __restrict__ ftd_b,
                            float* __restrict__ kkn, unsigned short* __restrict__ vvt,
                            float* __restrict__ tdpr) {
    int r = blockIdx.x;                 // 0..511
    int b = r >> 6, m = r & 63;
    __shared__ float as[DIMC];
    __shared__ float kbuf[RDIM];
    int tid = threadIdx.x;
    const float* ar = td + (size_t)r * DIMC;
    if (tid < DIMC) as[tid] = ar[tid];
    __syncthreads();
    if (tid < DIMC) {
        float acc = wv_b[tid];
        #pragma unroll 4
        for (int k = 0; k < DIMC; k++) acc += as[k] * wv_w[(size_t)k * DIMC + tid];
        vvt[((size_t)b * DIMC + tid) * MTOK + m] = f2bf(acc);
    } else if (tid < DIMC + DTD) {
        int c = tid - DIMC;
        float acc = ftd_b[c];
        #pragma unroll 4
        for (int k = 0; k < DIMC; k++) acc += as[k] * ftd_w[(size_t)k * DTD + c];
        tdpr[(size_t)r * DTD + c] = acc;
    } else if (tid < DIMC + DTD + RDIM) {
        int c = tid - DIMC - DTD;
        float acc = wk_b[c];
        #pragma unroll 4
        for (int k = 0; k < DIMC; k++) acc += as[k] * wk_w[(size_t)k * RDIM + c];
        kbuf[c] = acc;
    }
    __syncthreads();
    if (tid >= DIMC + DTD && tid < DIMC + DTD + RDIM) {
        int c = tid - DIMC - DTD;
        float ss = 0.f;
        #pragma unroll
        for (int j = 0; j < RDIM; j++) ss += kbuf[j] * kbuf[j];
        float inv = 1.f / fmaxf(sqrtf(ss), 1e-12f);
        kkn[(size_t)r * RDIM + c] = kbuf[c] * inv;
    }
}

// ---------------------------------------------------------------------------
// Window attention bias expansion
// ---------------------------------------------------------------------------
__global__ void wbias_kernel(const int* __restrict__ rpi, const float* __restrict__ rpb) {
    int e = blockIdx.x * blockDim.x + threadIdx.x;
    if (e < WINN * WINN) {
        int idx = rpi[e];
        #pragma unroll
        for (int h = 0; h < HEADS; h++) g_wbias[h * WINN * WINN + e] = rpb[idx * HEADS + h];
    }
}

// ---------------------------------------------------------------------------
// LayerNorm -> bf16 out (+ optional fused 10-dim q projection, fp32)
// ---------------------------------------------------------------------------
__global__ void ln_kernel(const float* __restrict__ x, const float* __restrict__ g,
                          const float* __restrict__ b, unsigned short* __restrict__ out,
                          const float* __restrict__ wq, const float* __restrict__ bq,
                          float* __restrict__ qout) {
    __shared__ float ws[1920];
    __shared__ float bqs[16];
    int tid = threadIdx.x;
    if (wq) {
        for (int i = tid; i < 1920; i += 256) ws[i] = (i < DIMC * RDIM) ? wq[i] : 0.f;
        if (tid < RDIM) bqs[tid] = bq[tid];
        __syncthreads();
    }
    int row = (blockIdx.x * blockDim.x + tid) >> 5;
    if (row >= ROWS) return;
    int lane = tid & 31;
    const float* xr = x + (size_t)row * DIMC;
    float v[6], s = 0.f, s2 = 0.f;
    #pragma unroll
    for (int k = 0; k < 6; k++) {
        int c = lane + k * 32;
        v[k] = (c < DIMC) ? xr[c] : 0.f;
        s += v[k]; s2 += v[k] * v[k];
    }
    s = warp_sum(s); s2 = warp_sum(s2);
    float mu = s * (1.f / DIMC);
    float var = s2 * (1.f / DIMC) - mu * mu;
    float rstd = rsqrtf(var + 1e-5f);
    float nv[6];
    unsigned short* orow = out + (size_t)row * DIMC;
    #pragma unroll
    for (int k = 0; k < 6; k++) {
        int c = lane + k * 32;
        nv[k] = (c < DIMC) ? ((v[k] - mu) * rstd * g[c] + b[c]) : 0.f;
        if (c < DIMC) orow[c] = f2bf(nv[k]);
    }
    if (wq) {
        float myq = 0.f;
        #pragma unroll
        for (int o = 0; o < RDIM; o++) {
            float p = 0.f;
            #pragma unroll
            for (int k = 0; k < 6; k++) p += nv[k] * ws[(lane + 32 * k) * RDIM + o];
            p = warp_sum(p);
            if (lane == o) myq = p + bqs[o];
        }
        if (lane < RDIM) qout[(size_t)row * RDIM + lane] = myq;
    }
}

// ---------------------------------------------------------------------------
// bf16 tensor-core GEMM (m16n8k16) with ldmatrix fragment loads.
// ---------------------------------------------------------------------------
struct GPass { const unsigned short* A; const unsigned short* W; int K; int kt; };

__global__ __launch_bounds__(256) void gemm_bf(
        const unsigned short* __restrict__ A1, const unsigned short* __restrict__ W1, int K1,
        const unsigned short* __restrict__ A2, const unsigned short* __restrict__ W2, int K2,
        const unsigned short* __restrict__ A3, const unsigned short* __restrict__ W3base,
        long w3_stride, int K3,
        const float* __restrict__ b1, const float* __restrict__ b2,
        const float* __restrict__ add1,
        float* __restrict__ C, int M, int N, int ldc, int act) {
    __shared__ unsigned short As[2][128][40];
    __shared__ unsigned short Ws[2][64][40];
    int tid  = threadIdx.x;
    int lane = tid & 31;
    int warp = tid >> 5;
    int warpM = warp & 3;
    int warpN = warp >> 2;
    int gId = lane >> 2;
    int tig = lane & 3;
    int row0 = blockIdx.y * 128;
    int col0 = blockIdx.x * 64;

    GPass ps[3];
    int np = 0;
    if (A1 && K1 > 0) ps[np++] = {A1, W1, K1, (K1 + 31) >> 5};
    if (A2 && K2 > 0) ps[np++] = {A2, W2, K2, (K2 + 31) >> 5};
    if (A3 && K3 > 0) ps[np++] = {A3, W3base + (size_t)(row0 >> 12) * w3_stride, K3, (K3 + 31) >> 5};
    int total = 0;
    for (int p = 0; p < np; p++) total += ps[p].kt;

    auto copy_tile = [&](int gi, int buf) {
        int p = 0, loc = gi;
        while (loc >= ps[p].kt) { loc -= ps[p].kt; p++; }
        const unsigned short* A = ps[p].A;
        const unsigned short* W = ps[p].W;
        int K = ps[p].K;
        int k0 = loc << 5;
        #pragma unroll
        for (int f = 0; f < 4; f++) {
            int c = tid + f * 256;
            int m = c >> 3, kc = (c & 7) << 2;
            int gk = k0 + kc;
            int rem = K - gk;
            int bytes = (rem <= 0) ? 0 : ((rem >= 4) ? 8 : rem * 2);
            const unsigned short* src = bytes ? (A + (size_t)(row0 + m) * K + gk) : A;
            unsigned dst = smem_u32(&As[buf][m][kc]);
            asm volatile("cp.async.ca.shared.global [%0], [%1], 8, %2;"
                         :: "r"(dst), "l"(src), "r"(bytes));
        }
        #pragma unroll
        for (int f = 0; f < 2; f++) {
            int c = tid + f * 256;
            int n = c >> 3, kc = (c & 7) << 2;
            int gn = col0 + n, gk = k0 + kc;
            int bytes = 0;
            if (gn < N) {
                int rem = K - gk;
                bytes = (rem <= 0) ? 0 : ((rem >= 4) ? 8 : rem * 2);
            }
            const unsigned short* src = bytes ? (W + (size_t)gn * K + gk) : W;
            unsigned dst = smem_u32(&Ws[buf][n][kc]);
            asm volatile("cp.async.ca.shared.global [%0], [%1], 8, %2;"
                         :: "r"(dst), "l"(src), "r"(bytes));
        }
    };

    float d[2][4][4];
    #pragma unroll
    for (int mt = 0; mt < 2; mt++)
        #pragma unroll
        for (int nt = 0; nt < 4; nt++)
            #pragma unroll
            for (int i = 0; i < 4; i++) d[mt][nt][i] = 0.f;

    copy_tile(0, 0);
    asm volatile("cp.async.commit_group;");
    for (int i = 0; i < total; i++) {
        asm volatile("cp.async.wait_group 0;");
        __syncthreads();
        if (i + 1 < total) {
            copy_tile(i + 1, (i + 1) & 1);
            asm volatile("cp.async.commit_group;");
        }
        int buf = i & 1;
        #pragma unroll
        for (int ks = 0; ks < 2; ks++) {
            int kb = ks * 16;
            unsigned a[2][4], bfr[4][2];
            int arow = lane & 15;
            int acol = kb + ((lane >> 4) << 3);
            #pragma unroll
            for (int mt = 0; mt < 2; mt++) {
                int m0 = warpM * 32 + mt * 16;
                unsigned ad = smem_u32(&As[buf][m0 + arow][acol]);
                ldsm4(a[mt][0], a[mt][1], a[mt][2], a[mt][3], ad);
            }
            int wrow = ((lane >> 4) << 3) + (lane & 7);
            int wcol = kb + (((lane >> 3) & 1) << 3);
            #pragma unroll
            for (int np2 = 0; np2 < 2; np2++) {
                int n0 = warpN * 32 + np2 * 16;
                unsigned ad = smem_u32(&Ws[buf][n0 + wrow][wcol]);
                unsigned r0, r1, r2, r3;
                ldsm4(r0, r1, r2, r3, ad);
                bfr[2*np2][0] = r0;  bfr[2*np2][1] = r1;
                bfr[2*np2+1][0] = r2; bfr[2*np2+1][1] = r3;
            }
            #pragma unroll
            for (int mt = 0; mt < 2; mt++)
                #pragma unroll
                for (int nt = 0; nt < 4; nt++)
                    mma_bf(d[mt][nt], a[mt], bfr[nt][0], bfr[nt][1]);
        }
    }

    #pragma unroll
    for (int mt = 0; mt < 2; mt++) {
        #pragma unroll
        for (int nt = 0; nt < 4; nt++) {
            #pragma unroll
            for (int i = 0; i < 4; i++) {
                int r = row0 + warpM * 32 + mt * 16 + gId + (i >> 1) * 8;
                int c = col0 + warpN * 32 + nt * 8 + tig * 2 + (i & 1);
                if (c < N) {
                    float v = d[mt][nt][i];
                    if (b1)   v += b1[c];
                    if (b2)   v += b2[c];
                    if (add1) v += add1[(size_t)r * N + c];
                    if (act)  v = gelu_exact(v);
                    C[(size_t)r * ldc + c] = v;
                }
            }
        }
    }
}

// ---------------------------------------------------------------------------
// ATD: softmax probs P (bf16) + argmax tkid. One warp per token. fp32 math.
// ---------------------------------------------------------------------------
__global__ void atd_kernel(const float* __restrict__ qatd, const float* __restrict__ kkn,
                           const float* __restrict__ scale,
                           unsigned short* __restrict__ P, int* __restrict__ tkid) {
    int t = (blockIdx.x * blockDim.x + threadIdx.x) >> 5;
    int lane = threadIdx.x & 31;
    if (t >= ROWS) return;
    int b = t >> 12;
    float q = (lane < RDIM) ? qatd[(size_t)t * RDIM + lane] : 0.f;
    float ss = warp_sum(q * q);
    float qn = q * (1.f / fmaxf(sqrtf(ss), 1e-12f));
    const float* kb = kkn + (size_t)b * MTOK * RDIM;
    float s0 = 0.f, s1 = 0.f;
    #pragma unroll
    for (int d = 0; d < RDIM; d++) {
        float qd = __shfl_sync(0xffffffffu, qn, d);
        s0 += qd * kb[lane * RDIM + d];
        s1 += qd * kb[(lane + 32) * RDIM + d];
    }
    float sc = fminf(fmaxf(scale[0], 0.f), 3.f);
    float ls = 1.f + sc * 4.15888308335967186f;  // log(64)
    s0 *= ls; s1 *= ls;
    float mv = fmaxf(s0, s1);
    int mi = (s0 >= s1) ? lane : lane + 32;
    #pragma unroll
    for (int o = 16; o; o >>= 1) {
        float ov = __shfl_xor_sync(0xffffffffu, mv, o);
        int   oi = __shfl_xor_sync(0xffffffffu, mi, o);
        if (ov > mv || (ov == mv && oi < mi)) { mv = ov; mi = oi; }
    }
    float p0 = __expf(s0 - mv), p1 = __expf(s1 - mv);
    float sum = warp_sum(p0 + p1);
    float inv = 1.f / sum;
    P[(size_t)t * MTOK + lane]      = f2bf(p0 * inv);
    P[(size_t)t * MTOK + lane + 32] = f2bf(p1 * inv);
    if (lane == 0) tkid[t] = mi;
}

// ---------------------------------------------------------------------------
// Single-pass stable counting sort scatter: block = (batch, bin).
// ---------------------------------------------------------------------------
__global__ void sortscatter_kernel(const int* __restrict__ tkid, int* __restrict__ sidx) {
    int b = blockIdx.x >> 6, bin = blockIdx.x & 63;
    const int* tk = tkid + b * NTOK;
    __shared__ int sc[256];
    int t = threadIdx.x;
    int start = t * 16;
    int eq = 0, less = 0;
    int vals[16];
    #pragma unroll
    for (int k = 0; k < 16; k++) {
        vals[k] = tk[start + k];
        eq += (vals[k] == bin);
        less += (vals[k] < bin);
    }
    sc[t] = (less << 16) | eq;
    __syncthreads();
    #pragma unroll
    for (int d = 1; d < 256; d <<= 1) {
        int v = (t >= d) ? sc[t - d] : 0;
        __syncthreads();
        sc[t] += v;
        __syncthreads();
    }
    int base = sc[255] >> 16;
    int pos = base + (sc[t] & 0xffff) - eq;
    #pragma unroll
    for (int k = 0; k < 16; k++)
        if (vals[k] == bin) sidx[b * NTOK + pos++] = start + k;
}

// ---------------------------------------------------------------------------
// AC_MSA grouped attention: 64 threads, 2 queries/thread, bf16 output.
// ---------------------------------------------------------------------------
__global__ __launch_bounds__(64) void acmsa_kernel(
        const float* __restrict__ qkv, const int* __restrict__ sidx,
        unsigned short* __restrict__ yout) {
    int bi = blockIdx.x;
    int hh = bi % HEADS;
    int g  = (bi / HEADS) % NG;
    int b  = bi / (HEADS * NG);
    int t = threadIdx.x;               // 0..63
    int lane = t & 31;
    int warp = t >> 5;                 // 0..1
    __shared__ __align__(16) float Ks[GS][32], Vs[GS][32];
    const int* sb = sidx + b * NTOK + g * GS;
    #pragma unroll 4
    for (int u = 0; u < 64; u++) {
        int rr = warp * 64 + u;
        int r_u = sb[rr];
        size_t rb = ((size_t)(b * NTOK + r_u)) * QKVW + hh * HD;
        float kv = 0.f, vv_ = 0.f;
        if (lane < HD) {
            kv  = qkv[rb + 180 + lane];
            vv_ = qkv[rb + 360 + lane];
        }
        Ks[rr][lane] = kv;
        Vs[rr][lane] = vv_;
    }
    const float scale = 0.18257418583505536f;   // 30^-0.5
    int rna = sb[t], rnb = sb[t + 64];
    const float2* qpa = (const float2*)(qkv + ((size_t)(b * NTOK + rna)) * QKVW + hh * HD);
    const float2* qpb = (const float2*)(qkv + ((size_t)(b * NTOK + rnb)) * QKVW + hh * HD);
    unsigned long long q2a[15], q2b[15];
    #pragma unroll
    for (int i = 0; i < 15; i++) {
        float2 va = qpa[i], vb = qpb[i];
        q2a[i] = pack2(va.x * scale, va.y * scale);
        q2b[i] = pack2(vb.x * scale, vb.y * scale);
    }
    __syncthreads();
    float ma = -1e30f, la = 0.f, mb = -1e30f, lb = 0.f;
    unsigned long long acc2a[15], acc2b[15];
    #pragma unroll
    for (int i = 0; i < 15; i++) { acc2a[i] = pack2(0.f, 0.f); acc2b[i] = pack2(0.f, 0.f); }
    for (int jc = 0; jc < GS; jc += 8) {
        float sa[8], sb_[8];
        #pragma unroll
        for (int u = 0; u < 8; u++) {
            const unsigned long long* k2 = (const unsigned long long*)Ks[jc + u];
            unsigned long long s2a = pack2(0.f, 0.f), s2b = pack2(0.f, 0.f);
            #pragma unroll
            for (int i = 0; i < 15; i++) {
                unsigned long long kk = k2[i];
                fma2(s2a, q2a[i], kk);
                fma2(s2b, q2b[i], kk);
            }
            float lo, hi;
            unpack2(s2a, lo, hi); sa[u]  = lo + hi;
            unpack2(s2b, lo, hi); sb_[u] = lo + hi;
        }
        float cma = sa[0], cmb = sb_[0];
        #pragma unroll
        for (int u = 1; u < 8; u++) { cma = fmaxf(cma, sa[u]); cmb = fmaxf(cmb, sb_[u]); }
        float mna = fmaxf(ma, cma), mnb = fmaxf(mb, cmb);
        float coa = __expf(ma - mna), cob = __expf(mb - mnb);
        ma = mna; mb = mnb;
        la *= coa; lb *= cob;
        unsigned long long coa2 = pack2(coa, coa), cob2 = pack2(cob, cob);
        #pragma unroll
        for (int i = 0; i < 15; i++) { acc2a[i] = mul2(acc2a[i], coa2); acc2b[i] = mul2(acc2b[i], cob2); }
        #pragma unroll
        for (int u = 0; u < 8; u++) {
            float pa = __expf(sa[u] - mna), pb = __expf(sb_[u] - mnb);
            la += pa; lb += pb;
            unsigned long long pa2 = pack2(pa, pa), pb2 = pack2(pb, pb);
            const unsigned long long* v2 = (const unsigned long long*)Vs[jc + u];
            #pragma unroll
            for (int i = 0; i < 15; i++) {
                unsigned long long vv_ = v2[i];
                fma2(acc2a[i], pa2, vv_);
                fma2(acc2b[i], pb2, vv_);
            }
        }
    }
    float inva = 1.f / la, invb = 1.f / lb;
    unsigned* ora = (unsigned*)(yout + ((size_t)(b * NTOK + rna)) * DIMC + hh * HD);
    unsigned* orb = (unsigned*)(yout + ((size_t)(b * NTOK + rnb)) * DIMC + hh * HD);
    #pragma unroll
    for (int i = 0; i < 15; i++) {
        float lo, hi;
        unpack2(acc2a[i], lo, hi); ora[i] = bf2pack(lo * inva, hi * inva);
        unpack2(acc2b[i], lo, hi); orb[i] = bf2pack(lo * invb, hi * invb);
    }
}

// ---------------------------------------------------------------------------
// Tensor-core window attention (flash-style).
// Block = (window, head); 8 warps x 32 queries. Keys in chunks of 32.
// Qs/Ks bf16 [256][40] (conflict-free ldmatrix); Vt bf16 [32][264]
// (bank = 4*gId + tig, all lanes distinct). S-frag reused as P A-frag.
// ---------------------------------------------------------------------------
#define VPITCH 264
#define WSMEM ((2*256*40 + 32*VPITCH) * 2)   // 57856 bytes

__global__ __launch_bounds__(256) void winattn_tc(const float* __restrict__ qkv,
                                                  unsigned short* __restrict__ yout) {
    extern __shared__ unsigned short sm16[];
    unsigned short* Qs = sm16;                 // [256][40]
    unsigned short* Ks = sm16 + 256 * 40;      // [256][40]
    unsigned short* Vt = sm16 + 2 * 256 * 40;  // [32][VPITCH]
    int bi = blockIdx.x;
    int hh = bi % HEADS;
    int wdx = bi / HEADS;
    int b = wdx >> 4;
    int wy = (wdx >> 2) & 3;
    int wx = wdx & 3;
    int lane = threadIdx.x & 31;
    int warp = threadIdx.x >> 5;               // 0..7
    const float scale = 0.18257418583505536f;  // 30^-0.5

    // fill: each warp loads 32 tokens (coalesced per row)
    #pragma unroll 4
    for (int u = 0; u < 32; u++) {
        int r = warp * 32 + u;
        int ny = (wy * WS + (r >> 4)) * WW + wx * WS + (r & 15);
        size_t rb = ((size_t)(b * NTOK + ny)) * QKVW + hh * HD;
        unsigned short qv = 0, kv = 0, vv = 0;
        if (lane < HD) {
            qv = f2bf(qkv[rb + lane] * scale);
            kv = f2bf(qkv[rb + 180 + lane]);
            vv = f2bf(qkv[rb + 360 + lane]);
        }
        Qs[r * 40 + lane] = qv;
        Ks[r * 40 + lane] = kv;
        Vt[lane * VPITCH + r] = vv;            // lanes 30,31 zero pad rows
    }
    __syncthreads();

    int gId = lane >> 2, tig = lane & 3;
    int m0 = warp * 32;

    // Q fragments (resident for whole kernel)
    unsigned qf[2][2][4];
    #pragma unroll
    for (int mt = 0; mt < 2; mt++)
        #pragma unroll
        for (int ks = 0; ks < 2; ks++) {
            unsigned ad = smem_u32(Qs + (m0 + mt * 16 + (lane & 15)) * 40
                                      + ks * 16 + ((lane >> 4) << 3));
            ldsm4(qf[mt][ks][0], qf[mt][ks][1], qf[mt][ks][2], qf[mt][ks][3], ad);
        }

    float mrow[2][2] = {{-1e30f, -1e30f}, {-1e30f, -1e30f}};
    float lrow[2][2] = {{0.f, 0.f}, {0.f, 0.f}};
    float o[2][4][4];
    #pragma unroll
    for (int mt = 0; mt < 2; mt++)
        #pragma unroll
        for (int vn = 0; vn < 4; vn++)
            #pragma unroll
            for (int i = 0; i < 4; i++) o[mt][vn][i] = 0.f;

    const float* bias = g_wbias + (size_t)hh * WINN * WINN;

    for (int jc = 0; jc < WINN; jc += 32) {
        // K fragments for this 32-key chunk
        unsigned kf[4][2][2];
        #pragma unroll
        for (int np2 = 0; np2 < 2; np2++)
            #pragma unroll
            for (int ks = 0; ks < 2; ks++) {
                unsigned ad = smem_u32(Ks + (jc + np2 * 16 + ((lane >> 4) << 3) + (lane & 7)) * 40
                                          + ks * 16 + (((lane >> 3) & 1) << 3));
                unsigned r0, r1, r2, r3;
                ldsm4(r0, r1, r2, r3, ad);
                kf[2*np2][ks][0] = r0;   kf[2*np2][ks][1] = r1;
                kf[2*np2+1][ks][0] = r2; kf[2*np2+1][ks][1] = r3;
            }
        // S = Q @ K^T + bias
        float s[2][4][4];
        #pragma unroll
        for (int mt = 0; mt < 2; mt++)
            #pragma unroll
            for (int nt = 0; nt < 4; nt++) {
                #pragma unroll
                for (int i = 0; i < 4; i++) s[mt][nt][i] = 0.f;
                #pragma unroll
                for (int ks = 0; ks < 2; ks++)
                    mma_bf(s[mt][nt], qf[mt][ks], kf[nt][ks][0], kf[nt][ks][1]);
            }
        #pragma unroll
        for (int mt = 0; mt < 2; mt++)
            #pragma unroll
            for (int h = 0; h < 2; h++) {
                int q = m0 + mt * 16 + gId + 8 * h;
                #pragma unroll
                for (int nt = 0; nt < 4; nt++) {
                    float2 bv = *(const float2*)&bias[(size_t)q * WINN + jc + nt * 8 + 2 * tig];
                    s[mt][nt][2*h]   += bv.x;
                    s[mt][nt][2*h+1] += bv.y;
                }
            }
        // online softmax per row (row stats shared across tig quad)
        float co2[2][2];
        #pragma unroll
        for (int mt = 0; mt < 2; mt++)
            #pragma unroll
            for (int h = 0; h < 2; h++) {
                float rm = -1e30f;
                #pragma unroll
                for (int nt = 0; nt < 4; nt++)
                    rm = fmaxf(rm, fmaxf(s[mt][nt][2*h], s[mt][nt][2*h+1]));
                rm = fmaxf(rm, __shfl_xor_sync(0xffffffffu, rm, 1));
                rm = fmaxf(rm, __shfl_xor_sync(0xffffffffu, rm, 2));
                float mn = fmaxf(mrow[mt][h], rm);
                float co = __expf(mrow[mt][h] - mn);
                mrow[mt][h] = mn;
                float rs = 0.f;
                #pragma unroll
                for (int nt = 0; nt < 4; nt++) {
                    float e0 = __expf(s[mt][nt][2*h]   - mn);
                    float e1 = __expf(s[mt][nt][2*h+1] - mn);
                    s[mt][nt][2*h] = e0; s[mt][nt][2*h+1] = e1;
                    rs += e0 + e1;
                }
                rs += __shfl_xor_sync(0xffffffffu, rs, 1);
                rs += __shfl_xor_sync(0xffffffffu, rs, 2);
                lrow[mt][h] = lrow[mt][h] * co + rs;
                co2[mt][h] = co;
            }
        #pragma unroll
        for (int mt = 0; mt < 2; mt++)
            #pragma unroll
            for (int vn = 0; vn < 4; vn++)
                #pragma unroll
                for (int i = 0; i < 4; i++) o[mt][vn][i] *= co2[mt][i >> 1];
        // O += P @ V  (S frag -> P A-frag, V^T B-frag from plain LDS.32)
        #pragma unroll
        for (int ks = 0; ks < 2; ks++) {
            unsigned a[2][4];
            #pragma unroll
            for (int mt = 0; mt < 2; mt++) {
                a[mt][0] = bf2pack(s[mt][2*ks][0],   s[mt][2*ks][1]);
                a[mt][1] = bf2pack(s[mt][2*ks][2],   s[mt][2*ks][3]);
                a[mt][2] = bf2pack(s[mt][2*ks+1][0], s[mt][2*ks+1][1]);
                a[mt][3] = bf2pack(s[mt][2*ks+1][2], s[mt][2*ks+1][3]);
            }
            #pragma unroll
            for (int vn = 0; vn < 4; vn++) {
                const unsigned short* vp = Vt + (vn * 8 + gId) * VPITCH + jc + ks * 16 + 2 * tig;
                unsigned b0 = *(const unsigned*)vp;
                unsigned b1 = *(const unsigned*)(vp + 8);
                #pragma unroll
                for (int mt = 0; mt < 2; mt++)
                    mma_bf(o[mt][vn], a[mt], b0, b1);
            }
        }
    }
    // write output
    #pragma unroll
    for (int mt = 0; mt < 2; mt++)
        #pragma unroll
        for (int h = 0; h < 2; h++) {
            float inv = 1.f / lrow[mt][h];
            int row = m0 + mt * 16 + gId + 8 * h;
            int ny = (wy * WS + (row >> 4)) * WW + wx * WS + (row & 15);
            unsigned short* obase = yout + ((size_t)(b * NTOK + ny)) * DIMC + hh * HD;
            #pragma unroll
            for (int vn = 0; vn < 4; vn++) {
                int vd = vn * 8 + 2 * tig;
                if (vd < HD)
                    *(unsigned*)(obase + vd) =
                        bf2pack(o[mt][vn][2*h] * inv, o[mt][vn][2*h+1] * inv);
            }
        }
}

// ---------------------------------------------------------------------------
// Gather per-token dictionary features into hc[:, 360:424] (fp32)
// ---------------------------------------------------------------------------
__global__ void gathertd_kernel(const float* __restrict__ tdproj, const int* __restrict__ tkid,
                                float* __restrict__ hc) {
    int e = blockIdx.x * blockDim.x + threadIdx.x;
    if (e < ROWS * DTD) {
        int r = e >> 6, j = e & 63;
        int b = r >> 12;
        hc[(size_t)r * CFF + MLP_HID + j] = tdproj[((size_t)b * MTOK + tkid[r]) * DTD + j];
    }
}

// ---------------------------------------------------------------------------
// Depthwise 5x5 conv + GELU + residual; bf16 output hc2.
// ---------------------------------------------------------------------------
#define DWCH 8
__global__ void dwconv_kernel(const float* __restrict__ hc, const float* __restrict__ w,
                              const float* __restrict__ bias, unsigned short* __restrict__ hc2) {
    __shared__ float smd[20 * 20 * DWCH];
    __shared__ float wsm[25][DWCH];
    __shared__ float bsm[DWCH];
    int tid = threadIdx.x;
    int c0 = blockIdx.y * DWCH;
    int b  = blockIdx.z;
    int tileY = (blockIdx.x >> 2) * 16, tileX = (blockIdx.x & 3) * 16;
    if (tid < 200) { int t5 = tid % 25, j = tid / 25; wsm[t5][j] = w[(c0 + j) * 25 + t5]; }
    if (tid < DWCH) bsm[tid] = bias[c0 + tid];
    for (int i = tid; i < 800; i += 256) {
        int cell = i >> 1, half = i & 1;
        int cy = cell / 20, cx = cell % 20;
        int gy = tileY + cy - 2, gx = tileX + cx - 2;
        float4 v = {0.f, 0.f, 0.f, 0.f};
        if (gy >= 0 && gy < 64 && gx >= 0 && gx < 64)
            v = *(const float4*)&hc[(((size_t)b << 12) + (gy << 6) + gx) * CFF + c0 + half * 4];
        *(float4*)&smd[cell * 8 + half * 4] = v;
    }
    __syncthreads();
    int ty = tid >> 4, tx = tid & 15;
    float acc[DWCH];
    #pragma unroll
    for (int j = 0; j < DWCH; j++) acc[j] = 0.f;
    #pragma unroll
    for (int ky = 0; ky < 5; ky++) {
        #pragma unroll
        for (int kx = 0; kx < 5; kx++) {
            const float* cp = &smd[((ty + ky) * 20 + tx + kx) * 8];
            float4 a0 = *(const float4*)cp;
            float4 a1 = *(const float4*)(cp + 4);
            int t5 = ky * 5 + kx;
            acc[0] += a0.x * wsm[t5][0];
            acc[1] += a0.y * wsm[t5][1];
            acc[2] += a0.z * wsm[t5][2];
            acc[3] += a0.w * wsm[t5][3];
            acc[4] += a1.x * wsm[t5][4];
            acc[5] += a1.y * wsm[t5][5];
            acc[6] += a1.z * wsm[t5][6];
            acc[7] += a1.w * wsm[t5][7];
        }
    }
    const float* ctr = &smd[((ty + 2) * 20 + tx + 2) * 8];
    size_t idx = (((size_t)b << 12) + ((size_t)(tileY + ty) << 6) + (tileX + tx)) * CFF + c0;
    float o[8];
    #pragma unroll
    for (int j = 0; j < 8; j++) o[j] = ctr[j] + gelu_exact(acc[j] + bsm[j]);
    uint4 pk;
    pk.x = bf2pack(o[0], o[1]);
    pk.y = bf2pack(o[2], o[3]);
    pk.z = bf2pack(o[4], o[5]);
    pk.w = bf2pack(o[6], o[7]);
    *(uint4*)&hc2[idx] = pk;
}

// ---------------------------------------------------------------------------
// Launch: two-stream DAG (as R12) with tensor-core window attention.
// ---------------------------------------------------------------------------
extern "C" void kernel_launch(void* const* d_in, const int* in_sizes, int n_in,
                              void* d_out, int out_size) {
    const float* x        = (const float*)d_in[0];
    const float* td       = (const float*)d_in[1];
    const float* n1g      = (const float*)d_in[2];
    const float* n1b      = (const float*)d_in[3];
    const float* wqkv_w   = (const float*)d_in[4];
    const float* wqkv_b   = (const float*)d_in[5];
    const float* atd_wq_w = (const float*)d_in[6];
    const float* atd_wq_b = (const float*)d_in[7];
    const float* atd_wk_w = (const float*)d_in[8];
    const float* atd_wk_b = (const float*)d_in[9];
    const float* atd_wv_w = (const float*)d_in[10];
    const float* atd_wv_b = (const float*)d_in[11];
    const float* atd_sc   = (const float*)d_in[12];
    const float* aca_w    = (const float*)d_in[13];
    const float* aca_b    = (const float*)d_in[14];
    const float* win_rpb  = (const float*)d_in[15];
    const float* win_w    = (const float*)d_in[16];
    const float* win_b    = (const float*)d_in[17];
    const float* fctd_w   = (const float*)d_in[18];
    const float* fctd_b   = (const float*)d_in[19];
    const float* fc1_w    = (const float*)d_in[20];
    const float* fc1_b    = (const float*)d_in[21];
    const float* dw_w     = (const float*)d_in[22];
    const float* dw_b     = (const float*)d_in[23];
    const float* fc2_w    = (const float*)d_in[24];
    const float* fc2_b    = (const float*)d_in[25];
    const float* n2g      = (const float*)d_in[26];
    const float* n2b      = (const float*)d_in[27];
    const int*   rpi      = (const int*)d_in[28];
    float* out = (float*)d_out;

    float *qkv, *qatd, *kkn, *tdpr, *xsum, *hc;
    unsigned short *xn, *x2n, *yaca, *ywin, *patd, *hc2, *vvt, *wt;
    int *tkid, *sidx;
    cudaGetSymbolAddress((void**)&xn,   g_xn);
    cudaGetSymbolAddress((void**)&qkv,  g_qkv);
    cudaGetSymbolAddress((void**)&qatd, g_qatd);
    cudaGetSymbolAddress((void**)&kkn,  g_kkn);
    cudaGetSymbolAddress((void**)&vvt,  g_vvt);
    cudaGetSymbolAddress((void**)&tdpr, g_tdpr);
    cudaGetSymbolAddress((void**)&patd, g_patd);
    cudaGetSymbolAddress((void**)&yaca, g_yaca);
    cudaGetSymbolAddress((void**)&ywin, g_ywin);
    cudaGetSymbolAddress((void**)&xsum, g_xsum);
    cudaGetSymbolAddress((void**)&x2n,  g_x2n);
    cudaGetSymbolAddress((void**)&hc,   g_hc);
    cudaGetSymbolAddress((void**)&hc2,  g_hc2);
    cudaGetSymbolAddress((void**)&tkid, g_tkid);
    cudaGetSymbolAddress((void**)&sidx, g_sidx);
    cudaGetSymbolAddress((void**)&wt,   g_wt);

    static cudaStream_t s1 = nullptr;
    static cudaEvent_t eRoot, eLn1, eConvw, eWbias, eQkv, eAcmsa, eGath;
    if (!s1) {
        cudaStreamCreateWithFlags(&s1, cudaStreamNonBlocking);
        cudaEventCreateWithFlags(&eRoot,  cudaEventDisableTiming);
        cudaEventCreateWithFlags(&eLn1,   cudaEventDisableTiming);
        cudaEventCreateWithFlags(&eConvw, cudaEventDisableTiming);
        cudaEventCreateWithFlags(&eWbias, cudaEventDisableTiming);
        cudaEventCreateWithFlags(&eQkv,   cudaEventDisableTiming);
        cudaEventCreateWithFlags(&eAcmsa, cudaEventDisableTiming);
        cudaEventCreateWithFlags(&eGath,  cudaEventDisableTiming);
        cudaFuncSetAttribute(winattn_tc, cudaFuncAttributeMaxDynamicSharedMemorySize, WSMEM);
    }

    // ---- fork side stream from main ----
    cudaEventRecord(eRoot, 0);
    cudaStreamWaitEvent(s1, eRoot, 0);

    // ---- side stream: prologue kernels ----
    convw_all<<<(S_TOT + 255)/256, 256, 0, s1>>>(wqkv_w, aca_w, win_w, fc1_w, fc2_w, wt);
    cudaEventRecord(eConvw, s1);
    wbias_kernel<<<WINN*WINN/256, 256, 0, s1>>>(rpi, win_rpb);
    cudaEventRecord(eWbias, s1);
    dict_kernel<<<BATCH*MTOK, 256, 0, s1>>>(td, atd_wk_w, atd_wk_b, atd_wv_w, atd_wv_b,
                                            fctd_w, fctd_b, kkn, vvt, tdpr);

    // ---- main stream: LN1 (+ fused q_atd) ----
    ln_kernel<<<ROWS/8, 256>>>(x, n1g, n1b, xn, atd_wq_w, atd_wq_b, qatd);
    cudaEventRecord(eLn1, 0);

    // main: qkv GEMM (needs convw)
    cudaStreamWaitEvent(0, eConvw, 0);
    gemm_bf<<<dim3(9, ROWS/128), 256>>>(xn, wt + WT_QKV, DIMC, nullptr, nullptr, 0,
                                        nullptr, nullptr, 0, 0,
                                        wqkv_b, nullptr, nullptr,
                                        qkv, ROWS, QKVW, QKVW, 0);
    cudaEventRecord(eQkv, 0);

    // main: tensor-core window attention (needs qkv + wbias)
    cudaStreamWaitEvent(0, eWbias, 0);
    winattn_tc<<<NWIN*HEADS, 256, WSMEM>>>(qkv, ywin);

    // ---- side stream: ATD chain (needs ln1; acmsa needs qkv) ----
    cudaStreamWaitEvent(s1, eLn1, 0);
    atd_kernel<<<ROWS/8, 256, 0, s1>>>(qatd, kkn, atd_sc, patd, tkid);
    sortscatter_kernel<<<BATCH*MTOK, 256, 0, s1>>>(tkid, sidx);
    cudaStreamWaitEvent(s1, eQkv, 0);
    acmsa_kernel<<<BATCH*NG*HEADS, 64, 0, s1>>>(qkv, sidx, yaca);
    cudaEventRecord(eAcmsa, s1);
    gathertd_kernel<<<ROWS*DTD/256, 256, 0, s1>>>(tdpr, tkid, hc);
    cudaEventRecord(eGath, s1);

    // ---- main stream: join acmsa branch, fused residual GEMM ----
    cudaStreamWaitEvent(0, eAcmsa, 0);
    gemm_bf<<<dim3(3, ROWS/128), 256>>>(yaca, wt + WT_ACA, DIMC, ywin, wt + WT_WIN, DIMC,
                                        patd, vvt, (long)DIMC*MTOK, MTOK,
                                        aca_b, win_b, x,
                                        xsum, ROWS, DIMC, DIMC, 0);
    ln_kernel<<<ROWS/8, 256>>>(xsum, n2g, n2b, x2n, nullptr, nullptr, nullptr);
    gemm_bf<<<dim3(6, ROWS/128), 256>>>(x2n, wt + WT_FC1, DIMC, nullptr, nullptr, 0,
                                        nullptr, nullptr, 0, 0,
                                        fc1_b, nullptr, nullptr,
                                        hc, ROWS, MLP_HID, CFF, 1);
    cudaStreamWaitEvent(0, eGath, 0);
    dwconv_kernel<<<dim3(16, CFF/DWCH, BATCH), 256>>>(hc, dw_w, dw_b, hc2);
    gemm_bf<<<dim3(3, ROWS/128), 256>>>(hc2, wt + WT_FC2, CFF, nullptr, nullptr, 0,
                                        nullptr, nullptr, 0, 0,
                                        fc2_b, nullptr, xsum,
                                        out, ROWS, DIMC, DIMC, 0);
}

// round 14
// speedup vs baseline: 2.2861x; 1.1615x over previous
#include <cuda_runtime.h>
#include <cuda_bf16.h>
#include <math.h>

// ---------------------------------------------------------------------------
// Problem constants
// ---------------------------------------------------------------------------
#define BATCH 8
#define NTOK 4096
#define ROWS (BATCH*NTOK)
#define DIMC 180
#define HEADS 6
#define HD 30
#define QKVW 540
#define MTOK 64
#define RDIM 10
#define GS 128
#define NG 32
#define WS 16
#define WINN 256
#define NWIN 128
#define MLP_HID 360
#define DTD 64
#define CFF 424
#define HH 64
#define WW 64

// bf16 weight scratch offsets (elements)
#define WT_QKV 0
#define WT_ACA (WT_QKV + DIMC*QKVW)
#define WT_WIN (WT_ACA + DIMC*DIMC)
#define WT_FC1 (WT_WIN + DIMC*DIMC)
#define WT_FC2 (WT_FC1 + DIMC*MLP_HID)
#define WT_TOTAL (WT_FC2 + CFF*DIMC)

// ---------------------------------------------------------------------------
// Scratch
// ---------------------------------------------------------------------------
__device__ unsigned short g_xn  [ROWS*DIMC];        // bf16
__device__ float g_qkv  [ROWS*QKVW];
__device__ float g_qatd [ROWS*RDIM];
__device__ float g_kkn  [BATCH*MTOK*RDIM];
__device__ unsigned short g_vvt [BATCH*DIMC*MTOK];  // bf16, transposed [b][n][m]
__device__ float g_tdpr [BATCH*MTOK*DTD];
__device__ unsigned short g_patd[ROWS*MTOK];        // bf16
__device__ int   g_tkid [ROWS];
__device__ int   g_sidx [ROWS];
__device__ unsigned short g_yaca[ROWS*DIMC];        // bf16
__device__ unsigned short g_ywin[ROWS*DIMC];        // bf16
__device__ float g_xsum [ROWS*DIMC];
__device__ unsigned short g_x2n [ROWS*DIMC];        // bf16
__device__ float g_hc   [ROWS*CFF];
__device__ unsigned short g_hc2 [ROWS*CFF];         // bf16
__device__ float g_wbias[HEADS*WINN*WINN];
__device__ unsigned short g_wt  [WT_TOTAL];         // bf16 transposed weights

// ---------------------------------------------------------------------------
// Helpers
// ---------------------------------------------------------------------------
__device__ __forceinline__ float warp_sum(float v) {
    #pragma unroll
    for (int o = 16; o; o >>= 1) v += __shfl_xor_sync(0xffffffffu, v, o);
    return v;
}
__device__ __forceinline__ float gelu_exact(float v) {
    return 0.5f * v * (1.0f + erff(v * 0.70710678118654752440f));
}
__device__ __forceinline__ unsigned smem_u32(const void* p) {
    return (unsigned)__cvta_generic_to_shared(p);
}
__device__ __forceinline__ unsigned short f2bf(float v) {
    __nv_bfloat16 h = __float2bfloat16_rn(v);
    return *(unsigned short*)&h;
}
__device__ __forceinline__ unsigned bf2pack(float lo, float hi) {
    __nv_bfloat162 h = __floats2bfloat162_rn(lo, hi);
    return *(unsigned*)&h;
}
__device__ __forceinline__ void ldsm4(unsigned& r0, unsigned& r1, unsigned& r2, unsigned& r3,
                                      unsigned addr) {
    asm volatile("ldmatrix.sync.aligned.m8n8.x4.shared.b16 {%0,%1,%2,%3}, [%4];"
                 : "=r"(r0), "=r"(r1), "=r"(r2), "=r"(r3) : "r"(addr));
}
__device__ __forceinline__ void mma_bf(float* d, const unsigned* a, unsigned b0, unsigned b1) {
    asm volatile(
        "mma.sync.aligned.m16n8k16.row.col.f32.bf16.bf16.f32 "
        "{%0,%1,%2,%3},{%4,%5,%6,%7},{%8,%9},{%0,%1,%2,%3};"
        : "+f"(d[0]), "+f"(d[1]), "+f"(d[2]), "+f"(d[3])
        : "r"(a[0]), "r"(a[1]), "r"(a[2]), "r"(a[3]), "r"(b0), "r"(b1));
}

// ---------------------------------------------------------------------------
// Merged weight transpose+convert for all five GEMM weights.
// ---------------------------------------------------------------------------
#define S_QKV (DIMC*QKVW)
#define S_ACA (DIMC*DIMC)
#define S_WIN (DIMC*DIMC)
#define S_FC1 (DIMC*MLP_HID)
#define S_FC2 (CFF*DIMC)
#define S_TOT (S_QKV+S_ACA+S_WIN+S_FC1+S_FC2)

__global__ void convw_all(const float* __restrict__ qkv_w, const float* __restrict__ aca_w,
                          const float* __restrict__ win_w, const float* __restrict__ fc1_w,
                          const float* __restrict__ fc2_w, unsigned short* __restrict__ wt) {
    int i = blockIdx.x * blockDim.x + threadIdx.x;
    if (i >= S_TOT) return;
    const float* W; int K, N, loc, base;
    if (i < S_QKV)                       { W = qkv_w; K = DIMC; N = QKVW;   loc = i;                         base = WT_QKV; }
    else if (i < S_QKV+S_ACA)            { W = aca_w; K = DIMC; N = DIMC;   loc = i - S_QKV;                 base = WT_ACA; }
    else if (i < S_QKV+S_ACA+S_WIN)      { W = win_w; K = DIMC; N = DIMC;   loc = i - S_QKV - S_ACA;         base = WT_WIN; }
    else if (i < S_QKV+S_ACA+S_WIN+S_FC1){ W = fc1_w; K = DIMC; N = MLP_HID;loc = i - S_QKV - S_ACA - S_WIN; base = WT_FC1; }
    else                                 { W = fc2_w; K = CFF;  N = DIMC;   loc = i - S_QKV-S_ACA-S_WIN-S_FC1; base = WT_FC2; }
    int n = loc / K, k = loc % K;
    wt[base + loc] = f2bf(W[(size_t)k * N + n]);
}

// ---------------------------------------------------------------------------
// Fused dictionary projections: kkn fp32 l2n, vvt bf16 transposed, tdpr fp32
// ---------------------------------------------------------------------------
__global__ void dict_kernel(const float* __restrict__ td,
                            const float* __restrict__ wk_w, const float* __restrict__ wk_b,
                            const float* __restrict__ wv_w, const float* __restrict__ wv_b,
                            const float* __restrict__ ftd_w, const float* __restrict__ ftd_b,
                            float* __restrict__ kkn, unsigned short* __restrict__ vvt,
                            float* __restrict__ tdpr) {
    int r = blockIdx.x;                 // 0..511
    int b = r >> 6, m = r & 63;
    __shared__ float as[DIMC];
    __shared__ float kbuf[RDIM];
    int tid = threadIdx.x;
    const float* ar = td + (size_t)r * DIMC;
    if (tid < DIMC) as[tid] = ar[tid];
    __syncthreads();
    if (tid < DIMC) {
        float acc = wv_b[tid];
        #pragma unroll 4
        for (int k = 0; k < DIMC; k++) acc += as[k] * wv_w[(size_t)k * DIMC + tid];
        vvt[((size_t)b * DIMC + tid) * MTOK + m] = f2bf(acc);
    } else if (tid < DIMC + DTD) {
        int c = tid - DIMC;
        float acc = ftd_b[c];
        #pragma unroll 4
        for (int k = 0; k < DIMC; k++) acc += as[k] * ftd_w[(size_t)k * DTD + c];
        tdpr[(size_t)r * DTD + c] = acc;
    } else if (tid < DIMC + DTD + RDIM) {
        int c = tid - DIMC - DTD;
        float acc = wk_b[c];
        #pragma unroll 4
        for (int k = 0; k < DIMC; k++) acc += as[k] * wk_w[(size_t)k * RDIM + c];
        kbuf[c] = acc;
    }
    __syncthreads();
    if (tid >= DIMC + DTD && tid < DIMC + DTD + RDIM) {
        int c = tid - DIMC - DTD;
        float ss = 0.f;
        #pragma unroll
        for (int j = 0; j < RDIM; j++) ss += kbuf[j] * kbuf[j];
        float inv = 1.f / fmaxf(sqrtf(ss), 1e-12f);
        kkn[(size_t)r * RDIM + c] = kbuf[c] * inv;
    }
}

// ---------------------------------------------------------------------------
// Window attention bias expansion
// ---------------------------------------------------------------------------
__global__ void wbias_kernel(const int* __restrict__ rpi, const float* __restrict__ rpb) {
    int e = blockIdx.x * blockDim.x + threadIdx.x;
    if (e < WINN * WINN) {
        int idx = rpi[e];
        #pragma unroll
        for (int h = 0; h < HEADS; h++) g_wbias[h * WINN * WINN + e] = rpb[idx * HEADS + h];
    }
}

// ---------------------------------------------------------------------------
// LayerNorm -> bf16 out (+ optional fused 10-dim q projection, fp32)
// ---------------------------------------------------------------------------
__global__ void ln_kernel(const float* __restrict__ x, const float* __restrict__ g,
                          const float* __restrict__ b, unsigned short* __restrict__ out,
                          const float* __restrict__ wq, const float* __restrict__ bq,
                          float* __restrict__ qout) {
    __shared__ float ws[1920];
    __shared__ float bqs[16];
    int tid = threadIdx.x;
    if (wq) {
        for (int i = tid; i < 1920; i += 256) ws[i] = (i < DIMC * RDIM) ? wq[i] : 0.f;
        if (tid < RDIM) bqs[tid] = bq[tid];
        __syncthreads();
    }
    int row = (blockIdx.x * blockDim.x + tid) >> 5;
    if (row >= ROWS) return;
    int lane = tid & 31;
    const float* xr = x + (size_t)row * DIMC;
    float v[6], s = 0.f, s2 = 0.f;
    #pragma unroll
    for (int k = 0; k < 6; k++) {
        int c = lane + k * 32;
        v[k] = (c < DIMC) ? xr[c] : 0.f;
        s += v[k]; s2 += v[k] * v[k];
    }
    s = warp_sum(s); s2 = warp_sum(s2);
    float mu = s * (1.f / DIMC);
    float var = s2 * (1.f / DIMC) - mu * mu;
    float rstd = rsqrtf(var + 1e-5f);
    float nv[6];
    unsigned short* orow = out + (size_t)row * DIMC;
    #pragma unroll
    for (int k = 0; k < 6; k++) {
        int c = lane + k * 32;
        nv[k] = (c < DIMC) ? ((v[k] - mu) * rstd * g[c] + b[c]) : 0.f;
        if (c < DIMC) orow[c] = f2bf(nv[k]);
    }
    if (wq) {
        float myq = 0.f;
        #pragma unroll
        for (int o = 0; o < RDIM; o++) {
            float p = 0.f;
            #pragma unroll
            for (int k = 0; k < 6; k++) p += nv[k] * ws[(lane + 32 * k) * RDIM + o];
            p = warp_sum(p);
            if (lane == o) myq = p + bqs[o];
        }
        if (lane < RDIM) qout[(size_t)row * RDIM + lane] = myq;
    }
}

// ---------------------------------------------------------------------------
// bf16 tensor-core GEMM (m16n8k16) with ldmatrix fragment loads.
// ---------------------------------------------------------------------------
struct GPass { const unsigned short* A; const unsigned short* W; int K; int kt; };

__global__ __launch_bounds__(256) void gemm_bf(
        const unsigned short* __restrict__ A1, const unsigned short* __restrict__ W1, int K1,
        const unsigned short* __restrict__ A2, const unsigned short* __restrict__ W2, int K2,
        const unsigned short* __restrict__ A3, const unsigned short* __restrict__ W3base,
        long w3_stride, int K3,
        const float* __restrict__ b1, const float* __restrict__ b2,
        const float* __restrict__ add1,
        float* __restrict__ C, int M, int N, int ldc, int act) {
    __shared__ unsigned short As[2][128][40];
    __shared__ unsigned short Ws[2][64][40];
    int tid  = threadIdx.x;
    int lane = tid & 31;
    int warp = tid >> 5;
    int warpM = warp & 3;
    int warpN = warp >> 2;
    int gId = lane >> 2;
    int tig = lane & 3;
    int row0 = blockIdx.y * 128;
    int col0 = blockIdx.x * 64;

    GPass ps[3];
    int np = 0;
    if (A1 && K1 > 0) ps[np++] = {A1, W1, K1, (K1 + 31) >> 5};
    if (A2 && K2 > 0) ps[np++] = {A2, W2, K2, (K2 + 31) >> 5};
    if (A3 && K3 > 0) ps[np++] = {A3, W3base + (size_t)(row0 >> 12) * w3_stride, K3, (K3 + 31) >> 5};
    int total = 0;
    for (int p = 0; p < np; p++) total += ps[p].kt;

    auto copy_tile = [&](int gi, int buf) {
        int p = 0, loc = gi;
        while (loc >= ps[p].kt) { loc -= ps[p].kt; p++; }
        const unsigned short* A = ps[p].A;
        const unsigned short* W = ps[p].W;
        int K = ps[p].K;
        int k0 = loc << 5;
        #pragma unroll
        for (int f = 0; f < 4; f++) {
            int c = tid + f * 256;
            int m = c >> 3, kc = (c & 7) << 2;
            int gk = k0 + kc;
            int rem = K - gk;
            int bytes = (rem <= 0) ? 0 : ((rem >= 4) ? 8 : rem * 2);
            const unsigned short* src = bytes ? (A + (size_t)(row0 + m) * K + gk) : A;
            unsigned dst = smem_u32(&As[buf][m][kc]);
            asm volatile("cp.async.ca.shared.global [%0], [%1], 8, %2;"
                         :: "r"(dst), "l"(src), "r"(bytes));
        }
        #pragma unroll
        for (int f = 0; f < 2; f++) {
            int c = tid + f * 256;
            int n = c >> 3, kc = (c & 7) << 2;
            int gn = col0 + n, gk = k0 + kc;
            int bytes = 0;
            if (gn < N) {
                int rem = K - gk;
                bytes = (rem <= 0) ? 0 : ((rem >= 4) ? 8 : rem * 2);
            }
            const unsigned short* src = bytes ? (W + (size_t)gn * K + gk) : W;
            unsigned dst = smem_u32(&Ws[buf][n][kc]);
            asm volatile("cp.async.ca.shared.global [%0], [%1], 8, %2;"
                         :: "r"(dst), "l"(src), "r"(bytes));
        }
    };

    float d[2][4][4];
    #pragma unroll
    for (int mt = 0; mt < 2; mt++)
        #pragma unroll
        for (int nt = 0; nt < 4; nt++)
            #pragma unroll
            for (int i = 0; i < 4; i++) d[mt][nt][i] = 0.f;

    copy_tile(0, 0);
    asm volatile("cp.async.commit_group;");
    for (int i = 0; i < total; i++) {
        asm volatile("cp.async.wait_group 0;");
        __syncthreads();
        if (i + 1 < total) {
            copy_tile(i + 1, (i + 1) & 1);
            asm volatile("cp.async.commit_group;");
        }
        int buf = i & 1;
        #pragma unroll
        for (int ks = 0; ks < 2; ks++) {
            int kb = ks * 16;
            unsigned a[2][4], bfr[4][2];
            int arow = lane & 15;
            int acol = kb + ((lane >> 4) << 3);
            #pragma unroll
            for (int mt = 0; mt < 2; mt++) {
                int m0 = warpM * 32 + mt * 16;
                unsigned ad = smem_u32(&As[buf][m0 + arow][acol]);
                ldsm4(a[mt][0], a[mt][1], a[mt][2], a[mt][3], ad);
            }
            int wrow = ((lane >> 4) << 3) + (lane & 7);
            int wcol = kb + (((lane >> 3) & 1) << 3);
            #pragma unroll
            for (int np2 = 0; np2 < 2; np2++) {
                int n0 = warpN * 32 + np2 * 16;
                unsigned ad = smem_u32(&Ws[buf][n0 + wrow][wcol]);
                unsigned r0, r1, r2, r3;
                ldsm4(r0, r1, r2, r3, ad);
                bfr[2*np2][0] = r0;  bfr[2*np2][1] = r1;
                bfr[2*np2+1][0] = r2; bfr[2*np2+1][1] = r3;
            }
            #pragma unroll
            for (int mt = 0; mt < 2; mt++)
                #pragma unroll
                for (int nt = 0; nt < 4; nt++)
                    mma_bf(d[mt][nt], a[mt], bfr[nt][0], bfr[nt][1]);
        }
    }

    #pragma unroll
    for (int mt = 0; mt < 2; mt++) {
        #pragma unroll
        for (int nt = 0; nt < 4; nt++) {
            #pragma unroll
            for (int i = 0; i < 4; i++) {
                int r = row0 + warpM * 32 + mt * 16 + gId + (i >> 1) * 8;
                int c = col0 + warpN * 32 + nt * 8 + tig * 2 + (i & 1);
                if (c < N) {
                    float v = d[mt][nt][i];
                    if (b1)   v += b1[c];
                    if (b2)   v += b2[c];
                    if (add1) v += add1[(size_t)r * N + c];
                    if (act)  v = gelu_exact(v);
                    C[(size_t)r * ldc + c] = v;
                }
            }
        }
    }
}

// ---------------------------------------------------------------------------
// ATD: softmax probs P (bf16) + argmax tkid. One warp per token. fp32 math.
// ---------------------------------------------------------------------------
__global__ void atd_kernel(const float* __restrict__ qatd, const float* __restrict__ kkn,
                           const float* __restrict__ scale,
                           unsigned short* __restrict__ P, int* __restrict__ tkid) {
    int t = (blockIdx.x * blockDim.x + threadIdx.x) >> 5;
    int lane = threadIdx.x & 31;
    if (t >= ROWS) return;
    int b = t >> 12;
    float q = (lane < RDIM) ? qatd[(size_t)t * RDIM + lane] : 0.f;
    float ss = warp_sum(q * q);
    float qn = q * (1.f / fmaxf(sqrtf(ss), 1e-12f));
    const float* kb = kkn + (size_t)b * MTOK * RDIM;
    float s0 = 0.f, s1 = 0.f;
    #pragma unroll
    for (int d = 0; d < RDIM; d++) {
        float qd = __shfl_sync(0xffffffffu, qn, d);
        s0 += qd * kb[lane * RDIM + d];
        s1 += qd * kb[(lane + 32) * RDIM + d];
    }
    float sc = fminf(fmaxf(scale[0], 0.f), 3.f);
    float ls = 1.f + sc * 4.15888308335967186f;  // log(64)
    s0 *= ls; s1 *= ls;
    float mv = fmaxf(s0, s1);
    int mi = (s0 >= s1) ? lane : lane + 32;
    #pragma unroll
    for (int o = 16; o; o >>= 1) {
        float ov = __shfl_xor_sync(0xffffffffu, mv, o);
        int   oi = __shfl_xor_sync(0xffffffffu, mi, o);
        if (ov > mv || (ov == mv && oi < mi)) { mv = ov; mi = oi; }
    }
    float p0 = __expf(s0 - mv), p1 = __expf(s1 - mv);
    float sum = warp_sum(p0 + p1);
    float inv = 1.f / sum;
    P[(size_t)t * MTOK + lane]      = f2bf(p0 * inv);
    P[(size_t)t * MTOK + lane + 32] = f2bf(p1 * inv);
    if (lane == 0) tkid[t] = mi;
}

// ---------------------------------------------------------------------------
// Single-pass stable counting sort scatter: block = (batch, bin).
// ---------------------------------------------------------------------------
__global__ void sortscatter_kernel(const int* __restrict__ tkid, int* __restrict__ sidx) {
    int b = blockIdx.x >> 6, bin = blockIdx.x & 63;
    const int* tk = tkid + b * NTOK;
    __shared__ int sc[256];
    int t = threadIdx.x;
    int start = t * 16;
    int eq = 0, less = 0;
    int vals[16];
    #pragma unroll
    for (int k = 0; k < 16; k++) {
        vals[k] = tk[start + k];
        eq += (vals[k] == bin);
        less += (vals[k] < bin);
    }
    sc[t] = (less << 16) | eq;
    __syncthreads();
    #pragma unroll
    for (int d = 1; d < 256; d <<= 1) {
        int v = (t >= d) ? sc[t - d] : 0;
        __syncthreads();
        sc[t] += v;
        __syncthreads();
    }
    int base = sc[255] >> 16;
    int pos = base + (sc[t] & 0xffff) - eq;
    #pragma unroll
    for (int k = 0; k < 16; k++)
        if (vals[k] == bin) sidx[b * NTOK + pos++] = start + k;
}

// ---------------------------------------------------------------------------
// Tensor-core AC_MSA grouped attention (flash-style, gathered rows).
// Block = (b, group, head); 4 warps x 32 queries = 128 rows. Keys = the same
// 128 rows, chunks of 32. Qs/Ks bf16 [128][40]; Vt bf16 [32][136]
// (136 shorts = 68 words == 4 mod 32 -> bank = 4*gId + tig, conflict-free).
// ---------------------------------------------------------------------------
#define APITCH 136

__global__ __launch_bounds__(128) void acmsa_tc(
        const float* __restrict__ qkv, const int* __restrict__ sidx,
        unsigned short* __restrict__ yout) {
    __shared__ unsigned short Qs[GS * 40];
    __shared__ unsigned short Ks[GS * 40];
    __shared__ unsigned short Vt[32 * APITCH];
    int bi = blockIdx.x;
    int hh = bi % HEADS;
    int g  = (bi / HEADS) % NG;
    int b  = bi / (HEADS * NG);
    int lane = threadIdx.x & 31;
    int warp = threadIdx.x >> 5;               // 0..3
    const float scale = 0.18257418583505536f;  // 30^-0.5
    const int* sb = sidx + b * NTOK + g * GS;

    // fill: each warp loads 32 gathered tokens
    #pragma unroll 4
    for (int u = 0; u < 32; u++) {
        int r = warp * 32 + u;
        int tok = sb[r];
        size_t rb = ((size_t)(b * NTOK + tok)) * QKVW + hh * HD;
        unsigned short qv = 0, kv = 0, vv = 0;
        if (lane < HD) {
            qv = f2bf(qkv[rb + lane] * scale);
            kv = f2bf(qkv[rb + 180 + lane]);
            vv = f2bf(qkv[rb + 360 + lane]);
        }
        Qs[r * 40 + lane] = qv;
        Ks[r * 40 + lane] = kv;
        Vt[lane * APITCH + r] = vv;
    }
    __syncthreads();

    int gId = lane >> 2, tig = lane & 3;
    int m0 = warp * 32;

    unsigned qf[2][2][4];
    #pragma unroll
    for (int mt = 0; mt < 2; mt++)
        #pragma unroll
        for (int ks = 0; ks < 2; ks++) {
            unsigned ad = smem_u32(Qs + (m0 + mt * 16 + (lane & 15)) * 40
                                      + ks * 16 + ((lane >> 4) << 3));
            ldsm4(qf[mt][ks][0], qf[mt][ks][1], qf[mt][ks][2], qf[mt][ks][3], ad);
        }

    float mrow[2][2] = {{-1e30f, -1e30f}, {-1e30f, -1e30f}};
    float lrow[2][2] = {{0.f, 0.f}, {0.f, 0.f}};
    float o[2][4][4];
    #pragma unroll
    for (int mt = 0; mt < 2; mt++)
        #pragma unroll
        for (int vn = 0; vn < 4; vn++)
            #pragma unroll
            for (int i = 0; i < 4; i++) o[mt][vn][i] = 0.f;

    for (int jc = 0; jc < GS; jc += 32) {
        unsigned kf[4][2][2];
        #pragma unroll
        for (int np2 = 0; np2 < 2; np2++)
            #pragma unroll
            for (int ks = 0; ks < 2; ks++) {
                unsigned ad = smem_u32(Ks + (jc + np2 * 16 + ((lane >> 4) << 3) + (lane & 7)) * 40
                                          + ks * 16 + (((lane >> 3) & 1) << 3));
                unsigned r0, r1, r2, r3;
                ldsm4(r0, r1, r2, r3, ad);
                kf[2*np2][ks][0] = r0;   kf[2*np2][ks][1] = r1;
                kf[2*np2+1][ks][0] = r2; kf[2*np2+1][ks][1] = r3;
            }
        float s[2][4][4];
        #pragma unroll
        for (int mt = 0; mt < 2; mt++)
            #pragma unroll
            for (int nt = 0; nt < 4; nt++) {
                #pragma unroll
                for (int i = 0; i < 4; i++) s[mt][nt][i] = 0.f;
                #pragma unroll
                for (int ks = 0; ks < 2; ks++)
                    mma_bf(s[mt][nt], qf[mt][ks], kf[nt][ks][0], kf[nt][ks][1]);
            }
        float co2[2][2];
        #pragma unroll
        for (int mt = 0; mt < 2; mt++)
            #pragma unroll
            for (int h = 0; h < 2; h++) {
                float rm = -1e30f;
                #pragma unroll
                for (int nt = 0; nt < 4; nt++)
                    rm = fmaxf(rm, fmaxf(s[mt][nt][2*h], s[mt][nt][2*h+1]));
                rm = fmaxf(rm, __shfl_xor_sync(0xffffffffu, rm, 1));
                rm = fmaxf(rm, __shfl_xor_sync(0xffffffffu, rm, 2));
                float mn = fmaxf(mrow[mt][h], rm);
                float co = __expf(mrow[mt][h] - mn);
                mrow[mt][h] = mn;
                float rs = 0.f;
                #pragma unroll
                for (int nt = 0; nt < 4; nt++) {
                    float e0 = __expf(s[mt][nt][2*h]   - mn);
                    float e1 = __expf(s[mt][nt][2*h+1] - mn);
                    s[mt][nt][2*h] = e0; s[mt][nt][2*h+1] = e1;
                    rs += e0 + e1;
                }
                rs += __shfl_xor_sync(0xffffffffu, rs, 1);
                rs += __shfl_xor_sync(0xffffffffu, rs, 2);
                lrow[mt][h] = lrow[mt][h] * co + rs;
                co2[mt][h] = co;
            }
        #pragma unroll
        for (int mt = 0; mt < 2; mt++)
            #pragma unroll
            for (int vn = 0; vn < 4; vn++)
                #pragma unroll
                for (int i = 0; i < 4; i++) o[mt][vn][i] *= co2[mt][i >> 1];
        #pragma unroll
        for (int ks = 0; ks < 2; ks++) {
            unsigned a[2][4];
            #pragma unroll
            for (int mt = 0; mt < 2; mt++) {
                a[mt][0] = bf2pack(s[mt][2*ks][0],   s[mt][2*ks][1]);
                a[mt][1] = bf2pack(s[mt][2*ks][2],   s[mt][2*ks][3]);
                a[mt][2] = bf2pack(s[mt][2*ks+1][0], s[mt][2*ks+1][1]);
                a[mt][3] = bf2pack(s[mt][2*ks+1][2], s[mt][2*ks+1][3]);
            }
            #pragma unroll
            for (int vn = 0; vn < 4; vn++) {
                const unsigned short* vp = Vt + (vn * 8 + gId) * APITCH + jc + ks * 16 + 2 * tig;
                unsigned b0 = *(const unsigned*)vp;
                unsigned b1 = *(const unsigned*)(vp + 8);
                #pragma unroll
                for (int mt = 0; mt < 2; mt++)
                    mma_bf(o[mt][vn], a[mt], b0, b1);
            }
        }
    }
    #pragma unroll
    for (int mt = 0; mt < 2; mt++)
        #pragma unroll
        for (int h = 0; h < 2; h++) {
            float inv = 1.f / lrow[mt][h];
            int row = m0 + mt * 16 + gId + 8 * h;
            int tok = sb[row];
            unsigned short* obase = yout + ((size_t)(b * NTOK + tok)) * DIMC + hh * HD;
            #pragma unroll
            for (int vn = 0; vn < 4; vn++) {
                int vd = vn * 8 + 2 * tig;
                if (vd < HD)
                    *(unsigned*)(obase + vd) =
                        bf2pack(o[mt][vn][2*h] * inv, o[mt][vn][2*h+1] * inv);
            }
        }
}

// ---------------------------------------------------------------------------
// Tensor-core window attention (flash-style).
// ---------------------------------------------------------------------------
#define VPITCH 264
#define WSMEM ((2*256*40 + 32*VPITCH) * 2)   // 57856 bytes

__global__ __launch_bounds__(256) void winattn_tc(const float* __restrict__ qkv,
                                                  unsigned short* __restrict__ yout) {
    extern __shared__ unsigned short sm16[];
    unsigned short* Qs = sm16;                 // [256][40]
    unsigned short* Ks = sm16 + 256 * 40;      // [256][40]
    unsigned short* Vt = sm16 + 2 * 256 * 40;  // [32][VPITCH]
    int bi = blockIdx.x;
    int hh = bi % HEADS;
    int wdx = bi / HEADS;
    int b = wdx >> 4;
    int wy = (wdx >> 2) & 3;
    int wx = wdx & 3;
    int lane = threadIdx.x & 31;
    int warp = threadIdx.x >> 5;               // 0..7
    const float scale = 0.18257418583505536f;  // 30^-0.5

    #pragma unroll 4
    for (int u = 0; u < 32; u++) {
        int r = warp * 32 + u;
        int ny = (wy * WS + (r >> 4)) * WW + wx * WS + (r & 15);
        size_t rb = ((size_t)(b * NTOK + ny)) * QKVW + hh * HD;
        unsigned short qv = 0, kv = 0, vv = 0;
        if (lane < HD) {
            qv = f2bf(qkv[rb + lane] * scale);
            kv = f2bf(qkv[rb + 180 + lane]);
            vv = f2bf(qkv[rb + 360 + lane]);
        }
        Qs[r * 40 + lane] = qv;
        Ks[r * 40 + lane] = kv;
        Vt[lane * VPITCH + r] = vv;
    }
    __syncthreads();

    int gId = lane >> 2, tig = lane & 3;
    int m0 = warp * 32;

    unsigned qf[2][2][4];
    #pragma unroll
    for (int mt = 0; mt < 2; mt++)
        #pragma unroll
        for (int ks = 0; ks < 2; ks++) {
            unsigned ad = smem_u32(Qs + (m0 + mt * 16 + (lane & 15)) * 40
                                      + ks * 16 + ((lane >> 4) << 3));
            ldsm4(qf[mt][ks][0], qf[mt][ks][1], qf[mt][ks][2], qf[mt][ks][3], ad);
        }

    float mrow[2][2] = {{-1e30f, -1e30f}, {-1e30f, -1e30f}};
    float lrow[2][2] = {{0.f, 0.f}, {0.f, 0.f}};
    float o[2][4][4];
    #pragma unroll
    for (int mt = 0; mt < 2; mt++)
        #pragma unroll
        for (int vn = 0; vn < 4; vn++)
            #pragma unroll
            for (int i = 0; i < 4; i++) o[mt][vn][i] = 0.f;

    const float* bias = g_wbias + (size_t)hh * WINN * WINN;

    for (int jc = 0; jc < WINN; jc += 32) {
        unsigned kf[4][2][2];
        #pragma unroll
        for (int np2 = 0; np2 < 2; np2++)
            #pragma unroll
            for (int ks = 0; ks < 2; ks++) {
                unsigned ad = smem_u32(Ks + (jc + np2 * 16 + ((lane >> 4) << 3) + (lane & 7)) * 40
                                          + ks * 16 + (((lane >> 3) & 1) << 3));
                unsigned r0, r1, r2, r3;
                ldsm4(r0, r1, r2, r3, ad);
                kf[2*np2][ks][0] = r0;   kf[2*np2][ks][1] = r1;
                kf[2*np2+1][ks][0] = r2; kf[2*np2+1][ks][1] = r3;
            }
        float s[2][4][4];
        #pragma unroll
        for (int mt = 0; mt < 2; mt++)
            #pragma unroll
            for (int nt = 0; nt < 4; nt++) {
                #pragma unroll
                for (int i = 0; i < 4; i++) s[mt][nt][i] = 0.f;
                #pragma unroll
                for (int ks = 0; ks < 2; ks++)
                    mma_bf(s[mt][nt], qf[mt][ks], kf[nt][ks][0], kf[nt][ks][1]);
            }
        #pragma unroll
        for (int mt = 0; mt < 2; mt++)
            #pragma unroll
            for (int h = 0; h < 2; h++) {
                int q = m0 + mt * 16 + gId + 8 * h;
                #pragma unroll
                for (int nt = 0; nt < 4; nt++) {
                    float2 bv = *(const float2*)&bias[(size_t)q * WINN + jc + nt * 8 + 2 * tig];
                    s[mt][nt][2*h]   += bv.x;
                    s[mt][nt][2*h+1] += bv.y;
                }
            }
        float co2[2][2];
        #pragma unroll
        for (int mt = 0; mt < 2; mt++)
            #pragma unroll
            for (int h = 0; h < 2; h++) {
                float rm = -1e30f;
                #pragma unroll
                for (int nt = 0; nt < 4; nt++)
                    rm = fmaxf(rm, fmaxf(s[mt][nt][2*h], s[mt][nt][2*h+1]));
                rm = fmaxf(rm, __shfl_xor_sync(0xffffffffu, rm, 1));
                rm = fmaxf(rm, __shfl_xor_sync(0xffffffffu, rm, 2));
                float mn = fmaxf(mrow[mt][h], rm);
                float co = __expf(mrow[mt][h] - mn);
                mrow[mt][h] = mn;
                float rs = 0.f;
                #pragma unroll
                for (int nt = 0; nt < 4; nt++) {
                    float e0 = __expf(s[mt][nt][2*h]   - mn);
                    float e1 = __expf(s[mt][nt][2*h+1] - mn);
                    s[mt][nt][2*h] = e0; s[mt][nt][2*h+1] = e1;
                    rs += e0 + e1;
                }
                rs += __shfl_xor_sync(0xffffffffu, rs, 1);
                rs += __shfl_xor_sync(0xffffffffu, rs, 2);
                lrow[mt][h] = lrow[mt][h] * co + rs;
                co2[mt][h] = co;
            }
        #pragma unroll
        for (int mt = 0; mt < 2; mt++)
            #pragma unroll
            for (int vn = 0; vn < 4; vn++)
                #pragma unroll
                for (int i = 0; i < 4; i++) o[mt][vn][i] *= co2[mt][i >> 1];
        #pragma unroll
        for (int ks = 0; ks < 2; ks++) {
            unsigned a[2][4];
            #pragma unroll
            for (int mt = 0; mt < 2; mt++) {
                a[mt][0] = bf2pack(s[mt][2*ks][0],   s[mt][2*ks][1]);
                a[mt][1] = bf2pack(s[mt][2*ks][2],   s[mt][2*ks][3]);
                a[mt][2] = bf2pack(s[mt][2*ks+1][0], s[mt][2*ks+1][1]);
                a[mt][3] = bf2pack(s[mt][2*ks+1][2], s[mt][2*ks+1][3]);
            }
            #pragma unroll
            for (int vn = 0; vn < 4; vn++) {
                const unsigned short* vp = Vt + (vn * 8 + gId) * VPITCH + jc + ks * 16 + 2 * tig;
                unsigned b0 = *(const unsigned*)vp;
                unsigned b1 = *(const unsigned*)(vp + 8);
                #pragma unroll
                for (int mt = 0; mt < 2; mt++)
                    mma_bf(o[mt][vn], a[mt], b0, b1);
            }
        }
    }
    #pragma unroll
    for (int mt = 0; mt < 2; mt++)
        #pragma unroll
        for (int h = 0; h < 2; h++) {
            float inv = 1.f / lrow[mt][h];
            int row = m0 + mt * 16 + gId + 8 * h;
            int ny = (wy * WS + (row >> 4)) * WW + wx * WS + (row & 15);
            unsigned short* obase = yout + ((size_t)(b * NTOK + ny)) * DIMC + hh * HD;
            #pragma unroll
            for (int vn = 0; vn < 4; vn++) {
                int vd = vn * 8 + 2 * tig;
                if (vd < HD)
                    *(unsigned*)(obase + vd) =
                        bf2pack(o[mt][vn][2*h] * inv, o[mt][vn][2*h+1] * inv);
            }
        }
}

// ---------------------------------------------------------------------------
// Gather per-token dictionary features into hc[:, 360:424] (fp32)
// ---------------------------------------------------------------------------
__global__ void gathertd_kernel(const float* __restrict__ tdproj, const int* __restrict__ tkid,
                                float* __restrict__ hc) {
    int e = blockIdx.x * blockDim.x + threadIdx.x;
    if (e < ROWS * DTD) {
        int r = e >> 6, j = e & 63;
        int b = r >> 12;
        hc[(size_t)r * CFF + MLP_HID + j] = tdproj[((size_t)b * MTOK + tkid[r]) * DTD + j];
    }
}

// ---------------------------------------------------------------------------
// Depthwise 5x5 conv + GELU + residual; bf16 output hc2.
// ---------------------------------------------------------------------------
#define DWCH 8
__global__ void dwconv_kernel(const float* __restrict__ hc, const float* __restrict__ w,
                              const float* __restrict__ bias, unsigned short* __restrict__ hc2) {
    __shared__ float smd[20 * 20 * DWCH];
    __shared__ float wsm[25][DWCH];
    __shared__ float bsm[DWCH];
    int tid = threadIdx.x;
    int c0 = blockIdx.y * DWCH;
    int b  = blockIdx.z;
    int tileY = (blockIdx.x >> 2) * 16, tileX = (blockIdx.x & 3) * 16;
    if (tid < 200) { int t5 = tid % 25, j = tid / 25; wsm[t5][j] = w[(c0 + j) * 25 + t5]; }
    if (tid < DWCH) bsm[tid] = bias[c0 + tid];
    for (int i = tid; i < 800; i += 256) {
        int cell = i >> 1, half = i & 1;
        int cy = cell / 20, cx = cell % 20;
        int gy = tileY + cy - 2, gx = tileX + cx - 2;
        float4 v = {0.f, 0.f, 0.f, 0.f};
        if (gy >= 0 && gy < 64 && gx >= 0 && gx < 64)
            v = *(const float4*)&hc[(((size_t)b << 12) + (gy << 6) + gx) * CFF + c0 + half * 4];
        *(float4*)&smd[cell * 8 + half * 4] = v;
    }
    __syncthreads();
    int ty = tid >> 4, tx = tid & 15;
    float acc[DWCH];
    #pragma unroll
    for (int j = 0; j < DWCH; j++) acc[j] = 0.f;
    #pragma unroll
    for (int ky = 0; ky < 5; ky++) {
        #pragma unroll
        for (int kx = 0; kx < 5; kx++) {
            const float* cp = &smd[((ty + ky) * 20 + tx + kx) * 8];
            float4 a0 = *(const float4*)cp;
            float4 a1 = *(const float4*)(cp + 4);
            int t5 = ky * 5 + kx;
            acc[0] += a0.x * wsm[t5][0];
            acc[1] += a0.y * wsm[t5][1];
            acc[2] += a0.z * wsm[t5][2];
            acc[3] += a0.w * wsm[t5][3];
            acc[4] += a1.x * wsm[t5][4];
            acc[5] += a1.y * wsm[t5][5];
            acc[6] += a1.z * wsm[t5][6];
            acc[7] += a1.w * wsm[t5][7];
        }
    }
    const float* ctr = &smd[((ty + 2) * 20 + tx + 2) * 8];
    size_t idx = (((size_t)b << 12) + ((size_t)(tileY + ty) << 6) + (tileX + tx)) * CFF + c0;
    float o[8];
    #pragma unroll
    for (int j = 0; j < 8; j++) o[j] = ctr[j] + gelu_exact(acc[j] + bsm[j]);
    uint4 pk;
    pk.x = bf2pack(o[0], o[1]);
    pk.y = bf2pack(o[2], o[3]);
    pk.z = bf2pack(o[4], o[5]);
    pk.w = bf2pack(o[6], o[7]);
    *(uint4*)&hc2[idx] = pk;
}

// ---------------------------------------------------------------------------
// Launch: two-stream DAG with tensor-core winattn + acmsa.
// ---------------------------------------------------------------------------
extern "C" void kernel_launch(void* const* d_in, const int* in_sizes, int n_in,
                              void* d_out, int out_size) {
    const float* x        = (const float*)d_in[0];
    const float* td       = (const float*)d_in[1];
    const float* n1g      = (const float*)d_in[2];
    const float* n1b      = (const float*)d_in[3];
    const float* wqkv_w   = (const float*)d_in[4];
    const float* wqkv_b   = (const float*)d_in[5];
    const float* atd_wq_w = (const float*)d_in[6];
    const float* atd_wq_b = (const float*)d_in[7];
    const float* atd_wk_w = (const float*)d_in[8];
    const float* atd_wk_b = (const float*)d_in[9];
    const float* atd_wv_w = (const float*)d_in[10];
    const float* atd_wv_b = (const float*)d_in[11];
    const float* atd_sc   = (const float*)d_in[12];
    const float* aca_w    = (const float*)d_in[13];
    const float* aca_b    = (const float*)d_in[14];
    const float* win_rpb  = (const float*)d_in[15];
    const float* win_w    = (const float*)d_in[16];
    const float* win_b    = (const float*)d_in[17];
    const float* fctd_w   = (const float*)d_in[18];
    const float* fctd_b   = (const float*)d_in[19];
    const float* fc1_w    = (const float*)d_in[20];
    const float* fc1_b    = (const float*)d_in[21];
    const float* dw_w     = (const float*)d_in[22];
    const float* dw_b     = (const float*)d_in[23];
    const float* fc2_w    = (const float*)d_in[24];
    const float* fc2_b    = (const float*)d_in[25];
    const float* n2g      = (const float*)d_in[26];
    const float* n2b      = (const float*)d_in[27];
    const int*   rpi      = (const int*)d_in[28];
    float* out = (float*)d_out;

    float *qkv, *qatd, *kkn, *tdpr, *xsum, *hc;
    unsigned short *xn, *x2n, *yaca, *ywin, *patd, *hc2, *vvt, *wt;
    int *tkid, *sidx;
    cudaGetSymbolAddress((void**)&xn,   g_xn);
    cudaGetSymbolAddress((void**)&qkv,  g_qkv);
    cudaGetSymbolAddress((void**)&qatd, g_qatd);
    cudaGetSymbolAddress((void**)&kkn,  g_kkn);
    cudaGetSymbolAddress((void**)&vvt,  g_vvt);
    cudaGetSymbolAddress((void**)&tdpr, g_tdpr);
    cudaGetSymbolAddress((void**)&patd, g_patd);
    cudaGetSymbolAddress((void**)&yaca, g_yaca);
    cudaGetSymbolAddress((void**)&ywin, g_ywin);
    cudaGetSymbolAddress((void**)&xsum, g_xsum);
    cudaGetSymbolAddress((void**)&x2n,  g_x2n);
    cudaGetSymbolAddress((void**)&hc,   g_hc);
    cudaGetSymbolAddress((void**)&hc2,  g_hc2);
    cudaGetSymbolAddress((void**)&tkid, g_tkid);
    cudaGetSymbolAddress((void**)&sidx, g_sidx);
    cudaGetSymbolAddress((void**)&wt,   g_wt);

    static cudaStream_t s1 = nullptr;
    static cudaEvent_t eRoot, eLn1, eConvw, eWbias, eQkv, eAcmsa, eGath;
    if (!s1) {
        cudaStreamCreateWithFlags(&s1, cudaStreamNonBlocking);
        cudaEventCreateWithFlags(&eRoot,  cudaEventDisableTiming);
        cudaEventCreateWithFlags(&eLn1,   cudaEventDisableTiming);
        cudaEventCreateWithFlags(&eConvw, cudaEventDisableTiming);
        cudaEventCreateWithFlags(&eWbias, cudaEventDisableTiming);
        cudaEventCreateWithFlags(&eQkv,   cudaEventDisableTiming);
        cudaEventCreateWithFlags(&eAcmsa, cudaEventDisableTiming);
        cudaEventCreateWithFlags(&eGath,  cudaEventDisableTiming);
        cudaFuncSetAttribute(winattn_tc, cudaFuncAttributeMaxDynamicSharedMemorySize, WSMEM);
    }

    // ---- fork side stream from main ----
    cudaEventRecord(eRoot, 0);
    cudaStreamWaitEvent(s1, eRoot, 0);

    // ---- side stream: prologue kernels ----
    convw_all<<<(S_TOT + 255)/256, 256, 0, s1>>>(wqkv_w, aca_w, win_w, fc1_w, fc2_w, wt);
    cudaEventRecord(eConvw, s1);
    wbias_kernel<<<WINN*WINN/256, 256, 0, s1>>>(rpi, win_rpb);
    cudaEventRecord(eWbias, s1);
    dict_kernel<<<BATCH*MTOK, 256, 0, s1>>>(td, atd_wk_w, atd_wk_b, atd_wv_w, atd_wv_b,
                                            fctd_w, fctd_b, kkn, vvt, tdpr);

    // ---- main stream: LN1 (+ fused q_atd) ----
    ln_kernel<<<ROWS/8, 256>>>(x, n1g, n1b, xn, atd_wq_w, atd_wq_b, qatd);
    cudaEventRecord(eLn1, 0);

    // main: qkv GEMM (needs convw)
    cudaStreamWaitEvent(0, eConvw, 0);
    gemm_bf<<<dim3(9, ROWS/128), 256>>>(xn, wt + WT_QKV, DIMC, nullptr, nullptr, 0,
                                        nullptr, nullptr, 0, 0,
                                        wqkv_b, nullptr, nullptr,
                                        qkv, ROWS, QKVW, QKVW, 0);
    cudaEventRecord(eQkv, 0);

    // main: tensor-core window attention (needs qkv + wbias)
    cudaStreamWaitEvent(0, eWbias, 0);
    winattn_tc<<<NWIN*HEADS, 256, WSMEM>>>(qkv, ywin);

    // ---- side stream: ATD chain (needs ln1; acmsa needs qkv) ----
    cudaStreamWaitEvent(s1, eLn1, 0);
    atd_kernel<<<ROWS/8, 256, 0, s1>>>(qatd, kkn, atd_sc, patd, tkid);
    sortscatter_kernel<<<BATCH*MTOK, 256, 0, s1>>>(tkid, sidx);
    cudaStreamWaitEvent(s1, eQkv, 0);
    acmsa_tc<<<BATCH*NG*HEADS, 128, 0, s1>>>(qkv, sidx, yaca);
    cudaEventRecord(eAcmsa, s1);
    gathertd_kernel<<<ROWS*DTD/256, 256, 0, s1>>>(tdpr, tkid, hc);
    cudaEventRecord(eGath, s1);

    // ---- main stream: join acmsa branch, fused residual GEMM ----
    cudaStreamWaitEvent(0, eAcmsa, 0);
    gemm_bf<<<dim3(3, ROWS/128), 256>>>(yaca, wt + WT_ACA, DIMC, ywin, wt + WT_WIN, DIMC,
                                        patd, vvt, (long)DIMC*MTOK, MTOK,
                                        aca_b, win_b, x,
                                        xsum, ROWS, DIMC, DIMC, 0);
    ln_kernel<<<ROWS/8, 256>>>(xsum, n2g, n2b, x2n, nullptr, nullptr, nullptr);
    gemm_bf<<<dim3(6, ROWS/128), 256>>>(x2n, wt + WT_FC1, DIMC, nullptr, nullptr, 0,
                                        nullptr, nullptr, 0, 0,
                                        fc1_b, nullptr, nullptr,
                                        hc, ROWS, MLP_HID, CFF, 1);
    cudaStreamWaitEvent(0, eGath, 0);
    dwconv_kernel<<<dim3(16, CFF/DWCH, BATCH), 256>>>(hc, dw_w, dw_b, hc2);
    gemm_bf<<<dim3(3, ROWS/128), 256>>>(hc2, wt + WT_FC2, CFF, nullptr, nullptr, 0,
                                        nullptr, nullptr, 0, 0,
                                        fc2_b, nullptr, xsum,
                                        out, ROWS, DIMC, DIMC, 0);
}